// round 9
// baseline (speedup 1.0000x reference)
#include <cuda_runtime.h>
#include <cuda_bf16.h>
#include <cstdint>

// ---------------------------------------------------------------------------
// MultiheadAttention with low-rank-augmented in/out projections.
// T=1024, B=8, E=1024, H=16, R=16, HD=64.
//
// R9 == R8 (int8 m16n8k32 projection GEMMs, 2-digit row-scaled split) with
// the host-passed-__device__-symbol bug fixed: quant_rows is templated and
// references the global scratch buffers from device code.
// ---------------------------------------------------------------------------

namespace {
constexpr int Tt = 1024;
constexpr int Bb = 8;
constexpr int Ee = 1024;
constexpr int Hh = 16;
constexpr int Rr = 16;
constexpr int HD = 64;
constexpr int F3 = 3 * Ee;          // 3072
constexpr int Nrows = Tt * Bb;      // 8192
constexpr int BM = 128, BN = 64, BK = 32;
constexpr int STAGE_B = 12288;      // Aa 4K, Ab 4K, Ba 2K, Bb 2K
}

// Scratch (device globals; no runtime allocation).
__device__ __align__(16) int8_t g_Wina[F3 * Ee];
__device__ __align__(16) int8_t g_Winb[F3 * Ee];
__device__ float g_sWin[F3];
__device__ __align__(16) int8_t g_Wouta[Ee * Ee];
__device__ __align__(16) int8_t g_Woutb[Ee * Ee];
__device__ float g_sWout[Ee];
__device__ __align__(16) int8_t g_Qa[Nrows * Ee];
__device__ __align__(16) int8_t g_Qb[Nrows * Ee];
__device__ float g_sQ[Nrows];
__device__ __align__(16) int8_t g_AOa[Nrows * Ee];
__device__ __align__(16) int8_t g_AOb[Nrows * Ee];
__device__ float g_sAO[Nrows];
__device__ __align__(16) float g_AO[Nrows * Ee];
__device__ __align__(16) __nv_bfloat16 g_Qh[Bb * Hh * Tt * HD];
__device__ __align__(16) __nv_bfloat16 g_Ql[Bb * Hh * Tt * HD];
__device__ __align__(16) __nv_bfloat16 g_Kh[Bb * Hh * Tt * HD];
__device__ __align__(16) __nv_bfloat16 g_Kl[Bb * Hh * Tt * HD];
__device__ __align__(16) __nv_bfloat16 g_Vh[Bb * Hh * Tt * HD];
__device__ __align__(16) __nv_bfloat16 g_Vl[Bb * Hh * Tt * HD];

// ---------------------------------------------------------------------------
__device__ __forceinline__ uint32_t smem_u32(const void* p) {
    uint32_t a;
    asm("{ .reg .u64 t; cvta.to.shared.u64 t, %1; cvt.u32.u64 %0, t; }"
        : "=r"(a) : "l"(p));
    return a;
}

#define LDSM4(R, A)                                                           \
    asm volatile("ldmatrix.sync.aligned.m8n8.x4.shared.b16 {%0,%1,%2,%3}, [%4];" \
                 : "=r"((R)[0]), "=r"((R)[1]), "=r"((R)[2]), "=r"((R)[3])     \
                 : "r"(A))

#define LDSM4T(R, A)                                                          \
    asm volatile("ldmatrix.sync.aligned.m8n8.x4.trans.shared.b16 {%0,%1,%2,%3}, [%4];" \
                 : "=r"((R)[0]), "=r"((R)[1]), "=r"((R)[2]), "=r"((R)[3])     \
                 : "r"(A))

#define MMA16816(C, A, B)                                                     \
    asm volatile("mma.sync.aligned.m16n8k16.row.col.f32.bf16.bf16.f32 "       \
                 "{%0,%1,%2,%3}, {%4,%5,%6,%7}, {%8,%9}, {%0,%1,%2,%3};"      \
                 : "+f"((C)[0]), "+f"((C)[1]), "+f"((C)[2]), "+f"((C)[3])     \
                 : "r"((A)[0]), "r"((A)[1]), "r"((A)[2]), "r"((A)[3]),        \
                   "r"((B)[0]), "r"((B)[1]))

#define MMAI8(C, A, B)                                                        \
    asm volatile("mma.sync.aligned.m16n8k32.row.col.s32.s8.s8.s32 "           \
                 "{%0,%1,%2,%3}, {%4,%5,%6,%7}, {%8,%9}, {%0,%1,%2,%3};"      \
                 : "+r"((C)[0]), "+r"((C)[1]), "+r"((C)[2]), "+r"((C)[3])     \
                 : "r"((A)[0]), "r"((A)[1]), "r"((A)[2]), "r"((A)[3]),        \
                   "r"((B)[0]), "r"((B)[1]))

#define CPASYNC16(D, S)                                                       \
    asm volatile("cp.async.cg.shared.global [%0], [%1], 16;"                  \
                 :: "r"(D), "l"(S))

// ---------------------------------------------------------------------------
// Row quantization: x ~ scale * (a*128 + b), a,b int8.
// ---------------------------------------------------------------------------
__device__ __forceinline__ float block_rowmax(float m, float* red) {
    const int lane = threadIdx.x & 31, warp = threadIdx.x >> 5;
#pragma unroll
    for (int o = 16; o; o >>= 1)
        m = fmaxf(m, __shfl_xor_sync(0xffffffffu, m, o));
    if (lane == 0) red[warp] = m;
    __syncthreads();
    float r = red[0];
#pragma unroll
    for (int i = 1; i < 8; ++i) r = fmaxf(r, red[i]);
    return r;
}

__device__ __forceinline__ void quant4(const float* v, float s,
                                       char4& qa, char4& qb) {
    float qf0 = v[0] * s, qf1 = v[1] * s, qf2 = v[2] * s, qf3 = v[3] * s;
    float a0 = rintf(qf0 * 0.0078125f), a1 = rintf(qf1 * 0.0078125f);
    float a2 = rintf(qf2 * 0.0078125f), a3 = rintf(qf3 * 0.0078125f);
    qa = make_char4((char)(int)a0, (char)(int)a1, (char)(int)a2, (char)(int)a3);
    qb = make_char4((char)(int)rintf(qf0 - 128.f * a0),
                    (char)(int)rintf(qf1 - 128.f * a1),
                    (char)(int)rintf(qf2 - 128.f * a2),
                    (char)(int)rintf(qf3 - 128.f * a3));
}

// ---------------------------------------------------------------------------
// W_eff = W + L@R, quantized per output row f. One block (256 thr) per row.
// ---------------------------------------------------------------------------
template <int WHICH>
__global__ __launch_bounds__(256)
void weff_q(const float* __restrict__ W,
            const float* __restrict__ L,
            const float* __restrict__ Rm)
{
    __shared__ float red[8];
    int8_t* qa_g = (WHICH == 0) ? g_Wina : g_Wouta;
    int8_t* qb_g = (WHICH == 0) ? g_Winb : g_Woutb;
    float* sc_g  = (WHICH == 0) ? g_sWin : g_sWout;

    const int f = blockIdx.x;
    const int e0 = threadIdx.x * 4;

    float4 wv = *reinterpret_cast<const float4*>(W + (size_t)f * Ee + e0);
    float w[4] = {wv.x, wv.y, wv.z, wv.w};
#pragma unroll
    for (int r = 0; r < Rr; ++r) {
        float lf = L[f * Rr + r];
        float4 rv = *reinterpret_cast<const float4*>(Rm + (size_t)r * Ee + e0);
        w[0] = fmaf(lf, rv.x, w[0]); w[1] = fmaf(lf, rv.y, w[1]);
        w[2] = fmaf(lf, rv.z, w[2]); w[3] = fmaf(lf, rv.w, w[3]);
    }
    float m = fmaxf(fmaxf(fabsf(w[0]), fabsf(w[1])),
                    fmaxf(fabsf(w[2]), fabsf(w[3])));
    m = block_rowmax(m, red);
    float s = (m > 0.f) ? 16256.f / m : 0.f;
    char4 qa, qb;
    quant4(w, s, qa, qb);
    *reinterpret_cast<char4*>(qa_g + (size_t)f * Ee + e0) = qa;
    *reinterpret_cast<char4*>(qb_g + (size_t)f * Ee + e0) = qb;
    if (threadIdx.x == 0) sc_g[f] = m * (1.f / 16256.f);
}

// ---------------------------------------------------------------------------
// Quantize rows of a dense fp32 [8192, 1024] matrix. One block per row.
// DST 0: X=query arg -> g_Qa/g_Qb/g_sQ.  DST 1: g_AO -> g_AOa/g_AOb/g_sAO.
// All global buffers referenced from DEVICE code (the R8 bug fix).
// ---------------------------------------------------------------------------
template <int DST>
__global__ __launch_bounds__(256)
void quant_rows(const float* __restrict__ X)
{
    __shared__ float red[8];
    const float* src = (DST == 0) ? X : g_AO;
    int8_t* qa_g = (DST == 0) ? g_Qa : g_AOa;
    int8_t* qb_g = (DST == 0) ? g_Qb : g_AOb;
    float* sc_g  = (DST == 0) ? g_sQ : g_sAO;

    const int row = blockIdx.x;
    const int e0 = threadIdx.x * 4;
    float4 xv = *reinterpret_cast<const float4*>(src + (size_t)row * Ee + e0);
    float v[4] = {xv.x, xv.y, xv.z, xv.w};
    float m = fmaxf(fmaxf(fabsf(v[0]), fabsf(v[1])),
                    fmaxf(fabsf(v[2]), fabsf(v[3])));
    m = block_rowmax(m, red);
    float s = (m > 0.f) ? 16256.f / m : 0.f;
    char4 qa, qb;
    quant4(v, s, qa, qb);
    *reinterpret_cast<char4*>(qa_g + (size_t)row * Ee + e0) = qa;
    *reinterpret_cast<char4*>(qb_g + (size_t)row * Ee + e0) = qb;
    if (threadIdx.x == 0) sc_g[row] = m * (1.f / 16256.f);
}

// ---------------------------------------------------------------------------
// Int8 tensor-pipe GEMM: C[m][n] = sA[m]*sB[n]*(ac*16384 + (ad+bc)*128) + bias.
// Tile 128x64x32, 8 warps (4x2), 4-stage cp.async (48KB), 2 CTAs/SM.
// MODE 0: A=query-quant, B=Win-quant -> scatter Q/K/V bf16 hi/lo (q *0.125)
// MODE 1: A=AO-quant, B=Wout-quant -> out fp32 + bias
// ---------------------------------------------------------------------------
template <int MODE>
__global__ __launch_bounds__(256, 2)
void gemm_imma(const float* __restrict__ bias, float* __restrict__ out,
               int N, int K)
{
    extern __shared__ __align__(16) char sm[];
    const int8_t* Aga = (MODE == 0) ? g_Qa : g_AOa;
    const int8_t* Agb = (MODE == 0) ? g_Qb : g_AOb;
    const int8_t* Bga = (MODE == 0) ? g_Wina : g_Wouta;
    const int8_t* Bgb = (MODE == 0) ? g_Winb : g_Woutb;
    const float* sA = (MODE == 0) ? g_sQ : g_sAO;
    const float* sB = (MODE == 0) ? g_sWin : g_sWout;

    const int tid  = threadIdx.x;
    const int lane = tid & 31;
    const int wid  = tid >> 5;
    const int wm   = wid >> 1;        // 0..3
    const int wn   = wid & 1;         // 0..1
    const int m0 = blockIdx.y * BM;
    const int n0 = blockIdx.x * BN;

    const uint32_t smb = smem_u32(sm);

    int accm[2][4][4];
    int accx[2][4][4];
#pragma unroll
    for (int a = 0; a < 2; ++a)
#pragma unroll
        for (int b = 0; b < 4; ++b)
#pragma unroll
            for (int c = 0; c < 4; ++c) { accm[a][b][c] = 0; accx[a][b][c] = 0; }

    const int nchunk = K / BK;

#define ISSUE_STAGE(CIDX)                                                     \
    {                                                                         \
        uint32_t base_ = smb + (uint32_t)((CIDX) & 3) * STAGE_B;              \
        {                                                                     \
            int row = tid >> 1, c8 = tid & 1;                                 \
            uint32_t dst = base_ + (uint32_t)(row * 32 + c8 * 16);            \
            size_t go = (size_t)(m0 + row) * K + (CIDX) * 32 + c8 * 16;       \
            CPASYNC16(dst, Aga + go);                                         \
            CPASYNC16(dst + 4096, Agb + go);                                  \
        }                                                                     \
        {                                                                     \
            int t2 = tid & 127;                                               \
            int row = t2 >> 1, c8 = t2 & 1;                                   \
            uint32_t dst = base_ + 8192u + (uint32_t)((tid >> 7) * 2048)      \
                         + (uint32_t)(row * 32 + c8 * 16);                    \
            const int8_t* srcB = (tid < 128) ? Bga : Bgb;                     \
            size_t go = (size_t)(n0 + row) * K + (CIDX) * 32 + c8 * 16;       \
            CPASYNC16(dst, srcB + go);                                        \
        }                                                                     \
        asm volatile("cp.async.commit_group;" ::: "memory");                  \
    }

    ISSUE_STAGE(0);
    ISSUE_STAGE(1);
    ISSUE_STAGE(2);

    const int arow = lane & 15;
    const int achk = lane >> 4;
    const int brow = (lane & 7) + ((lane >> 4) << 3);
    const int bchk = (lane >> 3) & 1;

    for (int c = 0; c < nchunk; ++c) {
        asm volatile("cp.async.wait_group 2;" ::: "memory");
        __syncthreads();

        if (c + 3 < nchunk) ISSUE_STAGE(c + 3);

        {
            uint32_t stb = smb + (uint32_t)(c & 3) * STAGE_B;
            uint32_t Aa[2][4], Ab[2][4];
#pragma unroll
            for (int mt = 0; mt < 2; ++mt) {
                uint32_t off = (uint32_t)((wm * 32 + mt * 16 + arow) * 32 + achk * 16);
                LDSM4(Aa[mt], stb + off);
                LDSM4(Ab[mt], stb + 4096 + off);
            }
            uint32_t Ba[4][2], Bb[4][2];
#pragma unroll
            for (int ng = 0; ng < 2; ++ng) {
                uint32_t off = (uint32_t)((wn * 32 + ng * 16 + brow) * 32 + bchk * 16);
                uint32_t r4[4];
                LDSM4(r4, stb + 8192 + off);
                Ba[ng * 2][0] = r4[0]; Ba[ng * 2][1] = r4[1];
                Ba[ng * 2 + 1][0] = r4[2]; Ba[ng * 2 + 1][1] = r4[3];
                LDSM4(r4, stb + 10240 + off);
                Bb[ng * 2][0] = r4[0]; Bb[ng * 2][1] = r4[1];
                Bb[ng * 2 + 1][0] = r4[2]; Bb[ng * 2 + 1][1] = r4[3];
            }
#pragma unroll
            for (int mt = 0; mt < 2; ++mt)
#pragma unroll
                for (int nb = 0; nb < 4; ++nb) {
                    MMAI8(accm[mt][nb], Aa[mt], Ba[nb]);
                    MMAI8(accx[mt][nb], Aa[mt], Bb[nb]);
                    MMAI8(accx[mt][nb], Ab[mt], Ba[nb]);
                }
        }
    }
#undef ISSUE_STAGE

    __syncthreads();

    const int r = lane >> 2, tg = lane & 3;
#pragma unroll
    for (int mt = 0; mt < 2; ++mt) {
#pragma unroll
        for (int nb = 0; nb < 4; ++nb) {
            int m = m0 + wm * 32 + mt * 16 + r;
            int n = n0 + wn * 32 + nb * 8 + tg * 2;
            float2 bb = *reinterpret_cast<const float2*>(bias + n);
            float2 sb = *reinterpret_cast<const float2*>(sB + n);
#pragma unroll
            for (int half = 0; half < 2; ++half) {
                int mm = m + half * 8;
                float sa = sA[mm];
                float s0 = sa * sb.x, s1 = sa * sb.y;
                float v0 = fmaf((float)accm[mt][nb][half * 2 + 0], 16384.f * s0,
                                (float)accx[mt][nb][half * 2 + 0] * (128.f * s0)) + bb.x;
                float v1 = fmaf((float)accm[mt][nb][half * 2 + 1], 16384.f * s1,
                                (float)accx[mt][nb][half * 2 + 1] * (128.f * s1)) + bb.y;
                if (MODE == 1) {
                    float2 vv = {v0, v1};
                    *reinterpret_cast<float2*>(out + (size_t)mm * N + n) = vv;
                } else {
                    int t = mm >> 3;
                    int b = mm & 7;
                    int which = n >> 10;
                    int h = (n >> 6) & 15;
                    int d = n & 63;
                    float sc = (which == 0) ? 0.125f : 1.0f;
                    float x = v0 * sc, y = v1 * sc;
                    __nv_bfloat16* bph = (which == 0) ? g_Qh : (which == 1) ? g_Kh : g_Vh;
                    __nv_bfloat16* bpl = (which == 0) ? g_Ql : (which == 1) ? g_Kl : g_Vl;
                    size_t off = ((size_t)(b * Hh + h) * Tt + t) * HD + d;
                    float2 vv = {x, y};
                    __nv_bfloat162 hh = __float22bfloat162_rn(vv);
                    *reinterpret_cast<__nv_bfloat162*>(bph + off) = hh;
                    float2 lo = {x - __bfloat162float(hh.x), y - __bfloat162float(hh.y)};
                    *reinterpret_cast<__nv_bfloat162*>(bpl + off) = __float22bfloat162_rn(lo);
                }
            }
        }
    }
}

// ---------------------------------------------------------------------------
// Flash attention on tensor pipe (R7 structure). Grid (b=8, h*8+tq=128) so
// CTAs sharing a rel_pos_bias slab are adjacent; epilogue writes fp32 AO.
// ---------------------------------------------------------------------------
__global__ __launch_bounds__(256, 2)
void attn_mma(const float* __restrict__ rpb)
{
    extern __shared__ __align__(16) char sm[];
    const int tid = threadIdx.x;
    const int lane = tid & 31;
    const int w = tid >> 5;
    const int b = blockIdx.x;
    const int h = blockIdx.y >> 3;
    const int t0 = (blockIdx.y & 7) * 128;
    const int bh = b * Hh + h;

    const uint32_t uQ = smem_u32(sm);
    const uint32_t uS0 = uQ + 32768;

    {
#pragma unroll
        for (int p = 0; p < 8; ++p) {
            int i = tid + p * 256;
            int half = i >> 10, rem = i & 1023;
            int row = rem >> 3, cc = rem & 7;
            const __nv_bfloat16* src = (half ? g_Ql : g_Qh)
                + ((size_t)bh * Tt + t0 + row) * HD + cc * 8;
            uint32_t dst = uQ + half * 16384 + row * 128 + (((cc ^ (row & 7))) << 4);
            CPASYNC16(dst, src);
        }
    }
    const __nv_bfloat16* kvsrc[4] = { g_Kh, g_Kl, g_Vh, g_Vl };
#define LOAD_CHUNK(CIDX, ST)                                                   \
    {                                                                          \
        const uint32_t base_ = uS0 + (uint32_t)(ST) * 32768;                   \
        int s0_ = (CIDX) * 64;                                                 \
        _Pragma("unroll")                                                      \
        for (int p = 0; p < 8; ++p) {                                          \
            int i = tid + p * 256;                                             \
            int tile = i >> 9;                                                 \
            int rem = i & 511;                                                 \
            int row = rem >> 3, cc = rem & 7;                                  \
            const __nv_bfloat16* src = kvsrc[tile]                             \
                + ((size_t)bh * Tt + s0_ + row) * HD + cc * 8;                 \
            uint32_t dst = base_ + tile * 8192 + row * 128                     \
                         + (((cc ^ (row & 7))) << 4);                          \
            CPASYNC16(dst, src);                                               \
        }                                                                      \
    }

    LOAD_CHUNK(0, 0);
    asm volatile("cp.async.commit_group;" ::: "memory");
    LOAD_CHUNK(1, 1);
    asm volatile("cp.async.commit_group;" ::: "memory");

    float o[8][4];
#pragma unroll
    for (int j = 0; j < 8; ++j)
#pragma unroll
        for (int v = 0; v < 4; ++v) o[j][v] = 0.f;
    float m0r = -1e30f, m1r = -1e30f, l0r = 0.f, l1r = 0.f;

    const int rq = lane >> 2;
    const int cq = (lane & 3) * 2;
    const size_t brow0_base = ((size_t)h * Tt + (t0 + w * 16 + rq)) * Tt;
    const size_t brow1_base = brow0_base + 8 * (size_t)Tt;

    const int qrow = w * 16 + (lane & 15);
    const uint32_t qrb = uQ + qrow * 128;
    const uint32_t qsel = (uint32_t)(lane >> 4);

    for (int c = 0; c < 16; ++c) {
        if (c == 15) asm volatile("cp.async.wait_group 0;" ::: "memory");
        else         asm volatile("cp.async.wait_group 1;" ::: "memory");
        __syncthreads();

        const uint32_t stb = uS0 + (uint32_t)(c & 1) * 32768;
        const int g = lane >> 3, i = lane & 7;

        float s[8][4];
#pragma unroll
        for (int j = 0; j < 8; ++j)
#pragma unroll
            for (int v = 0; v < 4; ++v) s[j][v] = 0.f;

#pragma unroll
        for (int kk = 0; kk < 4; ++kk) {
            uint32_t qh[4], ql[4];
            {
                uint32_t ccol = 2u * kk + qsel;
                uint32_t off = ((ccol ^ (qrow & 7)) << 4);
                LDSM4(qh, qrb + off);
                LDSM4(ql, qrb + 16384 + off);
            }
            uint32_t kbh[8][2], kbl[8][2];
            const int brow_off = i + ((g >> 1) << 3);
            const int bkc = kk * 2 + (g & 1);
#pragma unroll
            for (int ng = 0; ng < 4; ++ng) {
                int row = ng * 16 + brow_off;
                uint32_t off = (uint32_t)(row * 128 + ((bkc ^ (row & 7)) << 4));
                uint32_t r4[4];
                LDSM4(r4, stb + off);
                kbh[ng * 2][0] = r4[0]; kbh[ng * 2][1] = r4[1];
                kbh[ng * 2 + 1][0] = r4[2]; kbh[ng * 2 + 1][1] = r4[3];
                LDSM4(r4, stb + 8192 + off);
                kbl[ng * 2][0] = r4[0]; kbl[ng * 2][1] = r4[1];
                kbl[ng * 2 + 1][0] = r4[2]; kbl[ng * 2 + 1][1] = r4[3];
            }
#pragma unroll
            for (int nt = 0; nt < 8; ++nt) {
                MMA16816(s[nt], qh, kbh[nt]);
                MMA16816(s[nt], qh, kbl[nt]);
                MMA16816(s[nt], ql, kbh[nt]);
            }
        }

        {
            const float* bp0 = rpb + brow0_base + c * 64 + cq;
            const float* bp1 = rpb + brow1_base + c * 64 + cq;
#pragma unroll
            for (int j = 0; j < 8; ++j) {
                float2 b0 = *reinterpret_cast<const float2*>(bp0 + j * 8);
                float2 b1 = *reinterpret_cast<const float2*>(bp1 + j * 8);
                s[j][0] += b0.x; s[j][1] += b0.y;
                s[j][2] += b1.x; s[j][3] += b1.y;
            }
        }

        float cm0 = -1e30f, cm1 = -1e30f;
#pragma unroll
        for (int j = 0; j < 8; ++j) {
            cm0 = fmaxf(cm0, fmaxf(s[j][0], s[j][1]));
            cm1 = fmaxf(cm1, fmaxf(s[j][2], s[j][3]));
        }
        cm0 = fmaxf(cm0, __shfl_xor_sync(0xffffffffu, cm0, 1));
        cm0 = fmaxf(cm0, __shfl_xor_sync(0xffffffffu, cm0, 2));
        cm1 = fmaxf(cm1, __shfl_xor_sync(0xffffffffu, cm1, 1));
        cm1 = fmaxf(cm1, __shfl_xor_sync(0xffffffffu, cm1, 2));
        float m0n = fmaxf(m0r, cm0), m1n = fmaxf(m1r, cm1);
        float cor0 = __expf(m0r - m0n), cor1 = __expf(m1r - m1n);
        m0r = m0n; m1r = m1n;
        float rs0 = 0.f, rs1 = 0.f;
#pragma unroll
        for (int j = 0; j < 8; ++j) {
            s[j][0] = __expf(s[j][0] - m0n);
            s[j][1] = __expf(s[j][1] - m0n);
            s[j][2] = __expf(s[j][2] - m1n);
            s[j][3] = __expf(s[j][3] - m1n);
            rs0 += s[j][0] + s[j][1];
            rs1 += s[j][2] + s[j][3];
        }
        rs0 += __shfl_xor_sync(0xffffffffu, rs0, 1);
        rs0 += __shfl_xor_sync(0xffffffffu, rs0, 2);
        rs1 += __shfl_xor_sync(0xffffffffu, rs1, 1);
        rs1 += __shfl_xor_sync(0xffffffffu, rs1, 2);
        l0r = l0r * cor0 + rs0;
        l1r = l1r * cor1 + rs1;
#pragma unroll
        for (int j = 0; j < 8; ++j) {
            o[j][0] *= cor0; o[j][1] *= cor0;
            o[j][2] *= cor1; o[j][3] *= cor1;
        }

        uint32_t ph[8][2], pl[8][2];
#pragma unroll
        for (int j = 0; j < 8; ++j) {
            float2 v0 = {s[j][0], s[j][1]};
            __nv_bfloat162 hh0 = __float22bfloat162_rn(v0);
            ph[j][0] = *reinterpret_cast<uint32_t*>(&hh0);
            float2 lo0 = {s[j][0] - __bfloat162float(hh0.x),
                          s[j][1] - __bfloat162float(hh0.y)};
            __nv_bfloat162 ll0 = __float22bfloat162_rn(lo0);
            pl[j][0] = *reinterpret_cast<uint32_t*>(&ll0);
            float2 v1 = {s[j][2], s[j][3]};
            __nv_bfloat162 hh1 = __float22bfloat162_rn(v1);
            ph[j][1] = *reinterpret_cast<uint32_t*>(&hh1);
            float2 lo1 = {s[j][2] - __bfloat162float(hh1.x),
                          s[j][3] - __bfloat162float(hh1.y)};
            __nv_bfloat162 ll1 = __float22bfloat162_rn(lo1);
            pl[j][1] = *reinterpret_cast<uint32_t*>(&ll1);
        }

#pragma unroll
        for (int kk = 0; kk < 4; ++kk) {
            uint32_t a_h[4] = { ph[2*kk][0], ph[2*kk][1], ph[2*kk+1][0], ph[2*kk+1][1] };
            uint32_t a_l[4] = { pl[2*kk][0], pl[2*kk][1], pl[2*kk+1][0], pl[2*kk+1][1] };
            uint32_t vbh[8][2], vbl[8][2];
            const int srow = kk * 16 + i + ((g >> 1) << 3);
#pragma unroll
            for (int dg = 0; dg < 4; ++dg) {
                int ck = dg * 2 + (g & 1);
                uint32_t off = (uint32_t)(srow * 128 + ((ck ^ (srow & 7)) << 4));
                uint32_t r4[4];
                LDSM4T(r4, stb + 16384 + off);
                vbh[dg * 2][0] = r4[0]; vbh[dg * 2][1] = r4[2];
                vbh[dg * 2 + 1][0] = r4[1]; vbh[dg * 2 + 1][1] = r4[3];
                LDSM4T(r4, stb + 24576 + off);
                vbl[dg * 2][0] = r4[0]; vbl[dg * 2][1] = r4[2];
                vbl[dg * 2 + 1][0] = r4[1]; vbl[dg * 2 + 1][1] = r4[3];
            }
#pragma unroll
            for (int dt = 0; dt < 8; ++dt) {
                MMA16816(o[dt], a_h, vbh[dt]);
                MMA16816(o[dt], a_h, vbl[dt]);
                MMA16816(o[dt], a_l, vbh[dt]);
            }
        }

        __syncthreads();
        if (c + 2 < 16) {
            LOAD_CHUNK(c + 2, c & 1);
            asm volatile("cp.async.commit_group;" ::: "memory");
        }
    }

    float inv0 = 1.f / l0r, inv1 = 1.f / l1r;
    int t_row0 = t0 + w * 16 + rq;
    int t_row1 = t_row0 + 8;
#pragma unroll
    for (int j = 0; j < 8; ++j) {
        int d = j * 8 + cq;
        size_t i0 = ((size_t)t_row0 * Bb + b) * Ee + h * HD + d;
        size_t i1 = ((size_t)t_row1 * Bb + b) * Ee + h * HD + d;
        float2 v0 = {o[j][0] * inv0, o[j][1] * inv0};
        float2 v1 = {o[j][2] * inv1, o[j][3] * inv1};
        *reinterpret_cast<float2*>(g_AO + i0) = v0;
        *reinterpret_cast<float2*>(g_AO + i1) = v1;
    }
#undef LOAD_CHUNK
}

// ---------------------------------------------------------------------------
extern "C" void kernel_launch(void* const* d_in, const int* in_sizes, int n_in,
                              void* d_out, int out_size)
{
    const float* query = (const float*)d_in[0];
    const float* ipw   = (const float*)d_in[1];
    const float* ipb   = (const float*)d_in[2];
    const float* il    = (const float*)d_in[3];
    const float* ir    = (const float*)d_in[4];
    const float* opw   = (const float*)d_in[5];
    const float* opb   = (const float*)d_in[6];
    const float* ol    = (const float*)d_in[7];
    const float* orr   = (const float*)d_in[8];
    const float* rpb   = (const float*)d_in[9];
    float* out = (float*)d_out;

    static bool attr_set = false;
    if (!attr_set) {
        cudaFuncSetAttribute(gemm_imma<0>,
            cudaFuncAttributeMaxDynamicSharedMemorySize, 49152);
        cudaFuncSetAttribute(gemm_imma<1>,
            cudaFuncAttributeMaxDynamicSharedMemorySize, 49152);
        cudaFuncSetAttribute(attn_mma,
            cudaFuncAttributeMaxDynamicSharedMemorySize, 98304);
        attr_set = true;
    }

    weff_q<0><<<F3, 256>>>(ipw, il, ir);
    weff_q<1><<<Ee, 256>>>(opw, ol, orr);
    quant_rows<0><<<Nrows, 256>>>(query);

    gemm_imma<0><<<dim3(F3 / BN, Nrows / BM), 256, 49152>>>(ipb, nullptr, F3, Ee);

    attn_mma<<<dim3(Bb, Hh * 8), 256, 98304>>>(rpb);

    quant_rows<1><<<Nrows, 256>>>(nullptr);

    gemm_imma<1><<<dim3(Ee / BN, Nrows / BM), 256, 49152>>>(opb, out, Ee, Ee);
}

// round 10
// speedup vs baseline: 2.0072x; 2.0072x over previous
#include <cuda_runtime.h>
#include <cuda_bf16.h>
#include <cstdint>

// ---------------------------------------------------------------------------
// MultiheadAttention with low-rank-augmented in/out projections.
// T=1024, B=8, E=1024, H=16, R=16, HD=64.
//
// R10: revert to R7 (bf16 hi/lo split mma everywhere — int8 mma.sync proved
//      ~2x slower per MAC on sm_103a) + attention grid reordered (b fastest)
//      so CTAs sharing a rel_pos_bias slab are launch-adjacent (L2 reuse).
// ---------------------------------------------------------------------------

namespace {
constexpr int Tt = 1024;
constexpr int Bb = 8;
constexpr int Ee = 1024;
constexpr int Hh = 16;
constexpr int Rr = 16;
constexpr int HD = 64;
constexpr int F3 = 3 * Ee;          // 3072
constexpr int Nrows = Tt * Bb;      // 8192
constexpr int BM = 128, BN = 64, BK = 32;
constexpr int STAGE_B = 24576;      // Ah 8K, Al 8K, Bh 4K, Bl 4K
}

// Scratch (device globals; no runtime allocation).
__device__ __align__(16) __nv_bfloat16 g_Win_h[F3 * Ee];
__device__ __align__(16) __nv_bfloat16 g_Win_l[F3 * Ee];
__device__ __align__(16) __nv_bfloat16 g_Wout_h[Ee * Ee];
__device__ __align__(16) __nv_bfloat16 g_Wout_l[Ee * Ee];
__device__ __align__(16) __nv_bfloat16 g_Ah[Nrows * Ee];
__device__ __align__(16) __nv_bfloat16 g_Al[Nrows * Ee];
__device__ __align__(16) __nv_bfloat16 g_AOh[Nrows * Ee];
__device__ __align__(16) __nv_bfloat16 g_AOl[Nrows * Ee];
__device__ __align__(16) __nv_bfloat16 g_Qh[Bb * Hh * Tt * HD];
__device__ __align__(16) __nv_bfloat16 g_Ql[Bb * Hh * Tt * HD];
__device__ __align__(16) __nv_bfloat16 g_Kh[Bb * Hh * Tt * HD];
__device__ __align__(16) __nv_bfloat16 g_Kl[Bb * Hh * Tt * HD];
__device__ __align__(16) __nv_bfloat16 g_Vh[Bb * Hh * Tt * HD];
__device__ __align__(16) __nv_bfloat16 g_Vl[Bb * Hh * Tt * HD];

// ---------------------------------------------------------------------------
__device__ __forceinline__ uint32_t smem_u32(const void* p) {
    uint32_t a;
    asm("{ .reg .u64 t; cvta.to.shared.u64 t, %1; cvt.u32.u64 %0, t; }"
        : "=r"(a) : "l"(p));
    return a;
}

__device__ __forceinline__ void split_bf(float x, __nv_bfloat16& h, __nv_bfloat16& l) {
    h = __float2bfloat16(x);
    l = __float2bfloat16(x - __bfloat162float(h));
}

#define LDSM4(R, A)                                                           \
    asm volatile("ldmatrix.sync.aligned.m8n8.x4.shared.b16 {%0,%1,%2,%3}, [%4];" \
                 : "=r"((R)[0]), "=r"((R)[1]), "=r"((R)[2]), "=r"((R)[3])     \
                 : "r"(A))

#define LDSM4T(R, A)                                                          \
    asm volatile("ldmatrix.sync.aligned.m8n8.x4.trans.shared.b16 {%0,%1,%2,%3}, [%4];" \
                 : "=r"((R)[0]), "=r"((R)[1]), "=r"((R)[2]), "=r"((R)[3])     \
                 : "r"(A))

#define MMA16816(C, A, B)                                                     \
    asm volatile("mma.sync.aligned.m16n8k16.row.col.f32.bf16.bf16.f32 "       \
                 "{%0,%1,%2,%3}, {%4,%5,%6,%7}, {%8,%9}, {%0,%1,%2,%3};"      \
                 : "+f"((C)[0]), "+f"((C)[1]), "+f"((C)[2]), "+f"((C)[3])     \
                 : "r"((A)[0]), "r"((A)[1]), "r"((A)[2]), "r"((A)[3]),        \
                   "r"((B)[0]), "r"((B)[1]))

#define CPASYNC16(D, S)                                                       \
    asm volatile("cp.async.cg.shared.global [%0], [%1], 16;"                  \
                 :: "r"(D), "l"(S))

// ---------------------------------------------------------------------------
// W_eff = W + L@R, written as bf16 hi/lo split.
// ---------------------------------------------------------------------------
template <int WHICH>
__global__ void weff_kernel(const float* __restrict__ W,
                            const float* __restrict__ L,
                            const float* __restrict__ Rm)
{
    const int F = (WHICH == 0) ? F3 : Ee;
    __nv_bfloat16* oh = (WHICH == 0) ? g_Win_h : g_Wout_h;
    __nv_bfloat16* ol = (WHICH == 0) ? g_Win_l : g_Wout_l;
    int idx = blockIdx.x * 256 + threadIdx.x;
    if (idx >= F * Ee) return;
    int f = idx >> 10;
    int e = idx & 1023;
    float s = W[idx];
#pragma unroll
    for (int r = 0; r < Rr; ++r)
        s = fmaf(L[f * Rr + r], Rm[r * Ee + e], s);
    __nv_bfloat16 h, l;
    split_bf(s, h, l);
    oh[idx] = h;
    ol[idx] = l;
}

// ---------------------------------------------------------------------------
// Split query (fp32) into bf16 hi/lo.
// ---------------------------------------------------------------------------
__global__ void qsplit_kernel(const float* __restrict__ q)
{
    int idx = (blockIdx.x * 256 + threadIdx.x) * 4;
    float4 v = *reinterpret_cast<const float4*>(q + idx);
    __nv_bfloat16 h0, h1, h2, h3, l0, l1, l2, l3;
    split_bf(v.x, h0, l0); split_bf(v.y, h1, l1);
    split_bf(v.z, h2, l2); split_bf(v.w, h3, l3);
    __nv_bfloat162* ph = reinterpret_cast<__nv_bfloat162*>(g_Ah + idx);
    __nv_bfloat162* pl = reinterpret_cast<__nv_bfloat162*>(g_Al + idx);
    ph[0] = __nv_bfloat162(h0, h1); ph[1] = __nv_bfloat162(h2, h3);
    pl[0] = __nv_bfloat162(l0, l1); pl[1] = __nv_bfloat162(l2, l3);
}

// ---------------------------------------------------------------------------
// Tensor-pipe GEMM via mma.sync bf16 split: C = A·W^T + bias.
// Tile 128x64x32, 8 warps (4x2), warp tile 32x32, 4-stage cp.async (96KB),
// launch_bounds(256,2) -> 2 CTAs/SM. (R6/R7 structure)
// ---------------------------------------------------------------------------
template <int MODE>
__global__ __launch_bounds__(256, 2)
void gemm_mma(const float* __restrict__ bias, float* __restrict__ out,
              int N, int K)
{
    extern __shared__ __align__(16) char sm[];
    const __nv_bfloat16* Agh = (MODE == 0) ? g_Ah : g_AOh;
    const __nv_bfloat16* Agl = (MODE == 0) ? g_Al : g_AOl;
    const __nv_bfloat16* Bgh = (MODE == 0) ? g_Win_h : g_Wout_h;
    const __nv_bfloat16* Bgl = (MODE == 0) ? g_Win_l : g_Wout_l;

    const int tid  = threadIdx.x;
    const int lane = tid & 31;
    const int wid  = tid >> 5;
    const int wm   = wid >> 1;
    const int wn   = wid & 1;
    const int m0 = blockIdx.y * BM;
    const int n0 = blockIdx.x * BN;

    const uint32_t smb = smem_u32(sm);

    float acc[2][4][4];
#pragma unroll
    for (int a = 0; a < 2; ++a)
#pragma unroll
        for (int b = 0; b < 4; ++b)
#pragma unroll
            for (int c = 0; c < 4; ++c) acc[a][b][c] = 0.f;

    const int nchunk = K / BK;

#define ISSUE_STAGE(CIDX)                                                     \
    {                                                                         \
        uint32_t base_ = smb + (uint32_t)((CIDX) & 3) * STAGE_B;              \
        _Pragma("unroll")                                                     \
        for (int p = 0; p < 2; ++p) {                                         \
            int idx = tid + p * 256;                                          \
            int row = idx >> 2, c8 = idx & 3;                                 \
            uint32_t sw = (uint32_t)(row * 64 + ((c8 ^ ((row >> 1) & 3)) << 4)); \
            size_t go = (size_t)(m0 + row) * K + (CIDX) * 32 + c8 * 8;        \
            CPASYNC16(base_ + sw, Agh + go);                                  \
            CPASYNC16(base_ + 8192 + sw, Agl + go);                           \
        }                                                                     \
        {                                                                     \
            int row = tid >> 2, c8 = tid & 3;                                 \
            uint32_t sw = (uint32_t)(row * 64 + ((c8 ^ ((row >> 1) & 3)) << 4)); \
            size_t go = (size_t)(n0 + row) * K + (CIDX) * 32 + c8 * 8;        \
            CPASYNC16(base_ + 16384 + sw, Bgh + go);                          \
            CPASYNC16(base_ + 20480 + sw, Bgl + go);                          \
        }                                                                     \
        asm volatile("cp.async.commit_group;" ::: "memory");                  \
    }

    ISSUE_STAGE(0);
    ISSUE_STAGE(1);
    ISSUE_STAGE(2);

    for (int c = 0; c < nchunk; ++c) {
        asm volatile("cp.async.wait_group 2;" ::: "memory");
        __syncthreads();

        if (c + 3 < nchunk) ISSUE_STAGE(c + 3);

        {
            uint32_t stb = smb + (uint32_t)(c & 3) * STAGE_B;
            const int g = lane >> 3, i = lane & 7;
#pragma unroll
            for (int ks = 0; ks < 2; ++ks) {
                uint32_t ah[2][4], al[2][4];
                const int arow_off = i + ((g & 1) << 3);
                const int akc = ks * 2 + (g >> 1);
#pragma unroll
                for (int mt = 0; mt < 2; ++mt) {
                    int row = wm * 32 + mt * 16 + arow_off;
                    uint32_t off = (uint32_t)(row * 64 + ((akc ^ ((row >> 1) & 3)) << 4));
                    LDSM4(ah[mt], stb + off);
                    LDSM4(al[mt], stb + 8192 + off);
                }
                uint32_t bh[4][2], bl[4][2];
                const int brow_off = i + ((g >> 1) << 3);
                const int bkc = ks * 2 + (g & 1);
#pragma unroll
                for (int np = 0; np < 2; ++np) {
                    int row = wn * 32 + np * 16 + brow_off;
                    uint32_t off = (uint32_t)(row * 64 + ((bkc ^ ((row >> 1) & 3)) << 4));
                    uint32_t r4[4];
                    LDSM4(r4, stb + 16384 + off);
                    bh[np * 2][0] = r4[0]; bh[np * 2][1] = r4[1];
                    bh[np * 2 + 1][0] = r4[2]; bh[np * 2 + 1][1] = r4[3];
                    LDSM4(r4, stb + 20480 + off);
                    bl[np * 2][0] = r4[0]; bl[np * 2][1] = r4[1];
                    bl[np * 2 + 1][0] = r4[2]; bl[np * 2 + 1][1] = r4[3];
                }
#pragma unroll
                for (int mt = 0; mt < 2; ++mt)
#pragma unroll
                    for (int nb = 0; nb < 4; ++nb) {
                        MMA16816(acc[mt][nb], ah[mt], bh[nb]);
                        MMA16816(acc[mt][nb], ah[mt], bl[nb]);
                        MMA16816(acc[mt][nb], al[mt], bh[nb]);
                    }
            }
        }
    }
#undef ISSUE_STAGE

    __syncthreads();

    const int r = lane >> 2, tg = lane & 3;
#pragma unroll
    for (int mt = 0; mt < 2; ++mt) {
#pragma unroll
        for (int nb = 0; nb < 4; ++nb) {
            int m = m0 + wm * 32 + mt * 16 + r;
            int n = n0 + wn * 32 + nb * 8 + tg * 2;
            float2 bb = *reinterpret_cast<const float2*>(bias + n);
#pragma unroll
            for (int half = 0; half < 2; ++half) {
                int mm = m + half * 8;
                float v0 = acc[mt][nb][half * 2 + 0] + bb.x;
                float v1 = acc[mt][nb][half * 2 + 1] + bb.y;
                if (MODE == 1) {
                    float2 vv = {v0, v1};
                    *reinterpret_cast<float2*>(out + (size_t)mm * N + n) = vv;
                } else {
                    int t = mm >> 3;
                    int b = mm & 7;
                    int which = n >> 10;
                    int h = (n >> 6) & 15;
                    int d = n & 63;
                    float sc = (which == 0) ? 0.125f : 1.0f;
                    float x = v0 * sc, y = v1 * sc;
                    __nv_bfloat16* bph = (which == 0) ? g_Qh : (which == 1) ? g_Kh : g_Vh;
                    __nv_bfloat16* bpl = (which == 0) ? g_Ql : (which == 1) ? g_Kl : g_Vl;
                    size_t off = ((size_t)(b * Hh + h) * Tt + t) * HD + d;
                    float2 vv = {x, y};
                    __nv_bfloat162 hh = __float22bfloat162_rn(vv);
                    *reinterpret_cast<__nv_bfloat162*>(bph + off) = hh;
                    float2 lo = {x - __bfloat162float(hh.x), y - __bfloat162float(hh.y)};
                    *reinterpret_cast<__nv_bfloat162*>(bpl + off) = __float22bfloat162_rn(lo);
                }
            }
        }
    }
}

// ---------------------------------------------------------------------------
// Flash attention on tensor pipe (R7 structure), 2 CTAs/SM, Q reloaded from
// smem per k-step. Grid (b, h*8+tq): the 8 batch CTAs sharing a bias slab
// are launch-adjacent -> rel_pos_bias reads hit L2.
// ---------------------------------------------------------------------------
__global__ __launch_bounds__(256, 2)
void attn_mma(const float* __restrict__ rpb)
{
    extern __shared__ __align__(16) char sm[];
    const int tid = threadIdx.x;
    const int lane = tid & 31;
    const int w = tid >> 5;
    const int b = blockIdx.x;
    const int h = blockIdx.y >> 3;
    const int t0 = (blockIdx.y & 7) * 128;
    const int bh = b * Hh + h;

    const uint32_t uQ = smem_u32(sm);
    const uint32_t uS0 = uQ + 32768;

    {
#pragma unroll
        for (int p = 0; p < 8; ++p) {
            int i = tid + p * 256;
            int half = i >> 10, rem = i & 1023;
            int row = rem >> 3, cc = rem & 7;
            const __nv_bfloat16* src = (half ? g_Ql : g_Qh)
                + ((size_t)bh * Tt + t0 + row) * HD + cc * 8;
            uint32_t dst = uQ + half * 16384 + row * 128 + (((cc ^ (row & 7))) << 4);
            CPASYNC16(dst, src);
        }
    }
    const __nv_bfloat16* kvsrc[4] = { g_Kh, g_Kl, g_Vh, g_Vl };
#define LOAD_CHUNK(CIDX, ST)                                                   \
    {                                                                          \
        const uint32_t base_ = uS0 + (uint32_t)(ST) * 32768;                   \
        int s0_ = (CIDX) * 64;                                                 \
        _Pragma("unroll")                                                      \
        for (int p = 0; p < 8; ++p) {                                          \
            int i = tid + p * 256;                                             \
            int tile = i >> 9;                                                 \
            int rem = i & 511;                                                 \
            int row = rem >> 3, cc = rem & 7;                                  \
            const __nv_bfloat16* src = kvsrc[tile]                             \
                + ((size_t)bh * Tt + s0_ + row) * HD + cc * 8;                 \
            uint32_t dst = base_ + tile * 8192 + row * 128                     \
                         + (((cc ^ (row & 7))) << 4);                          \
            CPASYNC16(dst, src);                                               \
        }                                                                      \
    }

    LOAD_CHUNK(0, 0);
    asm volatile("cp.async.commit_group;" ::: "memory");
    LOAD_CHUNK(1, 1);
    asm volatile("cp.async.commit_group;" ::: "memory");

    float o[8][4];
#pragma unroll
    for (int j = 0; j < 8; ++j)
#pragma unroll
        for (int v = 0; v < 4; ++v) o[j][v] = 0.f;
    float m0r = -1e30f, m1r = -1e30f, l0r = 0.f, l1r = 0.f;

    const int rq = lane >> 2;
    const int cq = (lane & 3) * 2;
    const size_t brow0_base = ((size_t)h * Tt + (t0 + w * 16 + rq)) * Tt;
    const size_t brow1_base = brow0_base + 8 * (size_t)Tt;

    const int qrow = w * 16 + (lane & 15);
    const uint32_t qrb = uQ + qrow * 128;
    const uint32_t qsel = (uint32_t)(lane >> 4);

    for (int c = 0; c < 16; ++c) {
        if (c == 15) asm volatile("cp.async.wait_group 0;" ::: "memory");
        else         asm volatile("cp.async.wait_group 1;" ::: "memory");
        __syncthreads();

        const uint32_t stb = uS0 + (uint32_t)(c & 1) * 32768;
        const int g = lane >> 3, i = lane & 7;

        float s[8][4];
#pragma unroll
        for (int j = 0; j < 8; ++j)
#pragma unroll
            for (int v = 0; v < 4; ++v) s[j][v] = 0.f;

#pragma unroll
        for (int kk = 0; kk < 4; ++kk) {
            uint32_t qh[4], ql[4];
            {
                uint32_t ccol = 2u * kk + qsel;
                uint32_t off = ((ccol ^ (qrow & 7)) << 4);
                LDSM4(qh, qrb + off);
                LDSM4(ql, qrb + 16384 + off);
            }
            uint32_t kbh[8][2], kbl[8][2];
            const int brow_off = i + ((g >> 1) << 3);
            const int bkc = kk * 2 + (g & 1);
#pragma unroll
            for (int ng = 0; ng < 4; ++ng) {
                int row = ng * 16 + brow_off;
                uint32_t off = (uint32_t)(row * 128 + ((bkc ^ (row & 7)) << 4));
                uint32_t r4[4];
                LDSM4(r4, stb + off);
                kbh[ng * 2][0] = r4[0]; kbh[ng * 2][1] = r4[1];
                kbh[ng * 2 + 1][0] = r4[2]; kbh[ng * 2 + 1][1] = r4[3];
                LDSM4(r4, stb + 8192 + off);
                kbl[ng * 2][0] = r4[0]; kbl[ng * 2][1] = r4[1];
                kbl[ng * 2 + 1][0] = r4[2]; kbl[ng * 2 + 1][1] = r4[3];
            }
#pragma unroll
            for (int nt = 0; nt < 8; ++nt) {
                MMA16816(s[nt], qh, kbh[nt]);
                MMA16816(s[nt], qh, kbl[nt]);
                MMA16816(s[nt], ql, kbh[nt]);
            }
        }

        {
            const float* bp0 = rpb + brow0_base + c * 64 + cq;
            const float* bp1 = rpb + brow1_base + c * 64 + cq;
#pragma unroll
            for (int j = 0; j < 8; ++j) {
                float2 b0 = *reinterpret_cast<const float2*>(bp0 + j * 8);
                float2 b1 = *reinterpret_cast<const float2*>(bp1 + j * 8);
                s[j][0] += b0.x; s[j][1] += b0.y;
                s[j][2] += b1.x; s[j][3] += b1.y;
            }
        }

        float cm0 = -1e30f, cm1 = -1e30f;
#pragma unroll
        for (int j = 0; j < 8; ++j) {
            cm0 = fmaxf(cm0, fmaxf(s[j][0], s[j][1]));
            cm1 = fmaxf(cm1, fmaxf(s[j][2], s[j][3]));
        }
        cm0 = fmaxf(cm0, __shfl_xor_sync(0xffffffffu, cm0, 1));
        cm0 = fmaxf(cm0, __shfl_xor_sync(0xffffffffu, cm0, 2));
        cm1 = fmaxf(cm1, __shfl_xor_sync(0xffffffffu, cm1, 1));
        cm1 = fmaxf(cm1, __shfl_xor_sync(0xffffffffu, cm1, 2));
        float m0n = fmaxf(m0r, cm0), m1n = fmaxf(m1r, cm1);
        float cor0 = __expf(m0r - m0n), cor1 = __expf(m1r - m1n);
        m0r = m0n; m1r = m1n;
        float rs0 = 0.f, rs1 = 0.f;
#pragma unroll
        for (int j = 0; j < 8; ++j) {
            s[j][0] = __expf(s[j][0] - m0n);
            s[j][1] = __expf(s[j][1] - m0n);
            s[j][2] = __expf(s[j][2] - m1n);
            s[j][3] = __expf(s[j][3] - m1n);
            rs0 += s[j][0] + s[j][1];
            rs1 += s[j][2] + s[j][3];
        }
        rs0 += __shfl_xor_sync(0xffffffffu, rs0, 1);
        rs0 += __shfl_xor_sync(0xffffffffu, rs0, 2);
        rs1 += __shfl_xor_sync(0xffffffffu, rs1, 1);
        rs1 += __shfl_xor_sync(0xffffffffu, rs1, 2);
        l0r = l0r * cor0 + rs0;
        l1r = l1r * cor1 + rs1;
#pragma unroll
        for (int j = 0; j < 8; ++j) {
            o[j][0] *= cor0; o[j][1] *= cor0;
            o[j][2] *= cor1; o[j][3] *= cor1;
        }

        uint32_t ph[8][2], pl[8][2];
#pragma unroll
        for (int j = 0; j < 8; ++j) {
            float2 v0 = {s[j][0], s[j][1]};
            __nv_bfloat162 hh0 = __float22bfloat162_rn(v0);
            ph[j][0] = *reinterpret_cast<uint32_t*>(&hh0);
            float2 lo0 = {s[j][0] - __bfloat162float(hh0.x),
                          s[j][1] - __bfloat162float(hh0.y)};
            __nv_bfloat162 ll0 = __float22bfloat162_rn(lo0);
            pl[j][0] = *reinterpret_cast<uint32_t*>(&ll0);
            float2 v1 = {s[j][2], s[j][3]};
            __nv_bfloat162 hh1 = __float22bfloat162_rn(v1);
            ph[j][1] = *reinterpret_cast<uint32_t*>(&hh1);
            float2 lo1 = {s[j][2] - __bfloat162float(hh1.x),
                          s[j][3] - __bfloat162float(hh1.y)};
            __nv_bfloat162 ll1 = __float22bfloat162_rn(lo1);
            pl[j][1] = *reinterpret_cast<uint32_t*>(&ll1);
        }

#pragma unroll
        for (int kk = 0; kk < 4; ++kk) {
            uint32_t a_h[4] = { ph[2*kk][0], ph[2*kk][1], ph[2*kk+1][0], ph[2*kk+1][1] };
            uint32_t a_l[4] = { pl[2*kk][0], pl[2*kk][1], pl[2*kk+1][0], pl[2*kk+1][1] };
            uint32_t vbh[8][2], vbl[8][2];
            const int srow = kk * 16 + i + ((g >> 1) << 3);
#pragma unroll
            for (int dg = 0; dg < 4; ++dg) {
                int ck = dg * 2 + (g & 1);
                uint32_t off = (uint32_t)(srow * 128 + ((ck ^ (srow & 7)) << 4));
                uint32_t r4[4];
                LDSM4T(r4, stb + 16384 + off);
                vbh[dg * 2][0] = r4[0]; vbh[dg * 2][1] = r4[2];
                vbh[dg * 2 + 1][0] = r4[1]; vbh[dg * 2 + 1][1] = r4[3];
                LDSM4T(r4, stb + 24576 + off);
                vbl[dg * 2][0] = r4[0]; vbl[dg * 2][1] = r4[2];
                vbl[dg * 2 + 1][0] = r4[1]; vbl[dg * 2 + 1][1] = r4[3];
            }
#pragma unroll
            for (int dt = 0; dt < 8; ++dt) {
                MMA16816(o[dt], a_h, vbh[dt]);
                MMA16816(o[dt], a_h, vbl[dt]);
                MMA16816(o[dt], a_l, vbh[dt]);
            }
        }

        __syncthreads();
        if (c + 2 < 16) {
            LOAD_CHUNK(c + 2, c & 1);
            asm volatile("cp.async.commit_group;" ::: "memory");
        }
    }

    float inv0 = 1.f / l0r, inv1 = 1.f / l1r;
    int t_row0 = t0 + w * 16 + rq;
    int t_row1 = t_row0 + 8;
#pragma unroll
    for (int j = 0; j < 8; ++j) {
        int d = j * 8 + cq;
        size_t i0 = ((size_t)t_row0 * Bb + b) * Ee + h * HD + d;
        size_t i1 = ((size_t)t_row1 * Bb + b) * Ee + h * HD + d;
        float x0 = o[j][0] * inv0, y0 = o[j][1] * inv0;
        float x1 = o[j][2] * inv1, y1 = o[j][3] * inv1;
        float2 v0 = {x0, y0};
        __nv_bfloat162 hh0 = __float22bfloat162_rn(v0);
        *reinterpret_cast<__nv_bfloat162*>(g_AOh + i0) = hh0;
        float2 lo0 = {x0 - __bfloat162float(hh0.x), y0 - __bfloat162float(hh0.y)};
        *reinterpret_cast<__nv_bfloat162*>(g_AOl + i0) = __float22bfloat162_rn(lo0);
        float2 v1 = {x1, y1};
        __nv_bfloat162 hh1 = __float22bfloat162_rn(v1);
        *reinterpret_cast<__nv_bfloat162*>(g_AOh + i1) = hh1;
        float2 lo1 = {x1 - __bfloat162float(hh1.x), y1 - __bfloat162float(hh1.y)};
        *reinterpret_cast<__nv_bfloat162*>(g_AOl + i1) = __float22bfloat162_rn(lo1);
    }
#undef LOAD_CHUNK
}

// ---------------------------------------------------------------------------
extern "C" void kernel_launch(void* const* d_in, const int* in_sizes, int n_in,
                              void* d_out, int out_size)
{
    const float* query = (const float*)d_in[0];
    const float* ipw   = (const float*)d_in[1];
    const float* ipb   = (const float*)d_in[2];
    const float* il    = (const float*)d_in[3];
    const float* ir    = (const float*)d_in[4];
    const float* opw   = (const float*)d_in[5];
    const float* opb   = (const float*)d_in[6];
    const float* ol    = (const float*)d_in[7];
    const float* orr   = (const float*)d_in[8];
    const float* rpb   = (const float*)d_in[9];
    float* out = (float*)d_out;

    static bool attr_set = false;
    if (!attr_set) {
        cudaFuncSetAttribute(gemm_mma<0>,
            cudaFuncAttributeMaxDynamicSharedMemorySize, 98304);
        cudaFuncSetAttribute(gemm_mma<1>,
            cudaFuncAttributeMaxDynamicSharedMemorySize, 98304);
        cudaFuncSetAttribute(attn_mma,
            cudaFuncAttributeMaxDynamicSharedMemorySize, 98304);
        attr_set = true;
    }

    weff_kernel<0><<<(F3 * Ee + 255) / 256, 256>>>(ipw, il, ir);
    weff_kernel<1><<<(Ee * Ee + 255) / 256, 256>>>(opw, ol, orr);
    qsplit_kernel<<<Nrows * Ee / 1024, 256>>>(query);

    gemm_mma<0><<<dim3(F3 / BN, Nrows / BM), 256, 98304>>>(ipb, nullptr, F3, Ee);

    attn_mma<<<dim3(Bb, Hh * 8), 256, 98304>>>(rpb);

    gemm_mma<1><<<dim3(Ee / BN, Nrows / BM), 256, 98304>>>(opb, out, Ee, Ee);
}

// round 11
// speedup vs baseline: 2.3896x; 1.1905x over previous
#include <cuda_runtime.h>
#include <cuda_bf16.h>
#include <cuda_fp16.h>
#include <cstdint>

// ---------------------------------------------------------------------------
// MultiheadAttention with low-rank-augmented in/out projections.
// T=1024, B=8, E=1024, H=16, R=16, HD=64.
//
// R11: projection GEMMs use ASYMMETRIC fp16 split — A (activations) in fp16
//      hi/lo, W single fp16: C = Ah*W + Al*W (2 mmas per k16, was 3 with
//      bf16). Error = W quantization ~2.8e-4 norm-rel per GEMM.
//      Attention unchanged (bf16 3-term); its epilogue emits fp16 hi/lo.
// ---------------------------------------------------------------------------

namespace {
constexpr int Tt = 1024;
constexpr int Bb = 8;
constexpr int Ee = 1024;
constexpr int Hh = 16;
constexpr int Rr = 16;
constexpr int HD = 64;
constexpr int F3 = 3 * Ee;          // 3072
constexpr int Nrows = Tt * Bb;      // 8192
constexpr int BM = 128, BN = 64, BK = 32;
constexpr int STAGE_B = 20480;      // Ah 8K, Al 8K, W 4K
}

// Scratch (device globals; no runtime allocation).
__device__ __align__(16) __half g_Win_h[F3 * Ee];
__device__ __align__(16) __half g_Wout_h[Ee * Ee];
__device__ __align__(16) __half g_Ah[Nrows * Ee];
__device__ __align__(16) __half g_Al[Nrows * Ee];
__device__ __align__(16) __half g_AOh[Nrows * Ee];
__device__ __align__(16) __half g_AOl[Nrows * Ee];
__device__ __align__(16) __nv_bfloat16 g_Qh[Bb * Hh * Tt * HD];
__device__ __align__(16) __nv_bfloat16 g_Ql[Bb * Hh * Tt * HD];
__device__ __align__(16) __nv_bfloat16 g_Kh[Bb * Hh * Tt * HD];
__device__ __align__(16) __nv_bfloat16 g_Kl[Bb * Hh * Tt * HD];
__device__ __align__(16) __nv_bfloat16 g_Vh[Bb * Hh * Tt * HD];
__device__ __align__(16) __nv_bfloat16 g_Vl[Bb * Hh * Tt * HD];

// ---------------------------------------------------------------------------
__device__ __forceinline__ uint32_t smem_u32(const void* p) {
    uint32_t a;
    asm("{ .reg .u64 t; cvta.to.shared.u64 t, %1; cvt.u32.u64 %0, t; }"
        : "=r"(a) : "l"(p));
    return a;
}

__device__ __forceinline__ void split_bf(float x, __nv_bfloat16& h, __nv_bfloat16& l) {
    h = __float2bfloat16(x);
    l = __float2bfloat16(x - __bfloat162float(h));
}

__device__ __forceinline__ void split_h(float x, __half& h, __half& l) {
    h = __float2half(x);
    l = __float2half(x - __half2float(h));
}

#define LDSM4(R, A)                                                           \
    asm volatile("ldmatrix.sync.aligned.m8n8.x4.shared.b16 {%0,%1,%2,%3}, [%4];" \
                 : "=r"((R)[0]), "=r"((R)[1]), "=r"((R)[2]), "=r"((R)[3])     \
                 : "r"(A))

#define LDSM4T(R, A)                                                          \
    asm volatile("ldmatrix.sync.aligned.m8n8.x4.trans.shared.b16 {%0,%1,%2,%3}, [%4];" \
                 : "=r"((R)[0]), "=r"((R)[1]), "=r"((R)[2]), "=r"((R)[3])     \
                 : "r"(A))

#define MMA16816(C, A, B)                                                     \
    asm volatile("mma.sync.aligned.m16n8k16.row.col.f32.bf16.bf16.f32 "       \
                 "{%0,%1,%2,%3}, {%4,%5,%6,%7}, {%8,%9}, {%0,%1,%2,%3};"      \
                 : "+f"((C)[0]), "+f"((C)[1]), "+f"((C)[2]), "+f"((C)[3])     \
                 : "r"((A)[0]), "r"((A)[1]), "r"((A)[2]), "r"((A)[3]),        \
                   "r"((B)[0]), "r"((B)[1]))

#define MMAF16(C, A, B)                                                       \
    asm volatile("mma.sync.aligned.m16n8k16.row.col.f32.f16.f16.f32 "         \
                 "{%0,%1,%2,%3}, {%4,%5,%6,%7}, {%8,%9}, {%0,%1,%2,%3};"      \
                 : "+f"((C)[0]), "+f"((C)[1]), "+f"((C)[2]), "+f"((C)[3])     \
                 : "r"((A)[0]), "r"((A)[1]), "r"((A)[2]), "r"((A)[3]),        \
                   "r"((B)[0]), "r"((B)[1]))

#define CPASYNC16(D, S)                                                       \
    asm volatile("cp.async.cg.shared.global [%0], [%1], 16;"                  \
                 :: "r"(D), "l"(S))

// ---------------------------------------------------------------------------
// W_eff = W + L@R, written as single fp16.
// ---------------------------------------------------------------------------
template <int WHICH>
__global__ void weff_kernel(const float* __restrict__ W,
                            const float* __restrict__ L,
                            const float* __restrict__ Rm)
{
    const int F = (WHICH == 0) ? F3 : Ee;
    __half* oh = (WHICH == 0) ? g_Win_h : g_Wout_h;
    int idx = blockIdx.x * 256 + threadIdx.x;
    if (idx >= F * Ee) return;
    int f = idx >> 10;
    int e = idx & 1023;
    float s = W[idx];
#pragma unroll
    for (int r = 0; r < Rr; ++r)
        s = fmaf(L[f * Rr + r], Rm[r * Ee + e], s);
    oh[idx] = __float2half(s);
}

// ---------------------------------------------------------------------------
// Split query (fp32) into fp16 hi/lo.
// ---------------------------------------------------------------------------
__global__ void qsplit_kernel(const float* __restrict__ q)
{
    int idx = (blockIdx.x * 256 + threadIdx.x) * 4;
    float4 v = *reinterpret_cast<const float4*>(q + idx);
    __half h0, h1, h2, h3, l0, l1, l2, l3;
    split_h(v.x, h0, l0); split_h(v.y, h1, l1);
    split_h(v.z, h2, l2); split_h(v.w, h3, l3);
    __half2* ph = reinterpret_cast<__half2*>(g_Ah + idx);
    __half2* pl = reinterpret_cast<__half2*>(g_Al + idx);
    ph[0] = __halves2half2(h0, h1); ph[1] = __halves2half2(h2, h3);
    pl[0] = __halves2half2(l0, l1); pl[1] = __halves2half2(l2, l3);
}

// ---------------------------------------------------------------------------
// Tensor-pipe GEMM, asymmetric fp16 split: C = (Ah+Al)·W^T + bias.
// Tile 128x64x32, 8 warps (4x2), 4-stage cp.async (80KB), 2 CTAs/SM.
// 2 mmas per (mt,nb,k16). MODE 0 -> scatter Q/K/V bf16 hi/lo (q *0.125).
// MODE 1 -> out fp32 + bias.
// ---------------------------------------------------------------------------
template <int MODE>
__global__ __launch_bounds__(256, 2)
void gemm_mma(const float* __restrict__ bias, float* __restrict__ out,
              int N, int K)
{
    extern __shared__ __align__(16) char sm[];
    const __half* Agh = (MODE == 0) ? g_Ah : g_AOh;
    const __half* Agl = (MODE == 0) ? g_Al : g_AOl;
    const __half* Bg  = (MODE == 0) ? g_Win_h : g_Wout_h;

    const int tid  = threadIdx.x;
    const int lane = tid & 31;
    const int wid  = tid >> 5;
    const int wm   = wid >> 1;
    const int wn   = wid & 1;
    const int m0 = blockIdx.y * BM;
    const int n0 = blockIdx.x * BN;

    const uint32_t smb = smem_u32(sm);

    float acc[2][4][4];
#pragma unroll
    for (int a = 0; a < 2; ++a)
#pragma unroll
        for (int b = 0; b < 4; ++b)
#pragma unroll
            for (int c = 0; c < 4; ++c) acc[a][b][c] = 0.f;

    const int nchunk = K / BK;

#define ISSUE_STAGE(CIDX)                                                     \
    {                                                                         \
        uint32_t base_ = smb + (uint32_t)((CIDX) & 3) * STAGE_B;              \
        _Pragma("unroll")                                                     \
        for (int p = 0; p < 2; ++p) {                                         \
            int idx = tid + p * 256;                                          \
            int row = idx >> 2, c8 = idx & 3;                                 \
            uint32_t sw = (uint32_t)(row * 64 + ((c8 ^ ((row >> 1) & 3)) << 4)); \
            size_t go = (size_t)(m0 + row) * K + (CIDX) * 32 + c8 * 8;        \
            CPASYNC16(base_ + sw, Agh + go);                                  \
            CPASYNC16(base_ + 8192 + sw, Agl + go);                           \
        }                                                                     \
        {                                                                     \
            int row = tid >> 2, c8 = tid & 3;                                 \
            uint32_t sw = (uint32_t)(row * 64 + ((c8 ^ ((row >> 1) & 3)) << 4)); \
            size_t go = (size_t)(n0 + row) * K + (CIDX) * 32 + c8 * 8;        \
            CPASYNC16(base_ + 16384 + sw, Bg + go);                           \
        }                                                                     \
        asm volatile("cp.async.commit_group;" ::: "memory");                  \
    }

    ISSUE_STAGE(0);
    ISSUE_STAGE(1);
    ISSUE_STAGE(2);

    for (int c = 0; c < nchunk; ++c) {
        asm volatile("cp.async.wait_group 2;" ::: "memory");
        __syncthreads();

        if (c + 3 < nchunk) ISSUE_STAGE(c + 3);

        {
            uint32_t stb = smb + (uint32_t)(c & 3) * STAGE_B;
            const int g = lane >> 3, i = lane & 7;
#pragma unroll
            for (int ks = 0; ks < 2; ++ks) {
                uint32_t ah[2][4], al[2][4];
                const int arow_off = i + ((g & 1) << 3);
                const int akc = ks * 2 + (g >> 1);
#pragma unroll
                for (int mt = 0; mt < 2; ++mt) {
                    int row = wm * 32 + mt * 16 + arow_off;
                    uint32_t off = (uint32_t)(row * 64 + ((akc ^ ((row >> 1) & 3)) << 4));
                    LDSM4(ah[mt], stb + off);
                    LDSM4(al[mt], stb + 8192 + off);
                }
                uint32_t bh[4][2];
                const int brow_off = i + ((g >> 1) << 3);
                const int bkc = ks * 2 + (g & 1);
#pragma unroll
                for (int np = 0; np < 2; ++np) {
                    int row = wn * 32 + np * 16 + brow_off;
                    uint32_t off = (uint32_t)(row * 64 + ((bkc ^ ((row >> 1) & 3)) << 4));
                    uint32_t r4[4];
                    LDSM4(r4, stb + 16384 + off);
                    bh[np * 2][0] = r4[0]; bh[np * 2][1] = r4[1];
                    bh[np * 2 + 1][0] = r4[2]; bh[np * 2 + 1][1] = r4[3];
                }
#pragma unroll
                for (int mt = 0; mt < 2; ++mt)
#pragma unroll
                    for (int nb = 0; nb < 4; ++nb) {
                        MMAF16(acc[mt][nb], ah[mt], bh[nb]);
                        MMAF16(acc[mt][nb], al[mt], bh[nb]);
                    }
            }
        }
    }
#undef ISSUE_STAGE

    __syncthreads();

    const int r = lane >> 2, tg = lane & 3;
#pragma unroll
    for (int mt = 0; mt < 2; ++mt) {
#pragma unroll
        for (int nb = 0; nb < 4; ++nb) {
            int m = m0 + wm * 32 + mt * 16 + r;
            int n = n0 + wn * 32 + nb * 8 + tg * 2;
            float2 bb = *reinterpret_cast<const float2*>(bias + n);
#pragma unroll
            for (int half = 0; half < 2; ++half) {
                int mm = m + half * 8;
                float v0 = acc[mt][nb][half * 2 + 0] + bb.x;
                float v1 = acc[mt][nb][half * 2 + 1] + bb.y;
                if (MODE == 1) {
                    float2 vv = {v0, v1};
                    *reinterpret_cast<float2*>(out + (size_t)mm * N + n) = vv;
                } else {
                    int t = mm >> 3;
                    int b = mm & 7;
                    int which = n >> 10;
                    int h = (n >> 6) & 15;
                    int d = n & 63;
                    float sc = (which == 0) ? 0.125f : 1.0f;
                    float x = v0 * sc, y = v1 * sc;
                    __nv_bfloat16* bph = (which == 0) ? g_Qh : (which == 1) ? g_Kh : g_Vh;
                    __nv_bfloat16* bpl = (which == 0) ? g_Ql : (which == 1) ? g_Kl : g_Vl;
                    size_t off = ((size_t)(b * Hh + h) * Tt + t) * HD + d;
                    float2 vv = {x, y};
                    __nv_bfloat162 hh = __float22bfloat162_rn(vv);
                    *reinterpret_cast<__nv_bfloat162*>(bph + off) = hh;
                    float2 lo = {x - __bfloat162float(hh.x), y - __bfloat162float(hh.y)};
                    *reinterpret_cast<__nv_bfloat162*>(bpl + off) = __float22bfloat162_rn(lo);
                }
            }
        }
    }
}

// ---------------------------------------------------------------------------
// Flash attention on tensor pipe (R7 structure), 2 CTAs/SM, Q reloaded from
// smem per k-step. Epilogue writes fp16 hi/lo AO for the out-projection.
// ---------------------------------------------------------------------------
__global__ __launch_bounds__(256, 2)
void attn_mma(const float* __restrict__ rpb)
{
    extern __shared__ __align__(16) char sm[];
    const int tid = threadIdx.x;
    const int lane = tid & 31;
    const int w = tid >> 5;
    const int b = blockIdx.x;
    const int h = blockIdx.y >> 3;
    const int t0 = (blockIdx.y & 7) * 128;
    const int bh = b * Hh + h;

    const uint32_t uQ = smem_u32(sm);
    const uint32_t uS0 = uQ + 32768;

    {
#pragma unroll
        for (int p = 0; p < 8; ++p) {
            int i = tid + p * 256;
            int half_ = i >> 10, rem = i & 1023;
            int row = rem >> 3, cc = rem & 7;
            const __nv_bfloat16* src = (half_ ? g_Ql : g_Qh)
                + ((size_t)bh * Tt + t0 + row) * HD + cc * 8;
            uint32_t dst = uQ + half_ * 16384 + row * 128 + (((cc ^ (row & 7))) << 4);
            CPASYNC16(dst, src);
        }
    }
    const __nv_bfloat16* kvsrc[4] = { g_Kh, g_Kl, g_Vh, g_Vl };
#define LOAD_CHUNK(CIDX, ST)                                                   \
    {                                                                          \
        const uint32_t base_ = uS0 + (uint32_t)(ST) * 32768;                   \
        int s0_ = (CIDX) * 64;                                                 \
        _Pragma("unroll")                                                      \
        for (int p = 0; p < 8; ++p) {                                          \
            int i = tid + p * 256;                                             \
            int tile = i >> 9;                                                 \
            int rem = i & 511;                                                 \
            int row = rem >> 3, cc = rem & 7;                                  \
            const __nv_bfloat16* src = kvsrc[tile]                             \
                + ((size_t)bh * Tt + s0_ + row) * HD + cc * 8;                 \
            uint32_t dst = base_ + tile * 8192 + row * 128                     \
                         + (((cc ^ (row & 7))) << 4);                          \
            CPASYNC16(dst, src);                                               \
        }                                                                      \
    }

    LOAD_CHUNK(0, 0);
    asm volatile("cp.async.commit_group;" ::: "memory");
    LOAD_CHUNK(1, 1);
    asm volatile("cp.async.commit_group;" ::: "memory");

    float o[8][4];
#pragma unroll
    for (int j = 0; j < 8; ++j)
#pragma unroll
        for (int v = 0; v < 4; ++v) o[j][v] = 0.f;
    float m0r = -1e30f, m1r = -1e30f, l0r = 0.f, l1r = 0.f;

    const int rq = lane >> 2;
    const int cq = (lane & 3) * 2;
    const size_t brow0_base = ((size_t)h * Tt + (t0 + w * 16 + rq)) * Tt;
    const size_t brow1_base = brow0_base + 8 * (size_t)Tt;

    const int qrow = w * 16 + (lane & 15);
    const uint32_t qrb = uQ + qrow * 128;
    const uint32_t qsel = (uint32_t)(lane >> 4);

    for (int c = 0; c < 16; ++c) {
        if (c == 15) asm volatile("cp.async.wait_group 0;" ::: "memory");
        else         asm volatile("cp.async.wait_group 1;" ::: "memory");
        __syncthreads();

        const uint32_t stb = uS0 + (uint32_t)(c & 1) * 32768;
        const int g = lane >> 3, i = lane & 7;

        float s[8][4];
#pragma unroll
        for (int j = 0; j < 8; ++j)
#pragma unroll
            for (int v = 0; v < 4; ++v) s[j][v] = 0.f;

#pragma unroll
        for (int kk = 0; kk < 4; ++kk) {
            uint32_t qh[4], ql[4];
            {
                uint32_t ccol = 2u * kk + qsel;
                uint32_t off = ((ccol ^ (qrow & 7)) << 4);
                LDSM4(qh, qrb + off);
                LDSM4(ql, qrb + 16384 + off);
            }
            uint32_t kbh[8][2], kbl[8][2];
            const int brow_off = i + ((g >> 1) << 3);
            const int bkc = kk * 2 + (g & 1);
#pragma unroll
            for (int ng = 0; ng < 4; ++ng) {
                int row = ng * 16 + brow_off;
                uint32_t off = (uint32_t)(row * 128 + ((bkc ^ (row & 7)) << 4));
                uint32_t r4[4];
                LDSM4(r4, stb + off);
                kbh[ng * 2][0] = r4[0]; kbh[ng * 2][1] = r4[1];
                kbh[ng * 2 + 1][0] = r4[2]; kbh[ng * 2 + 1][1] = r4[3];
                LDSM4(r4, stb + 8192 + off);
                kbl[ng * 2][0] = r4[0]; kbl[ng * 2][1] = r4[1];
                kbl[ng * 2 + 1][0] = r4[2]; kbl[ng * 2 + 1][1] = r4[3];
            }
#pragma unroll
            for (int nt = 0; nt < 8; ++nt) {
                MMA16816(s[nt], qh, kbh[nt]);
                MMA16816(s[nt], qh, kbl[nt]);
                MMA16816(s[nt], ql, kbh[nt]);
            }
        }

        {
            const float* bp0 = rpb + brow0_base + c * 64 + cq;
            const float* bp1 = rpb + brow1_base + c * 64 + cq;
#pragma unroll
            for (int j = 0; j < 8; ++j) {
                float2 b0 = *reinterpret_cast<const float2*>(bp0 + j * 8);
                float2 b1 = *reinterpret_cast<const float2*>(bp1 + j * 8);
                s[j][0] += b0.x; s[j][1] += b0.y;
                s[j][2] += b1.x; s[j][3] += b1.y;
            }
        }

        float cm0 = -1e30f, cm1 = -1e30f;
#pragma unroll
        for (int j = 0; j < 8; ++j) {
            cm0 = fmaxf(cm0, fmaxf(s[j][0], s[j][1]));
            cm1 = fmaxf(cm1, fmaxf(s[j][2], s[j][3]));
        }
        cm0 = fmaxf(cm0, __shfl_xor_sync(0xffffffffu, cm0, 1));
        cm0 = fmaxf(cm0, __shfl_xor_sync(0xffffffffu, cm0, 2));
        cm1 = fmaxf(cm1, __shfl_xor_sync(0xffffffffu, cm1, 1));
        cm1 = fmaxf(cm1, __shfl_xor_sync(0xffffffffu, cm1, 2));
        float m0n = fmaxf(m0r, cm0), m1n = fmaxf(m1r, cm1);
        float cor0 = __expf(m0r - m0n), cor1 = __expf(m1r - m1n);
        m0r = m0n; m1r = m1n;
        float rs0 = 0.f, rs1 = 0.f;
#pragma unroll
        for (int j = 0; j < 8; ++j) {
            s[j][0] = __expf(s[j][0] - m0n);
            s[j][1] = __expf(s[j][1] - m0n);
            s[j][2] = __expf(s[j][2] - m1n);
            s[j][3] = __expf(s[j][3] - m1n);
            rs0 += s[j][0] + s[j][1];
            rs1 += s[j][2] + s[j][3];
        }
        rs0 += __shfl_xor_sync(0xffffffffu, rs0, 1);
        rs0 += __shfl_xor_sync(0xffffffffu, rs0, 2);
        rs1 += __shfl_xor_sync(0xffffffffu, rs1, 1);
        rs1 += __shfl_xor_sync(0xffffffffu, rs1, 2);
        l0r = l0r * cor0 + rs0;
        l1r = l1r * cor1 + rs1;
#pragma unroll
        for (int j = 0; j < 8; ++j) {
            o[j][0] *= cor0; o[j][1] *= cor0;
            o[j][2] *= cor1; o[j][3] *= cor1;
        }

        uint32_t ph[8][2], pl[8][2];
#pragma unroll
        for (int j = 0; j < 8; ++j) {
            float2 v0 = {s[j][0], s[j][1]};
            __nv_bfloat162 hh0 = __float22bfloat162_rn(v0);
            ph[j][0] = *reinterpret_cast<uint32_t*>(&hh0);
            float2 lo0 = {s[j][0] - __bfloat162float(hh0.x),
                          s[j][1] - __bfloat162float(hh0.y)};
            __nv_bfloat162 ll0 = __float22bfloat162_rn(lo0);
            pl[j][0] = *reinterpret_cast<uint32_t*>(&ll0);
            float2 v1 = {s[j][2], s[j][3]};
            __nv_bfloat162 hh1 = __float22bfloat162_rn(v1);
            ph[j][1] = *reinterpret_cast<uint32_t*>(&hh1);
            float2 lo1 = {s[j][2] - __bfloat162float(hh1.x),
                          s[j][3] - __bfloat162float(hh1.y)};
            __nv_bfloat162 ll1 = __float22bfloat162_rn(lo1);
            pl[j][1] = *reinterpret_cast<uint32_t*>(&ll1);
        }

#pragma unroll
        for (int kk = 0; kk < 4; ++kk) {
            uint32_t a_h[4] = { ph[2*kk][0], ph[2*kk][1], ph[2*kk+1][0], ph[2*kk+1][1] };
            uint32_t a_l[4] = { pl[2*kk][0], pl[2*kk][1], pl[2*kk+1][0], pl[2*kk+1][1] };
            uint32_t vbh[8][2], vbl[8][2];
            const int srow = kk * 16 + i + ((g >> 1) << 3);
#pragma unroll
            for (int dg = 0; dg < 4; ++dg) {
                int ck = dg * 2 + (g & 1);
                uint32_t off = (uint32_t)(srow * 128 + ((ck ^ (srow & 7)) << 4));
                uint32_t r4[4];
                LDSM4T(r4, stb + 16384 + off);
                vbh[dg * 2][0] = r4[0]; vbh[dg * 2][1] = r4[2];
                vbh[dg * 2 + 1][0] = r4[1]; vbh[dg * 2 + 1][1] = r4[3];
                LDSM4T(r4, stb + 24576 + off);
                vbl[dg * 2][0] = r4[0]; vbl[dg * 2][1] = r4[2];
                vbl[dg * 2 + 1][0] = r4[1]; vbl[dg * 2 + 1][1] = r4[3];
            }
#pragma unroll
            for (int dt = 0; dt < 8; ++dt) {
                MMA16816(o[dt], a_h, vbh[dt]);
                MMA16816(o[dt], a_h, vbl[dt]);
                MMA16816(o[dt], a_l, vbh[dt]);
            }
        }

        __syncthreads();
        if (c + 2 < 16) {
            LOAD_CHUNK(c + 2, c & 1);
            asm volatile("cp.async.commit_group;" ::: "memory");
        }
    }

    float inv0 = 1.f / l0r, inv1 = 1.f / l1r;
    int t_row0 = t0 + w * 16 + rq;
    int t_row1 = t_row0 + 8;
#pragma unroll
    for (int j = 0; j < 8; ++j) {
        int d = j * 8 + cq;
        size_t i0 = ((size_t)t_row0 * Bb + b) * Ee + h * HD + d;
        size_t i1 = ((size_t)t_row1 * Bb + b) * Ee + h * HD + d;
        float x0 = o[j][0] * inv0, y0 = o[j][1] * inv0;
        float x1 = o[j][2] * inv1, y1 = o[j][3] * inv1;
        float2 v0 = {x0, y0};
        __half2 hh0 = __float22half2_rn(v0);
        *reinterpret_cast<__half2*>(g_AOh + i0) = hh0;
        float2 lo0 = {x0 - __half2float(__low2half(hh0)),
                      y0 - __half2float(__high2half(hh0))};
        *reinterpret_cast<__half2*>(g_AOl + i0) = __float22half2_rn(lo0);
        float2 v1 = {x1, y1};
        __half2 hh1 = __float22half2_rn(v1);
        *reinterpret_cast<__half2*>(g_AOh + i1) = hh1;
        float2 lo1 = {x1 - __half2float(__low2half(hh1)),
                      y1 - __half2float(__high2half(hh1))};
        *reinterpret_cast<__half2*>(g_AOl + i1) = __float22half2_rn(lo1);
    }
#undef LOAD_CHUNK
}

// ---------------------------------------------------------------------------
extern "C" void kernel_launch(void* const* d_in, const int* in_sizes, int n_in,
                              void* d_out, int out_size)
{
    const float* query = (const float*)d_in[0];
    const float* ipw   = (const float*)d_in[1];
    const float* ipb   = (const float*)d_in[2];
    const float* il    = (const float*)d_in[3];
    const float* ir    = (const float*)d_in[4];
    const float* opw   = (const float*)d_in[5];
    const float* opb   = (const float*)d_in[6];
    const float* ol    = (const float*)d_in[7];
    const float* orr   = (const float*)d_in[8];
    const float* rpb   = (const float*)d_in[9];
    float* out = (float*)d_out;

    static bool attr_set = false;
    if (!attr_set) {
        cudaFuncSetAttribute(gemm_mma<0>,
            cudaFuncAttributeMaxDynamicSharedMemorySize, 81920);
        cudaFuncSetAttribute(gemm_mma<1>,
            cudaFuncAttributeMaxDynamicSharedMemorySize, 81920);
        cudaFuncSetAttribute(attn_mma,
            cudaFuncAttributeMaxDynamicSharedMemorySize, 98304);
        attr_set = true;
    }

    weff_kernel<0><<<(F3 * Ee + 255) / 256, 256>>>(ipw, il, ir);
    weff_kernel<1><<<(Ee * Ee + 255) / 256, 256>>>(opw, ol, orr);
    qsplit_kernel<<<Nrows * Ee / 1024, 256>>>(query);

    gemm_mma<0><<<dim3(F3 / BN, Nrows / BM), 256, 81920>>>(ipb, nullptr, F3, Ee);

    attn_mma<<<dim3(Bb, Hh * 8), 256, 98304>>>(rpb);

    gemm_mma<1><<<dim3(Ee / BN, Nrows / BM), 256, 81920>>>(opb, out, Ee, Ee);
}

// round 12
// speedup vs baseline: 2.6519x; 1.1098x over previous
#include <cuda_runtime.h>
#include <cuda_bf16.h>
#include <cuda_fp16.h>
#include <cstdint>

// ---------------------------------------------------------------------------
// MultiheadAttention with low-rank-augmented in/out projections.
// T=1024, B=8, E=1024, H=16, R=16, HD=64.
//
// R12: asymmetric fp16 split extended to attention — Q and P in fp16 hi/lo,
//      K and V single fp16 (2 mmas per k16 everywhere). Projection GEMMs
//      unchanged from R11 (A hi/lo fp16 x W single fp16).
// ---------------------------------------------------------------------------

namespace {
constexpr int Tt = 1024;
constexpr int Bb = 8;
constexpr int Ee = 1024;
constexpr int Hh = 16;
constexpr int Rr = 16;
constexpr int HD = 64;
constexpr int F3 = 3 * Ee;          // 3072
constexpr int Nrows = Tt * Bb;      // 8192
constexpr int BM = 128, BN = 64, BK = 32;
constexpr int STAGE_B = 20480;      // Ah 8K, Al 8K, W 4K
}

// Scratch (device globals; no runtime allocation).
__device__ __align__(16) __half g_Win_h[F3 * Ee];
__device__ __align__(16) __half g_Wout_h[Ee * Ee];
__device__ __align__(16) __half g_Ah[Nrows * Ee];
__device__ __align__(16) __half g_Al[Nrows * Ee];
__device__ __align__(16) __half g_AOh[Nrows * Ee];
__device__ __align__(16) __half g_AOl[Nrows * Ee];
__device__ __align__(16) __half g_Qh[Bb * Hh * Tt * HD];
__device__ __align__(16) __half g_Ql[Bb * Hh * Tt * HD];
__device__ __align__(16) __half g_K[Bb * Hh * Tt * HD];
__device__ __align__(16) __half g_V[Bb * Hh * Tt * HD];

// ---------------------------------------------------------------------------
__device__ __forceinline__ uint32_t smem_u32(const void* p) {
    uint32_t a;
    asm("{ .reg .u64 t; cvta.to.shared.u64 t, %1; cvt.u32.u64 %0, t; }"
        : "=r"(a) : "l"(p));
    return a;
}

__device__ __forceinline__ void split_h(float x, __half& h, __half& l) {
    h = __float2half(x);
    l = __float2half(x - __half2float(h));
}

#define LDSM4(R, A)                                                           \
    asm volatile("ldmatrix.sync.aligned.m8n8.x4.shared.b16 {%0,%1,%2,%3}, [%4];" \
                 : "=r"((R)[0]), "=r"((R)[1]), "=r"((R)[2]), "=r"((R)[3])     \
                 : "r"(A))

#define LDSM4T(R, A)                                                          \
    asm volatile("ldmatrix.sync.aligned.m8n8.x4.trans.shared.b16 {%0,%1,%2,%3}, [%4];" \
                 : "=r"((R)[0]), "=r"((R)[1]), "=r"((R)[2]), "=r"((R)[3])     \
                 : "r"(A))

#define MMAF16(C, A, B)                                                       \
    asm volatile("mma.sync.aligned.m16n8k16.row.col.f32.f16.f16.f32 "         \
                 "{%0,%1,%2,%3}, {%4,%5,%6,%7}, {%8,%9}, {%0,%1,%2,%3};"      \
                 : "+f"((C)[0]), "+f"((C)[1]), "+f"((C)[2]), "+f"((C)[3])     \
                 : "r"((A)[0]), "r"((A)[1]), "r"((A)[2]), "r"((A)[3]),        \
                   "r"((B)[0]), "r"((B)[1]))

#define CPASYNC16(D, S)                                                       \
    asm volatile("cp.async.cg.shared.global [%0], [%1], 16;"                  \
                 :: "r"(D), "l"(S))

// ---------------------------------------------------------------------------
// W_eff = W + L@R, written as single fp16.
// ---------------------------------------------------------------------------
template <int WHICH>
__global__ void weff_kernel(const float* __restrict__ W,
                            const float* __restrict__ L,
                            const float* __restrict__ Rm)
{
    const int F = (WHICH == 0) ? F3 : Ee;
    __half* oh = (WHICH == 0) ? g_Win_h : g_Wout_h;
    int idx = blockIdx.x * 256 + threadIdx.x;
    if (idx >= F * Ee) return;
    int f = idx >> 10;
    int e = idx & 1023;
    float s = W[idx];
#pragma unroll
    for (int r = 0; r < Rr; ++r)
        s = fmaf(L[f * Rr + r], Rm[r * Ee + e], s);
    oh[idx] = __float2half(s);
}

// ---------------------------------------------------------------------------
// Split query (fp32) into fp16 hi/lo.
// ---------------------------------------------------------------------------
__global__ void qsplit_kernel(const float* __restrict__ q)
{
    int idx = (blockIdx.x * 256 + threadIdx.x) * 4;
    float4 v = *reinterpret_cast<const float4*>(q + idx);
    __half h0, h1, h2, h3, l0, l1, l2, l3;
    split_h(v.x, h0, l0); split_h(v.y, h1, l1);
    split_h(v.z, h2, l2); split_h(v.w, h3, l3);
    __half2* ph = reinterpret_cast<__half2*>(g_Ah + idx);
    __half2* pl = reinterpret_cast<__half2*>(g_Al + idx);
    ph[0] = __halves2half2(h0, h1); ph[1] = __halves2half2(h2, h3);
    pl[0] = __halves2half2(l0, l1); pl[1] = __halves2half2(l2, l3);
}

// ---------------------------------------------------------------------------
// Tensor-pipe GEMM, asymmetric fp16 split: C = (Ah+Al)·W^T + bias.
// Tile 128x64x32, 8 warps (4x2), 4-stage cp.async (80KB), 2 CTAs/SM.
// MODE 0 -> Q fp16 hi/lo (q *0.125), K/V single fp16. MODE 1 -> out fp32.
// ---------------------------------------------------------------------------
template <int MODE>
__global__ __launch_bounds__(256, 2)
void gemm_mma(const float* __restrict__ bias, float* __restrict__ out,
              int N, int K)
{
    extern __shared__ __align__(16) char sm[];
    const __half* Agh = (MODE == 0) ? g_Ah : g_AOh;
    const __half* Agl = (MODE == 0) ? g_Al : g_AOl;
    const __half* Bg  = (MODE == 0) ? g_Win_h : g_Wout_h;

    const int tid  = threadIdx.x;
    const int lane = tid & 31;
    const int wid  = tid >> 5;
    const int wm   = wid >> 1;
    const int wn   = wid & 1;
    const int m0 = blockIdx.y * BM;
    const int n0 = blockIdx.x * BN;

    const uint32_t smb = smem_u32(sm);

    float acc[2][4][4];
#pragma unroll
    for (int a = 0; a < 2; ++a)
#pragma unroll
        for (int b = 0; b < 4; ++b)
#pragma unroll
            for (int c = 0; c < 4; ++c) acc[a][b][c] = 0.f;

    const int nchunk = K / BK;

#define ISSUE_STAGE(CIDX)                                                     \
    {                                                                         \
        uint32_t base_ = smb + (uint32_t)((CIDX) & 3) * STAGE_B;              \
        _Pragma("unroll")                                                     \
        for (int p = 0; p < 2; ++p) {                                         \
            int idx = tid + p * 256;                                          \
            int row = idx >> 2, c8 = idx & 3;                                 \
            uint32_t sw = (uint32_t)(row * 64 + ((c8 ^ ((row >> 1) & 3)) << 4)); \
            size_t go = (size_t)(m0 + row) * K + (CIDX) * 32 + c8 * 8;        \
            CPASYNC16(base_ + sw, Agh + go);                                  \
            CPASYNC16(base_ + 8192 + sw, Agl + go);                           \
        }                                                                     \
        {                                                                     \
            int row = tid >> 2, c8 = tid & 3;                                 \
            uint32_t sw = (uint32_t)(row * 64 + ((c8 ^ ((row >> 1) & 3)) << 4)); \
            size_t go = (size_t)(n0 + row) * K + (CIDX) * 32 + c8 * 8;        \
            CPASYNC16(base_ + 16384 + sw, Bg + go);                           \
        }                                                                     \
        asm volatile("cp.async.commit_group;" ::: "memory");                  \
    }

    ISSUE_STAGE(0);
    ISSUE_STAGE(1);
    ISSUE_STAGE(2);

    for (int c = 0; c < nchunk; ++c) {
        asm volatile("cp.async.wait_group 2;" ::: "memory");
        __syncthreads();

        if (c + 3 < nchunk) ISSUE_STAGE(c + 3);

        {
            uint32_t stb = smb + (uint32_t)(c & 3) * STAGE_B;
            const int g = lane >> 3, i = lane & 7;
#pragma unroll
            for (int ks = 0; ks < 2; ++ks) {
                uint32_t ah[2][4], al[2][4];
                const int arow_off = i + ((g & 1) << 3);
                const int akc = ks * 2 + (g >> 1);
#pragma unroll
                for (int mt = 0; mt < 2; ++mt) {
                    int row = wm * 32 + mt * 16 + arow_off;
                    uint32_t off = (uint32_t)(row * 64 + ((akc ^ ((row >> 1) & 3)) << 4));
                    LDSM4(ah[mt], stb + off);
                    LDSM4(al[mt], stb + 8192 + off);
                }
                uint32_t bh[4][2];
                const int brow_off = i + ((g >> 1) << 3);
                const int bkc = ks * 2 + (g & 1);
#pragma unroll
                for (int np = 0; np < 2; ++np) {
                    int row = wn * 32 + np * 16 + brow_off;
                    uint32_t off = (uint32_t)(row * 64 + ((bkc ^ ((row >> 1) & 3)) << 4));
                    uint32_t r4[4];
                    LDSM4(r4, stb + 16384 + off);
                    bh[np * 2][0] = r4[0]; bh[np * 2][1] = r4[1];
                    bh[np * 2 + 1][0] = r4[2]; bh[np * 2 + 1][1] = r4[3];
                }
#pragma unroll
                for (int mt = 0; mt < 2; ++mt)
#pragma unroll
                    for (int nb = 0; nb < 4; ++nb) {
                        MMAF16(acc[mt][nb], ah[mt], bh[nb]);
                        MMAF16(acc[mt][nb], al[mt], bh[nb]);
                    }
            }
        }
    }
#undef ISSUE_STAGE

    __syncthreads();

    const int r = lane >> 2, tg = lane & 3;
#pragma unroll
    for (int mt = 0; mt < 2; ++mt) {
#pragma unroll
        for (int nb = 0; nb < 4; ++nb) {
            int m = m0 + wm * 32 + mt * 16 + r;
            int n = n0 + wn * 32 + nb * 8 + tg * 2;
            float2 bb = *reinterpret_cast<const float2*>(bias + n);
#pragma unroll
            for (int half = 0; half < 2; ++half) {
                int mm = m + half * 8;
                float v0 = acc[mt][nb][half * 2 + 0] + bb.x;
                float v1 = acc[mt][nb][half * 2 + 1] + bb.y;
                if (MODE == 1) {
                    float2 vv = {v0, v1};
                    *reinterpret_cast<float2*>(out + (size_t)mm * N + n) = vv;
                } else {
                    int t = mm >> 3;
                    int b = mm & 7;
                    int which = n >> 10;
                    int h = (n >> 6) & 15;
                    int d = n & 63;
                    size_t off = ((size_t)(b * Hh + h) * Tt + t) * HD + d;
                    if (which == 0) {
                        float x = v0 * 0.125f, y = v1 * 0.125f;
                        float2 vv = {x, y};
                        __half2 hh = __float22half2_rn(vv);
                        *reinterpret_cast<__half2*>(g_Qh + off) = hh;
                        float2 lo = {x - __half2float(__low2half(hh)),
                                     y - __half2float(__high2half(hh))};
                        *reinterpret_cast<__half2*>(g_Ql + off) = __float22half2_rn(lo);
                    } else {
                        __half* dst = (which == 1) ? g_K : g_V;
                        float2 vv = {v0, v1};
                        *reinterpret_cast<__half2*>(dst + off) = __float22half2_rn(vv);
                    }
                }
            }
        }
    }
}

// ---------------------------------------------------------------------------
// Flash attention on tensor pipe. Q/P fp16 hi/lo, K/V single fp16
// (2 mmas per k16). smem: Q 32KB; 2 KV stages of 16KB (K 8K, V 8K) = 64KB.
// 2 CTAs/SM; Q fragments re-loaded from smem per k-step.
// ---------------------------------------------------------------------------
__global__ __launch_bounds__(256, 2)
void attn_mma(const float* __restrict__ rpb)
{
    extern __shared__ __align__(16) char sm[];
    const int tid = threadIdx.x;
    const int lane = tid & 31;
    const int w = tid >> 5;
    const int b = blockIdx.x;
    const int h = blockIdx.y >> 3;
    const int t0 = (blockIdx.y & 7) * 128;
    const int bh = b * Hh + h;

    const uint32_t uQ = smem_u32(sm);
    const uint32_t uS0 = uQ + 32768;

    {
#pragma unroll
        for (int p = 0; p < 8; ++p) {
            int i = tid + p * 256;
            int half_ = i >> 10, rem = i & 1023;
            int row = rem >> 3, cc = rem & 7;
            const __half* src = (half_ ? g_Ql : g_Qh)
                + ((size_t)bh * Tt + t0 + row) * HD + cc * 8;
            uint32_t dst = uQ + half_ * 16384 + row * 128 + (((cc ^ (row & 7))) << 4);
            CPASYNC16(dst, src);
        }
    }
    const __half* kvsrc[2] = { g_K, g_V };
#define LOAD_CHUNK(CIDX, ST)                                                   \
    {                                                                          \
        const uint32_t base_ = uS0 + (uint32_t)(ST) * 16384;                   \
        int s0_ = (CIDX) * 64;                                                 \
        _Pragma("unroll")                                                      \
        for (int p = 0; p < 4; ++p) {                                          \
            int i = tid + p * 256;                                             \
            int tile = i >> 9;                                                 \
            int rem = i & 511;                                                 \
            int row = rem >> 3, cc = rem & 7;                                  \
            const __half* src = kvsrc[tile]                                    \
                + ((size_t)bh * Tt + s0_ + row) * HD + cc * 8;                 \
            uint32_t dst = base_ + tile * 8192 + row * 128                     \
                         + (((cc ^ (row & 7))) << 4);                          \
            CPASYNC16(dst, src);                                               \
        }                                                                      \
    }

    LOAD_CHUNK(0, 0);
    asm volatile("cp.async.commit_group;" ::: "memory");
    LOAD_CHUNK(1, 1);
    asm volatile("cp.async.commit_group;" ::: "memory");

    float o[8][4];
#pragma unroll
    for (int j = 0; j < 8; ++j)
#pragma unroll
        for (int v = 0; v < 4; ++v) o[j][v] = 0.f;
    float m0r = -1e30f, m1r = -1e30f, l0r = 0.f, l1r = 0.f;

    const int rq = lane >> 2;
    const int cq = (lane & 3) * 2;
    const size_t brow0_base = ((size_t)h * Tt + (t0 + w * 16 + rq)) * Tt;
    const size_t brow1_base = brow0_base + 8 * (size_t)Tt;

    const int qrow = w * 16 + (lane & 15);
    const uint32_t qrb = uQ + qrow * 128;
    const uint32_t qsel = (uint32_t)(lane >> 4);

    for (int c = 0; c < 16; ++c) {
        if (c == 15) asm volatile("cp.async.wait_group 0;" ::: "memory");
        else         asm volatile("cp.async.wait_group 1;" ::: "memory");
        __syncthreads();

        const uint32_t stb = uS0 + (uint32_t)(c & 1) * 16384;
        const int g = lane >> 3, i = lane & 7;

        float s[8][4];
#pragma unroll
        for (int j = 0; j < 8; ++j)
#pragma unroll
            for (int v = 0; v < 4; ++v) s[j][v] = 0.f;

#pragma unroll
        for (int kk = 0; kk < 4; ++kk) {
            uint32_t qh[4], ql[4];
            {
                uint32_t ccol = 2u * kk + qsel;
                uint32_t off = ((ccol ^ (qrow & 7)) << 4);
                LDSM4(qh, qrb + off);
                LDSM4(ql, qrb + 16384 + off);
            }
            uint32_t kb[8][2];
            const int brow_off = i + ((g >> 1) << 3);
            const int bkc = kk * 2 + (g & 1);
#pragma unroll
            for (int ng = 0; ng < 4; ++ng) {
                int row = ng * 16 + brow_off;
                uint32_t off = (uint32_t)(row * 128 + ((bkc ^ (row & 7)) << 4));
                uint32_t r4[4];
                LDSM4(r4, stb + off);
                kb[ng * 2][0] = r4[0]; kb[ng * 2][1] = r4[1];
                kb[ng * 2 + 1][0] = r4[2]; kb[ng * 2 + 1][1] = r4[3];
            }
#pragma unroll
            for (int nt = 0; nt < 8; ++nt) {
                MMAF16(s[nt], qh, kb[nt]);
                MMAF16(s[nt], ql, kb[nt]);
            }
        }

        {
            const float* bp0 = rpb + brow0_base + c * 64 + cq;
            const float* bp1 = rpb + brow1_base + c * 64 + cq;
#pragma unroll
            for (int j = 0; j < 8; ++j) {
                float2 b0 = *reinterpret_cast<const float2*>(bp0 + j * 8);
                float2 b1 = *reinterpret_cast<const float2*>(bp1 + j * 8);
                s[j][0] += b0.x; s[j][1] += b0.y;
                s[j][2] += b1.x; s[j][3] += b1.y;
            }
        }

        float cm0 = -1e30f, cm1 = -1e30f;
#pragma unroll
        for (int j = 0; j < 8; ++j) {
            cm0 = fmaxf(cm0, fmaxf(s[j][0], s[j][1]));
            cm1 = fmaxf(cm1, fmaxf(s[j][2], s[j][3]));
        }
        cm0 = fmaxf(cm0, __shfl_xor_sync(0xffffffffu, cm0, 1));
        cm0 = fmaxf(cm0, __shfl_xor_sync(0xffffffffu, cm0, 2));
        cm1 = fmaxf(cm1, __shfl_xor_sync(0xffffffffu, cm1, 1));
        cm1 = fmaxf(cm1, __shfl_xor_sync(0xffffffffu, cm1, 2));
        float m0n = fmaxf(m0r, cm0), m1n = fmaxf(m1r, cm1);
        float cor0 = __expf(m0r - m0n), cor1 = __expf(m1r - m1n);
        m0r = m0n; m1r = m1n;
        float rs0 = 0.f, rs1 = 0.f;
#pragma unroll
        for (int j = 0; j < 8; ++j) {
            s[j][0] = __expf(s[j][0] - m0n);
            s[j][1] = __expf(s[j][1] - m0n);
            s[j][2] = __expf(s[j][2] - m1n);
            s[j][3] = __expf(s[j][3] - m1n);
            rs0 += s[j][0] + s[j][1];
            rs1 += s[j][2] + s[j][3];
        }
        rs0 += __shfl_xor_sync(0xffffffffu, rs0, 1);
        rs0 += __shfl_xor_sync(0xffffffffu, rs0, 2);
        rs1 += __shfl_xor_sync(0xffffffffu, rs1, 1);
        rs1 += __shfl_xor_sync(0xffffffffu, rs1, 2);
        l0r = l0r * cor0 + rs0;
        l1r = l1r * cor1 + rs1;
#pragma unroll
        for (int j = 0; j < 8; ++j) {
            o[j][0] *= cor0; o[j][1] *= cor0;
            o[j][2] *= cor1; o[j][3] *= cor1;
        }

        // P hi/lo (fp16) fragments
        uint32_t ph[8][2], pl[8][2];
#pragma unroll
        for (int j = 0; j < 8; ++j) {
            float2 v0 = {s[j][0], s[j][1]};
            __half2 hh0 = __float22half2_rn(v0);
            ph[j][0] = *reinterpret_cast<uint32_t*>(&hh0);
            float2 lo0 = {s[j][0] - __half2float(__low2half(hh0)),
                          s[j][1] - __half2float(__high2half(hh0))};
            __half2 ll0 = __float22half2_rn(lo0);
            pl[j][0] = *reinterpret_cast<uint32_t*>(&ll0);
            float2 v1 = {s[j][2], s[j][3]};
            __half2 hh1 = __float22half2_rn(v1);
            ph[j][1] = *reinterpret_cast<uint32_t*>(&hh1);
            float2 lo1 = {s[j][2] - __half2float(__low2half(hh1)),
                          s[j][3] - __half2float(__high2half(hh1))};
            __half2 ll1 = __float22half2_rn(lo1);
            pl[j][1] = *reinterpret_cast<uint32_t*>(&ll1);
        }

#pragma unroll
        for (int kk = 0; kk < 4; ++kk) {
            uint32_t a_h[4] = { ph[2*kk][0], ph[2*kk][1], ph[2*kk+1][0], ph[2*kk+1][1] };
            uint32_t a_l[4] = { pl[2*kk][0], pl[2*kk][1], pl[2*kk+1][0], pl[2*kk+1][1] };
            uint32_t vb[8][2];
            const int srow = kk * 16 + i + ((g >> 1) << 3);
#pragma unroll
            for (int dg = 0; dg < 4; ++dg) {
                int ck = dg * 2 + (g & 1);
                uint32_t off = (uint32_t)(srow * 128 + ((ck ^ (srow & 7)) << 4));
                uint32_t r4[4];
                LDSM4T(r4, stb + 8192 + off);
                vb[dg * 2][0] = r4[0]; vb[dg * 2][1] = r4[2];
                vb[dg * 2 + 1][0] = r4[1]; vb[dg * 2 + 1][1] = r4[3];
            }
#pragma unroll
            for (int dt = 0; dt < 8; ++dt) {
                MMAF16(o[dt], a_h, vb[dt]);
                MMAF16(o[dt], a_l, vb[dt]);
            }
        }

        __syncthreads();
        if (c + 2 < 16) {
            LOAD_CHUNK(c + 2, c & 1);
            asm volatile("cp.async.commit_group;" ::: "memory");
        }
    }

    float inv0 = 1.f / l0r, inv1 = 1.f / l1r;
    int t_row0 = t0 + w * 16 + rq;
    int t_row1 = t_row0 + 8;
#pragma unroll
    for (int j = 0; j < 8; ++j) {
        int d = j * 8 + cq;
        size_t i0 = ((size_t)t_row0 * Bb + b) * Ee + h * HD + d;
        size_t i1 = ((size_t)t_row1 * Bb + b) * Ee + h * HD + d;
        float x0 = o[j][0] * inv0, y0 = o[j][1] * inv0;
        float x1 = o[j][2] * inv1, y1 = o[j][3] * inv1;
        float2 v0 = {x0, y0};
        __half2 hh0 = __float22half2_rn(v0);
        *reinterpret_cast<__half2*>(g_AOh + i0) = hh0;
        float2 lo0 = {x0 - __half2float(__low2half(hh0)),
                      y0 - __half2float(__high2half(hh0))};
        *reinterpret_cast<__half2*>(g_AOl + i0) = __float22half2_rn(lo0);
        float2 v1 = {x1, y1};
        __half2 hh1 = __float22half2_rn(v1);
        *reinterpret_cast<__half2*>(g_AOh + i1) = hh1;
        float2 lo1 = {x1 - __half2float(__low2half(hh1)),
                      y1 - __half2float(__high2half(hh1))};
        *reinterpret_cast<__half2*>(g_AOl + i1) = __float22half2_rn(lo1);
    }
#undef LOAD_CHUNK
}

// ---------------------------------------------------------------------------
extern "C" void kernel_launch(void* const* d_in, const int* in_sizes, int n_in,
                              void* d_out, int out_size)
{
    const float* query = (const float*)d_in[0];
    const float* ipw   = (const float*)d_in[1];
    const float* ipb   = (const float*)d_in[2];
    const float* il    = (const float*)d_in[3];
    const float* ir    = (const float*)d_in[4];
    const float* opw   = (const float*)d_in[5];
    const float* opb   = (const float*)d_in[6];
    const float* ol    = (const float*)d_in[7];
    const float* orr   = (const float*)d_in[8];
    const float* rpb   = (const float*)d_in[9];
    float* out = (float*)d_out;

    static bool attr_set = false;
    if (!attr_set) {
        cudaFuncSetAttribute(gemm_mma<0>,
            cudaFuncAttributeMaxDynamicSharedMemorySize, 81920);
        cudaFuncSetAttribute(gemm_mma<1>,
            cudaFuncAttributeMaxDynamicSharedMemorySize, 81920);
        cudaFuncSetAttribute(attn_mma,
            cudaFuncAttributeMaxDynamicSharedMemorySize, 65536);
        attr_set = true;
    }

    weff_kernel<0><<<(F3 * Ee + 255) / 256, 256>>>(ipw, il, ir);
    weff_kernel<1><<<(Ee * Ee + 255) / 256, 256>>>(opw, ol, orr);
    qsplit_kernel<<<Nrows * Ee / 1024, 256>>>(query);

    gemm_mma<0><<<dim3(F3 / BN, Nrows / BM), 256, 81920>>>(ipb, nullptr, F3, Ee);

    attn_mma<<<dim3(Bb, Hh * 8), 256, 65536>>>(rpb);

    gemm_mma<1><<<dim3(Ee / BN, Nrows / BM), 256, 81920>>>(opb, out, Ee, Ee);
}

// round 13
// speedup vs baseline: 3.4549x; 1.3028x over previous
#include <cuda_runtime.h>
#include <cuda_fp16.h>
#include <cstdint>

// ---------------------------------------------------------------------------
// MultiheadAttention with low-rank-augmented in/out projections.
// T=1024, B=8, E=1024, H=16, R=16, HD=64.
//
// R13: precision budget re-targeted at the softmax. Q/K paths are fp16
//      single x single (logit abs error ~1.6e-4 -> negligible through
//      softmax): in-proj GEMM is 1 mma/k16, attention QK is 1 mma/k16.
//      P·V keeps P hi/lo and out-proj keeps A hi/lo (linear in output).
// ---------------------------------------------------------------------------

namespace {
constexpr int Tt = 1024;
constexpr int Bb = 8;
constexpr int Ee = 1024;
constexpr int Hh = 16;
constexpr int Rr = 16;
constexpr int HD = 64;
constexpr int F3 = 3 * Ee;          // 3072
constexpr int Nrows = Tt * Bb;      // 8192
constexpr int BM = 128, BN = 64, BK = 32;
constexpr int STAGE_B = 20480;      // Ah 8K, (Al 8K when split), W 4K
}

// Scratch (device globals; no runtime allocation).
__device__ __align__(16) __half g_Win_h[F3 * Ee];
__device__ __align__(16) __half g_Wout_h[Ee * Ee];
__device__ __align__(16) __half g_Ah[Nrows * Ee];
__device__ __align__(16) __half g_AOh[Nrows * Ee];
__device__ __align__(16) __half g_AOl[Nrows * Ee];
__device__ __align__(16) __half g_Q[Bb * Hh * Tt * HD];
__device__ __align__(16) __half g_K[Bb * Hh * Tt * HD];
__device__ __align__(16) __half g_V[Bb * Hh * Tt * HD];

// ---------------------------------------------------------------------------
__device__ __forceinline__ uint32_t smem_u32(const void* p) {
    uint32_t a;
    asm("{ .reg .u64 t; cvta.to.shared.u64 t, %1; cvt.u32.u64 %0, t; }"
        : "=r"(a) : "l"(p));
    return a;
}

#define LDSM4(R, A)                                                           \
    asm volatile("ldmatrix.sync.aligned.m8n8.x4.shared.b16 {%0,%1,%2,%3}, [%4];" \
                 : "=r"((R)[0]), "=r"((R)[1]), "=r"((R)[2]), "=r"((R)[3])     \
                 : "r"(A))

#define LDSM4T(R, A)                                                          \
    asm volatile("ldmatrix.sync.aligned.m8n8.x4.trans.shared.b16 {%0,%1,%2,%3}, [%4];" \
                 : "=r"((R)[0]), "=r"((R)[1]), "=r"((R)[2]), "=r"((R)[3])     \
                 : "r"(A))

#define MMAF16(C, A, B)                                                       \
    asm volatile("mma.sync.aligned.m16n8k16.row.col.f32.f16.f16.f32 "         \
                 "{%0,%1,%2,%3}, {%4,%5,%6,%7}, {%8,%9}, {%0,%1,%2,%3};"      \
                 : "+f"((C)[0]), "+f"((C)[1]), "+f"((C)[2]), "+f"((C)[3])     \
                 : "r"((A)[0]), "r"((A)[1]), "r"((A)[2]), "r"((A)[3]),        \
                   "r"((B)[0]), "r"((B)[1]))

#define CPASYNC16(D, S)                                                       \
    asm volatile("cp.async.cg.shared.global [%0], [%1], 16;"                  \
                 :: "r"(D), "l"(S))

// ---------------------------------------------------------------------------
// W_eff = W + L@R, written as single fp16.
// ---------------------------------------------------------------------------
template <int WHICH>
__global__ void weff_kernel(const float* __restrict__ W,
                            const float* __restrict__ L,
                            const float* __restrict__ Rm)
{
    const int F = (WHICH == 0) ? F3 : Ee;
    __half* oh = (WHICH == 0) ? g_Win_h : g_Wout_h;
    int idx = blockIdx.x * 256 + threadIdx.x;
    if (idx >= F * Ee) return;
    int f = idx >> 10;
    int e = idx & 1023;
    float s = W[idx];
#pragma unroll
    for (int r = 0; r < Rr; ++r)
        s = fmaf(L[f * Rr + r], Rm[r * Ee + e], s);
    oh[idx] = __float2half(s);
}

// ---------------------------------------------------------------------------
// Convert query (fp32) to single fp16.
// ---------------------------------------------------------------------------
__global__ void qsplit_kernel(const float* __restrict__ q)
{
    int idx = (blockIdx.x * 256 + threadIdx.x) * 4;
    float4 v = *reinterpret_cast<const float4*>(q + idx);
    __half2* ph = reinterpret_cast<__half2*>(g_Ah + idx);
    float2 v01 = {v.x, v.y}, v23 = {v.z, v.w};
    ph[0] = __float22half2_rn(v01);
    ph[1] = __float22half2_rn(v23);
}

// ---------------------------------------------------------------------------
// Tensor-pipe fp16 GEMM: C = A·W^T + bias.
// Tile 128x64x32, 8 warps (4x2), 4-stage cp.async, 2 CTAs/SM.
// SPLIT_A=1: A has hi/lo planes (2 mmas/k16); SPLIT_A=0: single A (1 mma).
// MODE 0 -> scatter Q/K/V single fp16 (q *0.125). MODE 1 -> out fp32 + bias.
// ---------------------------------------------------------------------------
template <int MODE, int SPLIT_A>
__global__ __launch_bounds__(256, 2)
void gemm_mma(const float* __restrict__ bias, float* __restrict__ out,
              int N, int K)
{
    extern __shared__ __align__(16) char sm[];
    const __half* Agh = (MODE == 0) ? g_Ah : g_AOh;
    const __half* Agl = (MODE == 0) ? g_Ah : g_AOl;   // unused when !SPLIT_A
    const __half* Bg  = (MODE == 0) ? g_Win_h : g_Wout_h;

    const int tid  = threadIdx.x;
    const int lane = tid & 31;
    const int wid  = tid >> 5;
    const int wm   = wid >> 1;
    const int wn   = wid & 1;
    const int m0 = blockIdx.y * BM;
    const int n0 = blockIdx.x * BN;

    const uint32_t smb = smem_u32(sm);

    float acc[2][4][4];
#pragma unroll
    for (int a = 0; a < 2; ++a)
#pragma unroll
        for (int b = 0; b < 4; ++b)
#pragma unroll
            for (int c = 0; c < 4; ++c) acc[a][b][c] = 0.f;

    const int nchunk = K / BK;

#define ISSUE_STAGE(CIDX)                                                     \
    {                                                                         \
        uint32_t base_ = smb + (uint32_t)((CIDX) & 3) * STAGE_B;              \
        _Pragma("unroll")                                                     \
        for (int p = 0; p < 2; ++p) {                                         \
            int idx = tid + p * 256;                                          \
            int row = idx >> 2, c8 = idx & 3;                                 \
            uint32_t sw = (uint32_t)(row * 64 + ((c8 ^ ((row >> 1) & 3)) << 4)); \
            size_t go = (size_t)(m0 + row) * K + (CIDX) * 32 + c8 * 8;        \
            CPASYNC16(base_ + sw, Agh + go);                                  \
            if (SPLIT_A) CPASYNC16(base_ + 8192 + sw, Agl + go);              \
        }                                                                     \
        {                                                                     \
            int row = tid >> 2, c8 = tid & 3;                                 \
            uint32_t sw = (uint32_t)(row * 64 + ((c8 ^ ((row >> 1) & 3)) << 4)); \
            size_t go = (size_t)(n0 + row) * K + (CIDX) * 32 + c8 * 8;        \
            CPASYNC16(base_ + 16384 + sw, Bg + go);                           \
        }                                                                     \
        asm volatile("cp.async.commit_group;" ::: "memory");                  \
    }

    ISSUE_STAGE(0);
    ISSUE_STAGE(1);
    ISSUE_STAGE(2);

    for (int c = 0; c < nchunk; ++c) {
        asm volatile("cp.async.wait_group 2;" ::: "memory");
        __syncthreads();

        if (c + 3 < nchunk) ISSUE_STAGE(c + 3);

        {
            uint32_t stb = smb + (uint32_t)(c & 3) * STAGE_B;
            const int g = lane >> 3, i = lane & 7;
#pragma unroll
            for (int ks = 0; ks < 2; ++ks) {
                uint32_t ah[2][4], al[2][4];
                const int arow_off = i + ((g & 1) << 3);
                const int akc = ks * 2 + (g >> 1);
#pragma unroll
                for (int mt = 0; mt < 2; ++mt) {
                    int row = wm * 32 + mt * 16 + arow_off;
                    uint32_t off = (uint32_t)(row * 64 + ((akc ^ ((row >> 1) & 3)) << 4));
                    LDSM4(ah[mt], stb + off);
                    if (SPLIT_A) LDSM4(al[mt], stb + 8192 + off);
                }
                uint32_t bh[4][2];
                const int brow_off = i + ((g >> 1) << 3);
                const int bkc = ks * 2 + (g & 1);
#pragma unroll
                for (int np = 0; np < 2; ++np) {
                    int row = wn * 32 + np * 16 + brow_off;
                    uint32_t off = (uint32_t)(row * 64 + ((bkc ^ ((row >> 1) & 3)) << 4));
                    uint32_t r4[4];
                    LDSM4(r4, stb + 16384 + off);
                    bh[np * 2][0] = r4[0]; bh[np * 2][1] = r4[1];
                    bh[np * 2 + 1][0] = r4[2]; bh[np * 2 + 1][1] = r4[3];
                }
#pragma unroll
                for (int mt = 0; mt < 2; ++mt)
#pragma unroll
                    for (int nb = 0; nb < 4; ++nb) {
                        MMAF16(acc[mt][nb], ah[mt], bh[nb]);
                        if (SPLIT_A) MMAF16(acc[mt][nb], al[mt], bh[nb]);
                    }
            }
        }
    }
#undef ISSUE_STAGE

    __syncthreads();

    const int r = lane >> 2, tg = lane & 3;
#pragma unroll
    for (int mt = 0; mt < 2; ++mt) {
#pragma unroll
        for (int nb = 0; nb < 4; ++nb) {
            int m = m0 + wm * 32 + mt * 16 + r;
            int n = n0 + wn * 32 + nb * 8 + tg * 2;
            float2 bb = *reinterpret_cast<const float2*>(bias + n);
#pragma unroll
            for (int half = 0; half < 2; ++half) {
                int mm = m + half * 8;
                float v0 = acc[mt][nb][half * 2 + 0] + bb.x;
                float v1 = acc[mt][nb][half * 2 + 1] + bb.y;
                if (MODE == 1) {
                    float2 vv = {v0, v1};
                    *reinterpret_cast<float2*>(out + (size_t)mm * N + n) = vv;
                } else {
                    int t = mm >> 3;
                    int b = mm & 7;
                    int which = n >> 10;
                    int h = (n >> 6) & 15;
                    int d = n & 63;
                    float sc = (which == 0) ? 0.125f : 1.0f;
                    __half* dst = (which == 0) ? g_Q : (which == 1) ? g_K : g_V;
                    size_t off = ((size_t)(b * Hh + h) * Tt + t) * HD + d;
                    float2 vv = {v0 * sc, v1 * sc};
                    *reinterpret_cast<__half2*>(dst + off) = __float22half2_rn(vv);
                }
            }
        }
    }
}

// ---------------------------------------------------------------------------
// Flash attention: Q,K,V single fp16 (QK 1 mma/k16); P hi/lo (PV 2 mmas/k16).
// smem: Q 16KB @0; 2 KV stages of 16KB @16384. 2 CTAs/SM.
// ---------------------------------------------------------------------------
__global__ __launch_bounds__(256, 2)
void attn_mma(const float* __restrict__ rpb)
{
    extern __shared__ __align__(16) char sm[];
    const int tid = threadIdx.x;
    const int lane = tid & 31;
    const int w = tid >> 5;
    const int b = blockIdx.x;
    const int h = blockIdx.y >> 3;
    const int t0 = (blockIdx.y & 7) * 128;
    const int bh = b * Hh + h;

    const uint32_t uQ = smem_u32(sm);
    const uint32_t uS0 = uQ + 16384;

    {   // Q tile: 128 rows x 128B = 16KB
#pragma unroll
        for (int p = 0; p < 4; ++p) {
            int i = tid + p * 256;
            int row = i >> 3, cc = i & 7;
            const __half* src = g_Q + ((size_t)bh * Tt + t0 + row) * HD + cc * 8;
            uint32_t dst = uQ + row * 128 + (((cc ^ (row & 7))) << 4);
            CPASYNC16(dst, src);
        }
    }
    const __half* kvsrc[2] = { g_K, g_V };
#define LOAD_CHUNK(CIDX, ST)                                                   \
    {                                                                          \
        const uint32_t base_ = uS0 + (uint32_t)(ST) * 16384;                   \
        int s0_ = (CIDX) * 64;                                                 \
        _Pragma("unroll")                                                      \
        for (int p = 0; p < 4; ++p) {                                          \
            int i = tid + p * 256;                                             \
            int tile = i >> 9;                                                 \
            int rem = i & 511;                                                 \
            int row = rem >> 3, cc = rem & 7;                                  \
            const __half* src = kvsrc[tile]                                    \
                + ((size_t)bh * Tt + s0_ + row) * HD + cc * 8;                 \
            uint32_t dst = base_ + tile * 8192 + row * 128                     \
                         + (((cc ^ (row & 7))) << 4);                          \
            CPASYNC16(dst, src);                                               \
        }                                                                      \
    }

    LOAD_CHUNK(0, 0);
    asm volatile("cp.async.commit_group;" ::: "memory");
    LOAD_CHUNK(1, 1);
    asm volatile("cp.async.commit_group;" ::: "memory");

    float o[8][4];
#pragma unroll
    for (int j = 0; j < 8; ++j)
#pragma unroll
        for (int v = 0; v < 4; ++v) o[j][v] = 0.f;
    float m0r = -1e30f, m1r = -1e30f, l0r = 0.f, l1r = 0.f;

    const int rq = lane >> 2;
    const int cq = (lane & 3) * 2;
    const size_t brow0_base = ((size_t)h * Tt + (t0 + w * 16 + rq)) * Tt;
    const size_t brow1_base = brow0_base + 8 * (size_t)Tt;

    const int qrow = w * 16 + (lane & 15);
    const uint32_t qrb = uQ + qrow * 128;
    const uint32_t qsel = (uint32_t)(lane >> 4);

    for (int c = 0; c < 16; ++c) {
        if (c == 15) asm volatile("cp.async.wait_group 0;" ::: "memory");
        else         asm volatile("cp.async.wait_group 1;" ::: "memory");
        __syncthreads();

        const uint32_t stb = uS0 + (uint32_t)(c & 1) * 16384;
        const int g = lane >> 3, i = lane & 7;

        float s[8][4];
#pragma unroll
        for (int j = 0; j < 8; ++j)
#pragma unroll
            for (int v = 0; v < 4; ++v) s[j][v] = 0.f;

#pragma unroll
        for (int kk = 0; kk < 4; ++kk) {
            uint32_t qh[4];
            {
                uint32_t ccol = 2u * kk + qsel;
                uint32_t off = ((ccol ^ (qrow & 7)) << 4);
                LDSM4(qh, qrb + off);
            }
            uint32_t kb[8][2];
            const int brow_off = i + ((g >> 1) << 3);
            const int bkc = kk * 2 + (g & 1);
#pragma unroll
            for (int ng = 0; ng < 4; ++ng) {
                int row = ng * 16 + brow_off;
                uint32_t off = (uint32_t)(row * 128 + ((bkc ^ (row & 7)) << 4));
                uint32_t r4[4];
                LDSM4(r4, stb + off);
                kb[ng * 2][0] = r4[0]; kb[ng * 2][1] = r4[1];
                kb[ng * 2 + 1][0] = r4[2]; kb[ng * 2 + 1][1] = r4[3];
            }
#pragma unroll
            for (int nt = 0; nt < 8; ++nt)
                MMAF16(s[nt], qh, kb[nt]);
        }

        {
            const float* bp0 = rpb + brow0_base + c * 64 + cq;
            const float* bp1 = rpb + brow1_base + c * 64 + cq;
#pragma unroll
            for (int j = 0; j < 8; ++j) {
                float2 b0 = *reinterpret_cast<const float2*>(bp0 + j * 8);
                float2 b1 = *reinterpret_cast<const float2*>(bp1 + j * 8);
                s[j][0] += b0.x; s[j][1] += b0.y;
                s[j][2] += b1.x; s[j][3] += b1.y;
            }
        }

        float cm0 = -1e30f, cm1 = -1e30f;
#pragma unroll
        for (int j = 0; j < 8; ++j) {
            cm0 = fmaxf(cm0, fmaxf(s[j][0], s[j][1]));
            cm1 = fmaxf(cm1, fmaxf(s[j][2], s[j][3]));
        }
        cm0 = fmaxf(cm0, __shfl_xor_sync(0xffffffffu, cm0, 1));
        cm0 = fmaxf(cm0, __shfl_xor_sync(0xffffffffu, cm0, 2));
        cm1 = fmaxf(cm1, __shfl_xor_sync(0xffffffffu, cm1, 1));
        cm1 = fmaxf(cm1, __shfl_xor_sync(0xffffffffu, cm1, 2));
        float m0n = fmaxf(m0r, cm0), m1n = fmaxf(m1r, cm1);
        float cor0 = __expf(m0r - m0n), cor1 = __expf(m1r - m1n);
        m0r = m0n; m1r = m1n;
        float rs0 = 0.f, rs1 = 0.f;
#pragma unroll
        for (int j = 0; j < 8; ++j) {
            s[j][0] = __expf(s[j][0] - m0n);
            s[j][1] = __expf(s[j][1] - m0n);
            s[j][2] = __expf(s[j][2] - m1n);
            s[j][3] = __expf(s[j][3] - m1n);
            rs0 += s[j][0] + s[j][1];
            rs1 += s[j][2] + s[j][3];
        }
        rs0 += __shfl_xor_sync(0xffffffffu, rs0, 1);
        rs0 += __shfl_xor_sync(0xffffffffu, rs0, 2);
        rs1 += __shfl_xor_sync(0xffffffffu, rs1, 1);
        rs1 += __shfl_xor_sync(0xffffffffu, rs1, 2);
        l0r = l0r * cor0 + rs0;
        l1r = l1r * cor1 + rs1;
#pragma unroll
        for (int j = 0; j < 8; ++j) {
            o[j][0] *= cor0; o[j][1] *= cor0;
            o[j][2] *= cor1; o[j][3] *= cor1;
        }

        // P hi/lo (fp16) fragments
        uint32_t ph[8][2], pl[8][2];
#pragma unroll
        for (int j = 0; j < 8; ++j) {
            float2 v0 = {s[j][0], s[j][1]};
            __half2 hh0 = __float22half2_rn(v0);
            ph[j][0] = *reinterpret_cast<uint32_t*>(&hh0);
            float2 lo0 = {s[j][0] - __half2float(__low2half(hh0)),
                          s[j][1] - __half2float(__high2half(hh0))};
            __half2 ll0 = __float22half2_rn(lo0);
            pl[j][0] = *reinterpret_cast<uint32_t*>(&ll0);
            float2 v1 = {s[j][2], s[j][3]};
            __half2 hh1 = __float22half2_rn(v1);
            ph[j][1] = *reinterpret_cast<uint32_t*>(&hh1);
            float2 lo1 = {s[j][2] - __half2float(__low2half(hh1)),
                          s[j][3] - __half2float(__high2half(hh1))};
            __half2 ll1 = __float22half2_rn(lo1);
            pl[j][1] = *reinterpret_cast<uint32_t*>(&ll1);
        }

#pragma unroll
        for (int kk = 0; kk < 4; ++kk) {
            uint32_t a_h[4] = { ph[2*kk][0], ph[2*kk][1], ph[2*kk+1][0], ph[2*kk+1][1] };
            uint32_t a_l[4] = { pl[2*kk][0], pl[2*kk][1], pl[2*kk+1][0], pl[2*kk+1][1] };
            uint32_t vb[8][2];
            const int srow = kk * 16 + i + ((g >> 1) << 3);
#pragma unroll
            for (int dg = 0; dg < 4; ++dg) {
                int ck = dg * 2 + (g & 1);
                uint32_t off = (uint32_t)(srow * 128 + ((ck ^ (srow & 7)) << 4));
                uint32_t r4[4];
                LDSM4T(r4, stb + 8192 + off);
                vb[dg * 2][0] = r4[0]; vb[dg * 2][1] = r4[2];
                vb[dg * 2 + 1][0] = r4[1]; vb[dg * 2 + 1][1] = r4[3];
            }
#pragma unroll
            for (int dt = 0; dt < 8; ++dt) {
                MMAF16(o[dt], a_h, vb[dt]);
                MMAF16(o[dt], a_l, vb[dt]);
            }
        }

        __syncthreads();
        if (c + 2 < 16) {
            LOAD_CHUNK(c + 2, c & 1);
            asm volatile("cp.async.commit_group;" ::: "memory");
        }
    }

    float inv0 = 1.f / l0r, inv1 = 1.f / l1r;
    int t_row0 = t0 + w * 16 + rq;
    int t_row1 = t_row0 + 8;
#pragma unroll
    for (int j = 0; j < 8; ++j) {
        int d = j * 8 + cq;
        size_t i0 = ((size_t)t_row0 * Bb + b) * Ee + h * HD + d;
        size_t i1 = ((size_t)t_row1 * Bb + b) * Ee + h * HD + d;
        float x0 = o[j][0] * inv0, y0 = o[j][1] * inv0;
        float x1 = o[j][2] * inv1, y1 = o[j][3] * inv1;
        float2 v0 = {x0, y0};
        __half2 hh0 = __float22half2_rn(v0);
        *reinterpret_cast<__half2*>(g_AOh + i0) = hh0;
        float2 lo0 = {x0 - __half2float(__low2half(hh0)),
                      y0 - __half2float(__high2half(hh0))};
        *reinterpret_cast<__half2*>(g_AOl + i0) = __float22half2_rn(lo0);
        float2 v1 = {x1, y1};
        __half2 hh1 = __float22half2_rn(v1);
        *reinterpret_cast<__half2*>(g_AOh + i1) = hh1;
        float2 lo1 = {x1 - __half2float(__low2half(hh1)),
                      y1 - __half2float(__high2half(hh1))};
        *reinterpret_cast<__half2*>(g_AOl + i1) = __float22half2_rn(lo1);
    }
#undef LOAD_CHUNK
}

// ---------------------------------------------------------------------------
extern "C" void kernel_launch(void* const* d_in, const int* in_sizes, int n_in,
                              void* d_out, int out_size)
{
    const float* query = (const float*)d_in[0];
    const float* ipw   = (const float*)d_in[1];
    const float* ipb   = (const float*)d_in[2];
    const float* il    = (const float*)d_in[3];
    const float* ir    = (const float*)d_in[4];
    const float* opw   = (const float*)d_in[5];
    const float* opb   = (const float*)d_in[6];
    const float* ol    = (const float*)d_in[7];
    const float* orr   = (const float*)d_in[8];
    const float* rpb   = (const float*)d_in[9];
    float* out = (float*)d_out;

    static bool attr_set = false;
    if (!attr_set) {
        cudaFuncSetAttribute((const void*)gemm_mma<0, 0>,
            cudaFuncAttributeMaxDynamicSharedMemorySize, 81920);
        cudaFuncSetAttribute((const void*)gemm_mma<1, 1>,
            cudaFuncAttributeMaxDynamicSharedMemorySize, 81920);
        cudaFuncSetAttribute((const void*)attn_mma,
            cudaFuncAttributeMaxDynamicSharedMemorySize, 49152);
        attr_set = true;
    }

    weff_kernel<0><<<(F3 * Ee + 255) / 256, 256>>>(ipw, il, ir);
    weff_kernel<1><<<(Ee * Ee + 255) / 256, 256>>>(opw, ol, orr);
    qsplit_kernel<<<Nrows * Ee / 1024, 256>>>(query);

    gemm_mma<0, 0><<<dim3(F3 / BN, Nrows / BM), 256, 81920>>>(ipb, nullptr, F3, Ee);

    attn_mma<<<dim3(Bb, Hh * 8), 256, 49152>>>(rpb);

    gemm_mma<1, 1><<<dim3(Ee / BN, Nrows / BM), 256, 81920>>>(opb, out, Ee, Ee);
}

// round 14
// speedup vs baseline: 3.8155x; 1.1044x over previous
#include <cuda_runtime.h>
#include <cuda_fp16.h>
#include <cstdint>

// ---------------------------------------------------------------------------
// MultiheadAttention with low-rank-augmented in/out projections.
// T=1024, B=8, E=1024, H=16, R=16, HD=64.
//
// R14: gemm<0> (single-A fp16) retiled to BK=64 (half the chunk overhead);
//      attention P·V drops the P-lo term (single x single, error budget
//      allows it). gemm<1> (split-A) unchanged at BK=32.
// ---------------------------------------------------------------------------

namespace {
constexpr int Tt = 1024;
constexpr int Bb = 8;
constexpr int Ee = 1024;
constexpr int Hh = 16;
constexpr int Rr = 16;
constexpr int HD = 64;
constexpr int F3 = 3 * Ee;          // 3072
constexpr int Nrows = Tt * Bb;      // 8192
constexpr int BM = 128, BN = 64;
constexpr int STAGE32 = 20480;      // split-A BK=32: Ah 8K, Al 8K, W 4K
constexpr int STAGE64 = 24576;      // single-A BK=64: A 16K, W 8K
}

// Scratch (device globals; no runtime allocation).
__device__ __align__(16) __half g_Win_h[F3 * Ee];
__device__ __align__(16) __half g_Wout_h[Ee * Ee];
__device__ __align__(16) __half g_Ah[Nrows * Ee];
__device__ __align__(16) __half g_AOh[Nrows * Ee];
__device__ __align__(16) __half g_AOl[Nrows * Ee];
__device__ __align__(16) __half g_Q[Bb * Hh * Tt * HD];
__device__ __align__(16) __half g_K[Bb * Hh * Tt * HD];
__device__ __align__(16) __half g_V[Bb * Hh * Tt * HD];

// ---------------------------------------------------------------------------
__device__ __forceinline__ uint32_t smem_u32(const void* p) {
    uint32_t a;
    asm("{ .reg .u64 t; cvta.to.shared.u64 t, %1; cvt.u32.u64 %0, t; }"
        : "=r"(a) : "l"(p));
    return a;
}

#define LDSM4(R, A)                                                           \
    asm volatile("ldmatrix.sync.aligned.m8n8.x4.shared.b16 {%0,%1,%2,%3}, [%4];" \
                 : "=r"((R)[0]), "=r"((R)[1]), "=r"((R)[2]), "=r"((R)[3])     \
                 : "r"(A))

#define LDSM4T(R, A)                                                          \
    asm volatile("ldmatrix.sync.aligned.m8n8.x4.trans.shared.b16 {%0,%1,%2,%3}, [%4];" \
                 : "=r"((R)[0]), "=r"((R)[1]), "=r"((R)[2]), "=r"((R)[3])     \
                 : "r"(A))

#define MMAF16(C, A, B)                                                       \
    asm volatile("mma.sync.aligned.m16n8k16.row.col.f32.f16.f16.f32 "         \
                 "{%0,%1,%2,%3}, {%4,%5,%6,%7}, {%8,%9}, {%0,%1,%2,%3};"      \
                 : "+f"((C)[0]), "+f"((C)[1]), "+f"((C)[2]), "+f"((C)[3])     \
                 : "r"((A)[0]), "r"((A)[1]), "r"((A)[2]), "r"((A)[3]),        \
                   "r"((B)[0]), "r"((B)[1]))

#define CPASYNC16(D, S)                                                       \
    asm volatile("cp.async.cg.shared.global [%0], [%1], 16;"                  \
                 :: "r"(D), "l"(S))

// ---------------------------------------------------------------------------
// W_eff = W + L@R, written as single fp16.
// ---------------------------------------------------------------------------
template <int WHICH>
__global__ void weff_kernel(const float* __restrict__ W,
                            const float* __restrict__ L,
                            const float* __restrict__ Rm)
{
    const int F = (WHICH == 0) ? F3 : Ee;
    __half* oh = (WHICH == 0) ? g_Win_h : g_Wout_h;
    int idx = blockIdx.x * 256 + threadIdx.x;
    if (idx >= F * Ee) return;
    int f = idx >> 10;
    int e = idx & 1023;
    float s = W[idx];
#pragma unroll
    for (int r = 0; r < Rr; ++r)
        s = fmaf(L[f * Rr + r], Rm[r * Ee + e], s);
    oh[idx] = __float2half(s);
}

// ---------------------------------------------------------------------------
// Convert query (fp32) to single fp16.
// ---------------------------------------------------------------------------
__global__ void qsplit_kernel(const float* __restrict__ q)
{
    int idx = (blockIdx.x * 256 + threadIdx.x) * 4;
    float4 v = *reinterpret_cast<const float4*>(q + idx);
    __half2* ph = reinterpret_cast<__half2*>(g_Ah + idx);
    float2 v01 = {v.x, v.y}, v23 = {v.z, v.w};
    ph[0] = __float22half2_rn(v01);
    ph[1] = __float22half2_rn(v23);
}

// ---------------------------------------------------------------------------
// In-projection GEMM, single-A fp16, BK=64 chunks.
// Tile 128x64x64, 8 warps (4x2), 4-stage cp.async (96KB), 2 CTAs/SM.
// Scatter to Q/K/V single fp16 (q *0.125).
// ---------------------------------------------------------------------------
__global__ __launch_bounds__(256, 2)
void gemm_in(const float* __restrict__ bias, int N, int K)
{
    extern __shared__ __align__(16) char sm[];
    const __half* Ag = g_Ah;
    const __half* Bg = g_Win_h;

    const int tid  = threadIdx.x;
    const int lane = tid & 31;
    const int wid  = tid >> 5;
    const int wm   = wid >> 1;
    const int wn   = wid & 1;
    const int m0 = blockIdx.y * BM;
    const int n0 = blockIdx.x * BN;

    const uint32_t smb = smem_u32(sm);

    float acc[2][4][4];
#pragma unroll
    for (int a = 0; a < 2; ++a)
#pragma unroll
        for (int b = 0; b < 4; ++b)
#pragma unroll
            for (int c = 0; c < 4; ++c) acc[a][b][c] = 0.f;

    const int nchunk = K / 64;      // 16

#define ISSUE64(CIDX)                                                         \
    {                                                                         \
        uint32_t base_ = smb + (uint32_t)((CIDX) & 3) * STAGE64;              \
        _Pragma("unroll")                                                     \
        for (int p = 0; p < 4; ++p) {                                         \
            int idx = tid + p * 256;                                          \
            int row = idx >> 3, c8 = idx & 7;                                 \
            uint32_t sw = (uint32_t)(row * 128 + ((c8 ^ (row & 7)) << 4));    \
            size_t go = (size_t)(m0 + row) * K + (CIDX) * 64 + c8 * 8;        \
            CPASYNC16(base_ + sw, Ag + go);                                   \
        }                                                                     \
        _Pragma("unroll")                                                     \
        for (int p = 0; p < 2; ++p) {                                         \
            int idx = tid + p * 256;                                          \
            int row = idx >> 3, c8 = idx & 7;                                 \
            uint32_t sw = (uint32_t)(row * 128 + ((c8 ^ (row & 7)) << 4));    \
            size_t go = (size_t)(n0 + row) * K + (CIDX) * 64 + c8 * 8;        \
            CPASYNC16(base_ + 16384 + sw, Bg + go);                           \
        }                                                                     \
        asm volatile("cp.async.commit_group;" ::: "memory");                  \
    }

    ISSUE64(0);
    ISSUE64(1);
    ISSUE64(2);

    for (int c = 0; c < nchunk; ++c) {
        asm volatile("cp.async.wait_group 2;" ::: "memory");
        __syncthreads();

        if (c + 3 < nchunk) ISSUE64(c + 3);

        {
            uint32_t stb = smb + (uint32_t)(c & 3) * STAGE64;
            const int g = lane >> 3, i = lane & 7;
#pragma unroll
            for (int ks = 0; ks < 4; ++ks) {
                uint32_t ah[2][4];
                const int arow_off = i + ((g & 1) << 3);
                const int akc = ks * 2 + (g >> 1);
#pragma unroll
                for (int mt = 0; mt < 2; ++mt) {
                    int row = wm * 32 + mt * 16 + arow_off;
                    uint32_t off = (uint32_t)(row * 128 + ((akc ^ (row & 7)) << 4));
                    LDSM4(ah[mt], stb + off);
                }
                uint32_t bh[4][2];
                const int brow_off = i + ((g >> 1) << 3);
                const int bkc = ks * 2 + (g & 1);
#pragma unroll
                for (int np = 0; np < 2; ++np) {
                    int row = wn * 32 + np * 16 + brow_off;
                    uint32_t off = (uint32_t)(row * 128 + ((bkc ^ (row & 7)) << 4));
                    uint32_t r4[4];
                    LDSM4(r4, stb + 16384 + off);
                    bh[np * 2][0] = r4[0]; bh[np * 2][1] = r4[1];
                    bh[np * 2 + 1][0] = r4[2]; bh[np * 2 + 1][1] = r4[3];
                }
#pragma unroll
                for (int mt = 0; mt < 2; ++mt)
#pragma unroll
                    for (int nb = 0; nb < 4; ++nb)
                        MMAF16(acc[mt][nb], ah[mt], bh[nb]);
            }
        }
    }
#undef ISSUE64

    __syncthreads();

    const int r = lane >> 2, tg = lane & 3;
#pragma unroll
    for (int mt = 0; mt < 2; ++mt) {
#pragma unroll
        for (int nb = 0; nb < 4; ++nb) {
            int m = m0 + wm * 32 + mt * 16 + r;
            int n = n0 + wn * 32 + nb * 8 + tg * 2;
            float2 bb = *reinterpret_cast<const float2*>(bias + n);
#pragma unroll
            for (int half = 0; half < 2; ++half) {
                int mm = m + half * 8;
                float v0 = acc[mt][nb][half * 2 + 0] + bb.x;
                float v1 = acc[mt][nb][half * 2 + 1] + bb.y;
                int t = mm >> 3;
                int b = mm & 7;
                int which = n >> 10;
                int h = (n >> 6) & 15;
                int d = n & 63;
                float sc = (which == 0) ? 0.125f : 1.0f;
                __half* dst = (which == 0) ? g_Q : (which == 1) ? g_K : g_V;
                size_t off = ((size_t)(b * Hh + h) * Tt + t) * HD + d;
                float2 vv = {v0 * sc, v1 * sc};
                *reinterpret_cast<__half2*>(dst + off) = __float22half2_rn(vv);
            }
        }
    }
}

// ---------------------------------------------------------------------------
// Out-projection GEMM, split-A fp16, BK=32 (unchanged R13 structure).
// ---------------------------------------------------------------------------
__global__ __launch_bounds__(256, 2)
void gemm_out(const float* __restrict__ bias, float* __restrict__ out,
              int N, int K)
{
    extern __shared__ __align__(16) char sm[];
    const __half* Agh = g_AOh;
    const __half* Agl = g_AOl;
    const __half* Bg  = g_Wout_h;

    const int tid  = threadIdx.x;
    const int lane = tid & 31;
    const int wid  = tid >> 5;
    const int wm   = wid >> 1;
    const int wn   = wid & 1;
    const int m0 = blockIdx.y * BM;
    const int n0 = blockIdx.x * BN;

    const uint32_t smb = smem_u32(sm);

    float acc[2][4][4];
#pragma unroll
    for (int a = 0; a < 2; ++a)
#pragma unroll
        for (int b = 0; b < 4; ++b)
#pragma unroll
            for (int c = 0; c < 4; ++c) acc[a][b][c] = 0.f;

    const int nchunk = K / 32;

#define ISSUE32(CIDX)                                                         \
    {                                                                         \
        uint32_t base_ = smb + (uint32_t)((CIDX) & 3) * STAGE32;              \
        _Pragma("unroll")                                                     \
        for (int p = 0; p < 2; ++p) {                                         \
            int idx = tid + p * 256;                                          \
            int row = idx >> 2, c8 = idx & 3;                                 \
            uint32_t sw = (uint32_t)(row * 64 + ((c8 ^ ((row >> 1) & 3)) << 4)); \
            size_t go = (size_t)(m0 + row) * K + (CIDX) * 32 + c8 * 8;        \
            CPASYNC16(base_ + sw, Agh + go);                                  \
            CPASYNC16(base_ + 8192 + sw, Agl + go);                           \
        }                                                                     \
        {                                                                     \
            int row = tid >> 2, c8 = tid & 3;                                 \
            uint32_t sw = (uint32_t)(row * 64 + ((c8 ^ ((row >> 1) & 3)) << 4)); \
            size_t go = (size_t)(n0 + row) * K + (CIDX) * 32 + c8 * 8;        \
            CPASYNC16(base_ + 16384 + sw, Bg + go);                           \
        }                                                                     \
        asm volatile("cp.async.commit_group;" ::: "memory");                  \
    }

    ISSUE32(0);
    ISSUE32(1);
    ISSUE32(2);

    for (int c = 0; c < nchunk; ++c) {
        asm volatile("cp.async.wait_group 2;" ::: "memory");
        __syncthreads();

        if (c + 3 < nchunk) ISSUE32(c + 3);

        {
            uint32_t stb = smb + (uint32_t)(c & 3) * STAGE32;
            const int g = lane >> 3, i = lane & 7;
#pragma unroll
            for (int ks = 0; ks < 2; ++ks) {
                uint32_t ah[2][4], al[2][4];
                const int arow_off = i + ((g & 1) << 3);
                const int akc = ks * 2 + (g >> 1);
#pragma unroll
                for (int mt = 0; mt < 2; ++mt) {
                    int row = wm * 32 + mt * 16 + arow_off;
                    uint32_t off = (uint32_t)(row * 64 + ((akc ^ ((row >> 1) & 3)) << 4));
                    LDSM4(ah[mt], stb + off);
                    LDSM4(al[mt], stb + 8192 + off);
                }
                uint32_t bh[4][2];
                const int brow_off = i + ((g >> 1) << 3);
                const int bkc = ks * 2 + (g & 1);
#pragma unroll
                for (int np = 0; np < 2; ++np) {
                    int row = wn * 32 + np * 16 + brow_off;
                    uint32_t off = (uint32_t)(row * 64 + ((bkc ^ ((row >> 1) & 3)) << 4));
                    uint32_t r4[4];
                    LDSM4(r4, stb + 16384 + off);
                    bh[np * 2][0] = r4[0]; bh[np * 2][1] = r4[1];
                    bh[np * 2 + 1][0] = r4[2]; bh[np * 2 + 1][1] = r4[3];
                }
#pragma unroll
                for (int mt = 0; mt < 2; ++mt)
#pragma unroll
                    for (int nb = 0; nb < 4; ++nb) {
                        MMAF16(acc[mt][nb], ah[mt], bh[nb]);
                        MMAF16(acc[mt][nb], al[mt], bh[nb]);
                    }
            }
        }
    }
#undef ISSUE32

    __syncthreads();

    const int r = lane >> 2, tg = lane & 3;
#pragma unroll
    for (int mt = 0; mt < 2; ++mt) {
#pragma unroll
        for (int nb = 0; nb < 4; ++nb) {
            int m = m0 + wm * 32 + mt * 16 + r;
            int n = n0 + wn * 32 + nb * 8 + tg * 2;
            float2 bb = *reinterpret_cast<const float2*>(bias + n);
#pragma unroll
            for (int half = 0; half < 2; ++half) {
                int mm = m + half * 8;
                float2 vv = {acc[mt][nb][half * 2 + 0] + bb.x,
                             acc[mt][nb][half * 2 + 1] + bb.y};
                *reinterpret_cast<float2*>(out + (size_t)mm * N + n) = vv;
            }
        }
    }
}

// ---------------------------------------------------------------------------
// Flash attention: Q,K,V,P all single fp16 (1 mma/k16 in QK and PV).
// smem: Q 16KB @0; 2 KV stages of 16KB @16384. 2 CTAs/SM.
// ---------------------------------------------------------------------------
__global__ __launch_bounds__(256, 2)
void attn_mma(const float* __restrict__ rpb)
{
    extern __shared__ __align__(16) char sm[];
    const int tid = threadIdx.x;
    const int lane = tid & 31;
    const int w = tid >> 5;
    const int b = blockIdx.x;
    const int h = blockIdx.y >> 3;
    const int t0 = (blockIdx.y & 7) * 128;
    const int bh = b * Hh + h;

    const uint32_t uQ = smem_u32(sm);
    const uint32_t uS0 = uQ + 16384;

    {
#pragma unroll
        for (int p = 0; p < 4; ++p) {
            int i = tid + p * 256;
            int row = i >> 3, cc = i & 7;
            const __half* src = g_Q + ((size_t)bh * Tt + t0 + row) * HD + cc * 8;
            uint32_t dst = uQ + row * 128 + (((cc ^ (row & 7))) << 4);
            CPASYNC16(dst, src);
        }
    }
    const __half* kvsrc[2] = { g_K, g_V };
#define LOAD_CHUNK(CIDX, ST)                                                   \
    {                                                                          \
        const uint32_t base_ = uS0 + (uint32_t)(ST) * 16384;                   \
        int s0_ = (CIDX) * 64;                                                 \
        _Pragma("unroll")                                                      \
        for (int p = 0; p < 4; ++p) {                                          \
            int i = tid + p * 256;                                             \
            int tile = i >> 9;                                                 \
            int rem = i & 511;                                                 \
            int row = rem >> 3, cc = rem & 7;                                  \
            const __half* src = kvsrc[tile]                                    \
                + ((size_t)bh * Tt + s0_ + row) * HD + cc * 8;                 \
            uint32_t dst = base_ + tile * 8192 + row * 128                     \
                         + (((cc ^ (row & 7))) << 4);                          \
            CPASYNC16(dst, src);                                               \
        }                                                                      \
    }

    LOAD_CHUNK(0, 0);
    asm volatile("cp.async.commit_group;" ::: "memory");
    LOAD_CHUNK(1, 1);
    asm volatile("cp.async.commit_group;" ::: "memory");

    float o[8][4];
#pragma unroll
    for (int j = 0; j < 8; ++j)
#pragma unroll
        for (int v = 0; v < 4; ++v) o[j][v] = 0.f;
    float m0r = -1e30f, m1r = -1e30f, l0r = 0.f, l1r = 0.f;

    const int rq = lane >> 2;
    const int cq = (lane & 3) * 2;
    const size_t brow0_base = ((size_t)h * Tt + (t0 + w * 16 + rq)) * Tt;
    const size_t brow1_base = brow0_base + 8 * (size_t)Tt;

    const int qrow = w * 16 + (lane & 15);
    const uint32_t qrb = uQ + qrow * 128;
    const uint32_t qsel = (uint32_t)(lane >> 4);

    for (int c = 0; c < 16; ++c) {
        if (c == 15) asm volatile("cp.async.wait_group 0;" ::: "memory");
        else         asm volatile("cp.async.wait_group 1;" ::: "memory");
        __syncthreads();

        const uint32_t stb = uS0 + (uint32_t)(c & 1) * 16384;
        const int g = lane >> 3, i = lane & 7;

        float s[8][4];
#pragma unroll
        for (int j = 0; j < 8; ++j)
#pragma unroll
            for (int v = 0; v < 4; ++v) s[j][v] = 0.f;

#pragma unroll
        for (int kk = 0; kk < 4; ++kk) {
            uint32_t qh[4];
            {
                uint32_t ccol = 2u * kk + qsel;
                uint32_t off = ((ccol ^ (qrow & 7)) << 4);
                LDSM4(qh, qrb + off);
            }
            uint32_t kb[8][2];
            const int brow_off = i + ((g >> 1) << 3);
            const int bkc = kk * 2 + (g & 1);
#pragma unroll
            for (int ng = 0; ng < 4; ++ng) {
                int row = ng * 16 + brow_off;
                uint32_t off = (uint32_t)(row * 128 + ((bkc ^ (row & 7)) << 4));
                uint32_t r4[4];
                LDSM4(r4, stb + off);
                kb[ng * 2][0] = r4[0]; kb[ng * 2][1] = r4[1];
                kb[ng * 2 + 1][0] = r4[2]; kb[ng * 2 + 1][1] = r4[3];
            }
#pragma unroll
            for (int nt = 0; nt < 8; ++nt)
                MMAF16(s[nt], qh, kb[nt]);
        }

        {
            const float* bp0 = rpb + brow0_base + c * 64 + cq;
            const float* bp1 = rpb + brow1_base + c * 64 + cq;
#pragma unroll
            for (int j = 0; j < 8; ++j) {
                float2 b0 = *reinterpret_cast<const float2*>(bp0 + j * 8);
                float2 b1 = *reinterpret_cast<const float2*>(bp1 + j * 8);
                s[j][0] += b0.x; s[j][1] += b0.y;
                s[j][2] += b1.x; s[j][3] += b1.y;
            }
        }

        float cm0 = -1e30f, cm1 = -1e30f;
#pragma unroll
        for (int j = 0; j < 8; ++j) {
            cm0 = fmaxf(cm0, fmaxf(s[j][0], s[j][1]));
            cm1 = fmaxf(cm1, fmaxf(s[j][2], s[j][3]));
        }
        cm0 = fmaxf(cm0, __shfl_xor_sync(0xffffffffu, cm0, 1));
        cm0 = fmaxf(cm0, __shfl_xor_sync(0xffffffffu, cm0, 2));
        cm1 = fmaxf(cm1, __shfl_xor_sync(0xffffffffu, cm1, 1));
        cm1 = fmaxf(cm1, __shfl_xor_sync(0xffffffffu, cm1, 2));
        float m0n = fmaxf(m0r, cm0), m1n = fmaxf(m1r, cm1);
        float cor0 = __expf(m0r - m0n), cor1 = __expf(m1r - m1n);
        m0r = m0n; m1r = m1n;
        float rs0 = 0.f, rs1 = 0.f;
#pragma unroll
        for (int j = 0; j < 8; ++j) {
            s[j][0] = __expf(s[j][0] - m0n);
            s[j][1] = __expf(s[j][1] - m0n);
            s[j][2] = __expf(s[j][2] - m1n);
            s[j][3] = __expf(s[j][3] - m1n);
            rs0 += s[j][0] + s[j][1];
            rs1 += s[j][2] + s[j][3];
        }
        rs0 += __shfl_xor_sync(0xffffffffu, rs0, 1);
        rs0 += __shfl_xor_sync(0xffffffffu, rs0, 2);
        rs1 += __shfl_xor_sync(0xffffffffu, rs1, 1);
        rs1 += __shfl_xor_sync(0xffffffffu, rs1, 2);
        l0r = l0r * cor0 + rs0;
        l1r = l1r * cor1 + rs1;
#pragma unroll
        for (int j = 0; j < 8; ++j) {
            o[j][0] *= cor0; o[j][1] *= cor0;
            o[j][2] *= cor1; o[j][3] *= cor1;
        }

        // P single fp16 fragments
        uint32_t ph[8][2];
#pragma unroll
        for (int j = 0; j < 8; ++j) {
            float2 v0 = {s[j][0], s[j][1]};
            __half2 hh0 = __float22half2_rn(v0);
            ph[j][0] = *reinterpret_cast<uint32_t*>(&hh0);
            float2 v1 = {s[j][2], s[j][3]};
            __half2 hh1 = __float22half2_rn(v1);
            ph[j][1] = *reinterpret_cast<uint32_t*>(&hh1);
        }

#pragma unroll
        for (int kk = 0; kk < 4; ++kk) {
            uint32_t a_h[4] = { ph[2*kk][0], ph[2*kk][1], ph[2*kk+1][0], ph[2*kk+1][1] };
            uint32_t vb[8][2];
            const int srow = kk * 16 + i + ((g >> 1) << 3);
#pragma unroll
            for (int dg = 0; dg < 4; ++dg) {
                int ck = dg * 2 + (g & 1);
                uint32_t off = (uint32_t)(srow * 128 + ((ck ^ (srow & 7)) << 4));
                uint32_t r4[4];
                LDSM4T(r4, stb + 8192 + off);
                vb[dg * 2][0] = r4[0]; vb[dg * 2][1] = r4[2];
                vb[dg * 2 + 1][0] = r4[1]; vb[dg * 2 + 1][1] = r4[3];
            }
#pragma unroll
            for (int dt = 0; dt < 8; ++dt)
                MMAF16(o[dt], a_h, vb[dt]);
        }

        __syncthreads();
        if (c + 2 < 16) {
            LOAD_CHUNK(c + 2, c & 1);
            asm volatile("cp.async.commit_group;" ::: "memory");
        }
    }

    float inv0 = 1.f / l0r, inv1 = 1.f / l1r;
    int t_row0 = t0 + w * 16 + rq;
    int t_row1 = t_row0 + 8;
#pragma unroll
    for (int j = 0; j < 8; ++j) {
        int d = j * 8 + cq;
        size_t i0 = ((size_t)t_row0 * Bb + b) * Ee + h * HD + d;
        size_t i1 = ((size_t)t_row1 * Bb + b) * Ee + h * HD + d;
        float x0 = o[j][0] * inv0, y0 = o[j][1] * inv0;
        float x1 = o[j][2] * inv1, y1 = o[j][3] * inv1;
        float2 v0 = {x0, y0};
        __half2 hh0 = __float22half2_rn(v0);
        *reinterpret_cast<__half2*>(g_AOh + i0) = hh0;
        float2 lo0 = {x0 - __half2float(__low2half(hh0)),
                      y0 - __half2float(__high2half(hh0))};
        *reinterpret_cast<__half2*>(g_AOl + i0) = __float22half2_rn(lo0);
        float2 v1 = {x1, y1};
        __half2 hh1 = __float22half2_rn(v1);
        *reinterpret_cast<__half2*>(g_AOh + i1) = hh1;
        float2 lo1 = {x1 - __half2float(__low2half(hh1)),
                      y1 - __half2float(__high2half(hh1))};
        *reinterpret_cast<__half2*>(g_AOl + i1) = __float22half2_rn(lo1);
    }
#undef LOAD_CHUNK
}

// ---------------------------------------------------------------------------
extern "C" void kernel_launch(void* const* d_in, const int* in_sizes, int n_in,
                              void* d_out, int out_size)
{
    const float* query = (const float*)d_in[0];
    const float* ipw   = (const float*)d_in[1];
    const float* ipb   = (const float*)d_in[2];
    const float* il    = (const float*)d_in[3];
    const float* ir    = (const float*)d_in[4];
    const float* opw   = (const float*)d_in[5];
    const float* opb   = (const float*)d_in[6];
    const float* ol    = (const float*)d_in[7];
    const float* orr   = (const float*)d_in[8];
    const float* rpb   = (const float*)d_in[9];
    float* out = (float*)d_out;

    static bool attr_set = false;
    if (!attr_set) {
        cudaFuncSetAttribute((const void*)gemm_in,
            cudaFuncAttributeMaxDynamicSharedMemorySize, 98304);
        cudaFuncSetAttribute((const void*)gemm_out,
            cudaFuncAttributeMaxDynamicSharedMemorySize, 81920);
        cudaFuncSetAttribute((const void*)attn_mma,
            cudaFuncAttributeMaxDynamicSharedMemorySize, 49152);
        attr_set = true;
    }

    weff_kernel<0><<<(F3 * Ee + 255) / 256, 256>>>(ipw, il, ir);
    weff_kernel<1><<<(Ee * Ee + 255) / 256, 256>>>(opw, ol, orr);
    qsplit_kernel<<<Nrows * Ee / 1024, 256>>>(query);

    gemm_in<<<dim3(F3 / BN, Nrows / BM), 256, 98304>>>(ipb, F3, Ee);

    attn_mma<<<dim3(Bb, Hh * 8), 256, 49152>>>(rpb);

    gemm_out<<<dim3(Ee / BN, Nrows / BM), 256, 81920>>>(opb, out, Ee, Ee);
}

// round 15
// speedup vs baseline: 4.2818x; 1.1222x over previous
#include <cuda_runtime.h>
#include <cuda_fp16.h>
#include <cstdint>

// ---------------------------------------------------------------------------
// MultiheadAttention with low-rank-augmented in/out projections.
// T=1024, B=8, E=1024, H=16, R=16, HD=64.
//
// R15: gemm_out converted to the same single-A fp16 BK=64 scheme as gemm_in
//      (AO-lo plane dropped; error budget 5.0e-4 -> ~5.8e-4 predicted).
//      Attention epilogue writes single fp16 AO. Attention core unchanged.
// ---------------------------------------------------------------------------

namespace {
constexpr int Tt = 1024;
constexpr int Bb = 8;
constexpr int Ee = 1024;
constexpr int Hh = 16;
constexpr int Rr = 16;
constexpr int HD = 64;
constexpr int F3 = 3 * Ee;          // 3072
constexpr int Nrows = Tt * Bb;      // 8192
constexpr int BM = 128, BN = 64;
constexpr int STAGE64 = 24576;      // A 16K, W 8K
}

// Scratch (device globals; no runtime allocation).
__device__ __align__(16) __half g_Win_h[F3 * Ee];
__device__ __align__(16) __half g_Wout_h[Ee * Ee];
__device__ __align__(16) __half g_Ah[Nrows * Ee];
__device__ __align__(16) __half g_AOh[Nrows * Ee];
__device__ __align__(16) __half g_Q[Bb * Hh * Tt * HD];
__device__ __align__(16) __half g_K[Bb * Hh * Tt * HD];
__device__ __align__(16) __half g_V[Bb * Hh * Tt * HD];

// ---------------------------------------------------------------------------
__device__ __forceinline__ uint32_t smem_u32(const void* p) {
    uint32_t a;
    asm("{ .reg .u64 t; cvta.to.shared.u64 t, %1; cvt.u32.u64 %0, t; }"
        : "=r"(a) : "l"(p));
    return a;
}

#define LDSM4(R, A)                                                           \
    asm volatile("ldmatrix.sync.aligned.m8n8.x4.shared.b16 {%0,%1,%2,%3}, [%4];" \
                 : "=r"((R)[0]), "=r"((R)[1]), "=r"((R)[2]), "=r"((R)[3])     \
                 : "r"(A))

#define LDSM4T(R, A)                                                          \
    asm volatile("ldmatrix.sync.aligned.m8n8.x4.trans.shared.b16 {%0,%1,%2,%3}, [%4];" \
                 : "=r"((R)[0]), "=r"((R)[1]), "=r"((R)[2]), "=r"((R)[3])     \
                 : "r"(A))

#define MMAF16(C, A, B)                                                       \
    asm volatile("mma.sync.aligned.m16n8k16.row.col.f32.f16.f16.f32 "         \
                 "{%0,%1,%2,%3}, {%4,%5,%6,%7}, {%8,%9}, {%0,%1,%2,%3};"      \
                 : "+f"((C)[0]), "+f"((C)[1]), "+f"((C)[2]), "+f"((C)[3])     \
                 : "r"((A)[0]), "r"((A)[1]), "r"((A)[2]), "r"((A)[3]),        \
                   "r"((B)[0]), "r"((B)[1]))

#define CPASYNC16(D, S)                                                       \
    asm volatile("cp.async.cg.shared.global [%0], [%1], 16;"                  \
                 :: "r"(D), "l"(S))

// ---------------------------------------------------------------------------
// W_eff = W + L@R, written as single fp16.
// ---------------------------------------------------------------------------
template <int WHICH>
__global__ void weff_kernel(const float* __restrict__ W,
                            const float* __restrict__ L,
                            const float* __restrict__ Rm)
{
    const int F = (WHICH == 0) ? F3 : Ee;
    __half* oh = (WHICH == 0) ? g_Win_h : g_Wout_h;
    int idx = blockIdx.x * 256 + threadIdx.x;
    if (idx >= F * Ee) return;
    int f = idx >> 10;
    int e = idx & 1023;
    float s = W[idx];
#pragma unroll
    for (int r = 0; r < Rr; ++r)
        s = fmaf(L[f * Rr + r], Rm[r * Ee + e], s);
    oh[idx] = __float2half(s);
}

// ---------------------------------------------------------------------------
// Convert query (fp32) to single fp16.
// ---------------------------------------------------------------------------
__global__ void qsplit_kernel(const float* __restrict__ q)
{
    int idx = (blockIdx.x * 256 + threadIdx.x) * 4;
    float4 v = *reinterpret_cast<const float4*>(q + idx);
    __half2* ph = reinterpret_cast<__half2*>(g_Ah + idx);
    float2 v01 = {v.x, v.y}, v23 = {v.z, v.w};
    ph[0] = __float22half2_rn(v01);
    ph[1] = __float22half2_rn(v23);
}

// ---------------------------------------------------------------------------
// Unified single-A fp16 GEMM, BK=64 chunks.
// Tile 128x64x64, 8 warps (4x2), 4-stage cp.async (96KB), 2 CTAs/SM.
// MODE 0: A=g_Ah, W=g_Win_h -> scatter Q/K/V single fp16 (q *0.125)
// MODE 1: A=g_AOh, W=g_Wout_h -> out fp32 + bias
// ---------------------------------------------------------------------------
template <int MODE>
__global__ __launch_bounds__(256, 2)
void gemm_mma(const float* __restrict__ bias, float* __restrict__ out,
              int N, int K)
{
    extern __shared__ __align__(16) char sm[];
    const __half* Ag = (MODE == 0) ? g_Ah : g_AOh;
    const __half* Bg = (MODE == 0) ? g_Win_h : g_Wout_h;

    const int tid  = threadIdx.x;
    const int lane = tid & 31;
    const int wid  = tid >> 5;
    const int wm   = wid >> 1;
    const int wn   = wid & 1;
    const int m0 = blockIdx.y * BM;
    const int n0 = blockIdx.x * BN;

    const uint32_t smb = smem_u32(sm);

    float acc[2][4][4];
#pragma unroll
    for (int a = 0; a < 2; ++a)
#pragma unroll
        for (int b = 0; b < 4; ++b)
#pragma unroll
            for (int c = 0; c < 4; ++c) acc[a][b][c] = 0.f;

    const int nchunk = K / 64;      // 16

#define ISSUE64(CIDX)                                                         \
    {                                                                         \
        uint32_t base_ = smb + (uint32_t)((CIDX) & 3) * STAGE64;              \
        _Pragma("unroll")                                                     \
        for (int p = 0; p < 4; ++p) {                                         \
            int idx = tid + p * 256;                                          \
            int row = idx >> 3, c8 = idx & 7;                                 \
            uint32_t sw = (uint32_t)(row * 128 + ((c8 ^ (row & 7)) << 4));    \
            size_t go = (size_t)(m0 + row) * K + (CIDX) * 64 + c8 * 8;        \
            CPASYNC16(base_ + sw, Ag + go);                                   \
        }                                                                     \
        _Pragma("unroll")                                                     \
        for (int p = 0; p < 2; ++p) {                                         \
            int idx = tid + p * 256;                                          \
            int row = idx >> 3, c8 = idx & 7;                                 \
            uint32_t sw = (uint32_t)(row * 128 + ((c8 ^ (row & 7)) << 4));    \
            size_t go = (size_t)(n0 + row) * K + (CIDX) * 64 + c8 * 8;        \
            CPASYNC16(base_ + 16384 + sw, Bg + go);                           \
        }                                                                     \
        asm volatile("cp.async.commit_group;" ::: "memory");                  \
    }

    ISSUE64(0);
    ISSUE64(1);
    ISSUE64(2);

    for (int c = 0; c < nchunk; ++c) {
        asm volatile("cp.async.wait_group 2;" ::: "memory");
        __syncthreads();

        if (c + 3 < nchunk) ISSUE64(c + 3);

        {
            uint32_t stb = smb + (uint32_t)(c & 3) * STAGE64;
            const int g = lane >> 3, i = lane & 7;
#pragma unroll
            for (int ks = 0; ks < 4; ++ks) {
                uint32_t ah[2][4];
                const int arow_off = i + ((g & 1) << 3);
                const int akc = ks * 2 + (g >> 1);
#pragma unroll
                for (int mt = 0; mt < 2; ++mt) {
                    int row = wm * 32 + mt * 16 + arow_off;
                    uint32_t off = (uint32_t)(row * 128 + ((akc ^ (row & 7)) << 4));
                    LDSM4(ah[mt], stb + off);
                }
                uint32_t bh[4][2];
                const int brow_off = i + ((g >> 1) << 3);
                const int bkc = ks * 2 + (g & 1);
#pragma unroll
                for (int np = 0; np < 2; ++np) {
                    int row = wn * 32 + np * 16 + brow_off;
                    uint32_t off = (uint32_t)(row * 128 + ((bkc ^ (row & 7)) << 4));
                    uint32_t r4[4];
                    LDSM4(r4, stb + 16384 + off);
                    bh[np * 2][0] = r4[0]; bh[np * 2][1] = r4[1];
                    bh[np * 2 + 1][0] = r4[2]; bh[np * 2 + 1][1] = r4[3];
                }
#pragma unroll
                for (int mt = 0; mt < 2; ++mt)
#pragma unroll
                    for (int nb = 0; nb < 4; ++nb)
                        MMAF16(acc[mt][nb], ah[mt], bh[nb]);
            }
        }
    }
#undef ISSUE64

    __syncthreads();

    const int r = lane >> 2, tg = lane & 3;
#pragma unroll
    for (int mt = 0; mt < 2; ++mt) {
#pragma unroll
        for (int nb = 0; nb < 4; ++nb) {
            int m = m0 + wm * 32 + mt * 16 + r;
            int n = n0 + wn * 32 + nb * 8 + tg * 2;
            float2 bb = *reinterpret_cast<const float2*>(bias + n);
#pragma unroll
            for (int half = 0; half < 2; ++half) {
                int mm = m + half * 8;
                float v0 = acc[mt][nb][half * 2 + 0] + bb.x;
                float v1 = acc[mt][nb][half * 2 + 1] + bb.y;
                if (MODE == 1) {
                    float2 vv = {v0, v1};
                    *reinterpret_cast<float2*>(out + (size_t)mm * N + n) = vv;
                } else {
                    int t = mm >> 3;
                    int b = mm & 7;
                    int which = n >> 10;
                    int h = (n >> 6) & 15;
                    int d = n & 63;
                    float sc = (which == 0) ? 0.125f : 1.0f;
                    __half* dst = (which == 0) ? g_Q : (which == 1) ? g_K : g_V;
                    size_t off = ((size_t)(b * Hh + h) * Tt + t) * HD + d;
                    float2 vv = {v0 * sc, v1 * sc};
                    *reinterpret_cast<__half2*>(dst + off) = __float22half2_rn(vv);
                }
            }
        }
    }
}

// ---------------------------------------------------------------------------
// Flash attention: Q,K,V,P all single fp16 (1 mma/k16 in QK and PV).
// smem: Q 16KB @0; 2 KV stages of 16KB @16384. 2 CTAs/SM.
// Epilogue writes single fp16 AO.
// ---------------------------------------------------------------------------
__global__ __launch_bounds__(256, 2)
void attn_mma(const float* __restrict__ rpb)
{
    extern __shared__ __align__(16) char sm[];
    const int tid = threadIdx.x;
    const int lane = tid & 31;
    const int w = tid >> 5;
    const int b = blockIdx.x;
    const int h = blockIdx.y >> 3;
    const int t0 = (blockIdx.y & 7) * 128;
    const int bh = b * Hh + h;

    const uint32_t uQ = smem_u32(sm);
    const uint32_t uS0 = uQ + 16384;

    {
#pragma unroll
        for (int p = 0; p < 4; ++p) {
            int i = tid + p * 256;
            int row = i >> 3, cc = i & 7;
            const __half* src = g_Q + ((size_t)bh * Tt + t0 + row) * HD + cc * 8;
            uint32_t dst = uQ + row * 128 + (((cc ^ (row & 7))) << 4);
            CPASYNC16(dst, src);
        }
    }
    const __half* kvsrc[2] = { g_K, g_V };
#define LOAD_CHUNK(CIDX, ST)                                                   \
    {                                                                          \
        const uint32_t base_ = uS0 + (uint32_t)(ST) * 16384;                   \
        int s0_ = (CIDX) * 64;                                                 \
        _Pragma("unroll")                                                      \
        for (int p = 0; p < 4; ++p) {                                          \
            int i = tid + p * 256;                                             \
            int tile = i >> 9;                                                 \
            int rem = i & 511;                                                 \
            int row = rem >> 3, cc = rem & 7;                                  \
            const __half* src = kvsrc[tile]                                    \
                + ((size_t)bh * Tt + s0_ + row) * HD + cc * 8;                 \
            uint32_t dst = base_ + tile * 8192 + row * 128                     \
                         + (((cc ^ (row & 7))) << 4);                          \
            CPASYNC16(dst, src);                                               \
        }                                                                      \
    }

    LOAD_CHUNK(0, 0);
    asm volatile("cp.async.commit_group;" ::: "memory");
    LOAD_CHUNK(1, 1);
    asm volatile("cp.async.commit_group;" ::: "memory");

    float o[8][4];
#pragma unroll
    for (int j = 0; j < 8; ++j)
#pragma unroll
        for (int v = 0; v < 4; ++v) o[j][v] = 0.f;
    float m0r = -1e30f, m1r = -1e30f, l0r = 0.f, l1r = 0.f;

    const int rq = lane >> 2;
    const int cq = (lane & 3) * 2;
    const size_t brow0_base = ((size_t)h * Tt + (t0 + w * 16 + rq)) * Tt;
    const size_t brow1_base = brow0_base + 8 * (size_t)Tt;

    const int qrow = w * 16 + (lane & 15);
    const uint32_t qrb = uQ + qrow * 128;
    const uint32_t qsel = (uint32_t)(lane >> 4);

    for (int c = 0; c < 16; ++c) {
        if (c == 15) asm volatile("cp.async.wait_group 0;" ::: "memory");
        else         asm volatile("cp.async.wait_group 1;" ::: "memory");
        __syncthreads();

        const uint32_t stb = uS0 + (uint32_t)(c & 1) * 16384;
        const int g = lane >> 3, i = lane & 7;

        float s[8][4];
#pragma unroll
        for (int j = 0; j < 8; ++j)
#pragma unroll
            for (int v = 0; v < 4; ++v) s[j][v] = 0.f;

#pragma unroll
        for (int kk = 0; kk < 4; ++kk) {
            uint32_t qh[4];
            {
                uint32_t ccol = 2u * kk + qsel;
                uint32_t off = ((ccol ^ (qrow & 7)) << 4);
                LDSM4(qh, qrb + off);
            }
            uint32_t kb[8][2];
            const int brow_off = i + ((g >> 1) << 3);
            const int bkc = kk * 2 + (g & 1);
#pragma unroll
            for (int ng = 0; ng < 4; ++ng) {
                int row = ng * 16 + brow_off;
                uint32_t off = (uint32_t)(row * 128 + ((bkc ^ (row & 7)) << 4));
                uint32_t r4[4];
                LDSM4(r4, stb + off);
                kb[ng * 2][0] = r4[0]; kb[ng * 2][1] = r4[1];
                kb[ng * 2 + 1][0] = r4[2]; kb[ng * 2 + 1][1] = r4[3];
            }
#pragma unroll
            for (int nt = 0; nt < 8; ++nt)
                MMAF16(s[nt], qh, kb[nt]);
        }

        {
            const float* bp0 = rpb + brow0_base + c * 64 + cq;
            const float* bp1 = rpb + brow1_base + c * 64 + cq;
#pragma unroll
            for (int j = 0; j < 8; ++j) {
                float2 b0 = *reinterpret_cast<const float2*>(bp0 + j * 8);
                float2 b1 = *reinterpret_cast<const float2*>(bp1 + j * 8);
                s[j][0] += b0.x; s[j][1] += b0.y;
                s[j][2] += b1.x; s[j][3] += b1.y;
            }
        }

        float cm0 = -1e30f, cm1 = -1e30f;
#pragma unroll
        for (int j = 0; j < 8; ++j) {
            cm0 = fmaxf(cm0, fmaxf(s[j][0], s[j][1]));
            cm1 = fmaxf(cm1, fmaxf(s[j][2], s[j][3]));
        }
        cm0 = fmaxf(cm0, __shfl_xor_sync(0xffffffffu, cm0, 1));
        cm0 = fmaxf(cm0, __shfl_xor_sync(0xffffffffu, cm0, 2));
        cm1 = fmaxf(cm1, __shfl_xor_sync(0xffffffffu, cm1, 1));
        cm1 = fmaxf(cm1, __shfl_xor_sync(0xffffffffu, cm1, 2));
        float m0n = fmaxf(m0r, cm0), m1n = fmaxf(m1r, cm1);
        float cor0 = __expf(m0r - m0n), cor1 = __expf(m1r - m1n);
        m0r = m0n; m1r = m1n;
        float rs0 = 0.f, rs1 = 0.f;
#pragma unroll
        for (int j = 0; j < 8; ++j) {
            s[j][0] = __expf(s[j][0] - m0n);
            s[j][1] = __expf(s[j][1] - m0n);
            s[j][2] = __expf(s[j][2] - m1n);
            s[j][3] = __expf(s[j][3] - m1n);
            rs0 += s[j][0] + s[j][1];
            rs1 += s[j][2] + s[j][3];
        }
        rs0 += __shfl_xor_sync(0xffffffffu, rs0, 1);
        rs0 += __shfl_xor_sync(0xffffffffu, rs0, 2);
        rs1 += __shfl_xor_sync(0xffffffffu, rs1, 1);
        rs1 += __shfl_xor_sync(0xffffffffu, rs1, 2);
        l0r = l0r * cor0 + rs0;
        l1r = l1r * cor1 + rs1;
#pragma unroll
        for (int j = 0; j < 8; ++j) {
            o[j][0] *= cor0; o[j][1] *= cor0;
            o[j][2] *= cor1; o[j][3] *= cor1;
        }

        uint32_t ph[8][2];
#pragma unroll
        for (int j = 0; j < 8; ++j) {
            float2 v0 = {s[j][0], s[j][1]};
            __half2 hh0 = __float22half2_rn(v0);
            ph[j][0] = *reinterpret_cast<uint32_t*>(&hh0);
            float2 v1 = {s[j][2], s[j][3]};
            __half2 hh1 = __float22half2_rn(v1);
            ph[j][1] = *reinterpret_cast<uint32_t*>(&hh1);
        }

#pragma unroll
        for (int kk = 0; kk < 4; ++kk) {
            uint32_t a_h[4] = { ph[2*kk][0], ph[2*kk][1], ph[2*kk+1][0], ph[2*kk+1][1] };
            uint32_t vb[8][2];
            const int srow = kk * 16 + i + ((g >> 1) << 3);
#pragma unroll
            for (int dg = 0; dg < 4; ++dg) {
                int ck = dg * 2 + (g & 1);
                uint32_t off = (uint32_t)(srow * 128 + ((ck ^ (srow & 7)) << 4));
                uint32_t r4[4];
                LDSM4T(r4, stb + 8192 + off);
                vb[dg * 2][0] = r4[0]; vb[dg * 2][1] = r4[2];
                vb[dg * 2 + 1][0] = r4[1]; vb[dg * 2 + 1][1] = r4[3];
            }
#pragma unroll
            for (int dt = 0; dt < 8; ++dt)
                MMAF16(o[dt], a_h, vb[dt]);
        }

        __syncthreads();
        if (c + 2 < 16) {
            LOAD_CHUNK(c + 2, c & 1);
            asm volatile("cp.async.commit_group;" ::: "memory");
        }
    }

    float inv0 = 1.f / l0r, inv1 = 1.f / l1r;
    int t_row0 = t0 + w * 16 + rq;
    int t_row1 = t_row0 + 8;
#pragma unroll
    for (int j = 0; j < 8; ++j) {
        int d = j * 8 + cq;
        size_t i0 = ((size_t)t_row0 * Bb + b) * Ee + h * HD + d;
        size_t i1 = ((size_t)t_row1 * Bb + b) * Ee + h * HD + d;
        float2 v0 = {o[j][0] * inv0, o[j][1] * inv0};
        float2 v1 = {o[j][2] * inv1, o[j][3] * inv1};
        *reinterpret_cast<__half2*>(g_AOh + i0) = __float22half2_rn(v0);
        *reinterpret_cast<__half2*>(g_AOh + i1) = __float22half2_rn(v1);
    }
#undef LOAD_CHUNK
}

// ---------------------------------------------------------------------------
extern "C" void kernel_launch(void* const* d_in, const int* in_sizes, int n_in,
                              void* d_out, int out_size)
{
    const float* query = (const float*)d_in[0];
    const float* ipw   = (const float*)d_in[1];
    const float* ipb   = (const float*)d_in[2];
    const float* il    = (const float*)d_in[3];
    const float* ir    = (const float*)d_in[4];
    const float* opw   = (const float*)d_in[5];
    const float* opb   = (const float*)d_in[6];
    const float* ol    = (const float*)d_in[7];
    const float* orr   = (const float*)d_in[8];
    const float* rpb   = (const float*)d_in[9];
    float* out = (float*)d_out;

    static bool attr_set = false;
    if (!attr_set) {
        cudaFuncSetAttribute((const void*)gemm_mma<0>,
            cudaFuncAttributeMaxDynamicSharedMemorySize, 98304);
        cudaFuncSetAttribute((const void*)gemm_mma<1>,
            cudaFuncAttributeMaxDynamicSharedMemorySize, 98304);
        cudaFuncSetAttribute((const void*)attn_mma,
            cudaFuncAttributeMaxDynamicSharedMemorySize, 49152);
        attr_set = true;
    }

    weff_kernel<0><<<(F3 * Ee + 255) / 256, 256>>>(ipw, il, ir);
    weff_kernel<1><<<(Ee * Ee + 255) / 256, 256>>>(opw, ol, orr);
    qsplit_kernel<<<Nrows * Ee / 1024, 256>>>(query);

    gemm_mma<0><<<dim3(F3 / BN, Nrows / BM), 256, 98304>>>(ipb, nullptr, F3, Ee);

    attn_mma<<<dim3(Bb, Hh * 8), 256, 49152>>>(rpb);

    gemm_mma<1><<<dim3(Ee / BN, Nrows / BM), 256, 98304>>>(opb, out, Ee, Ee);
}

// round 16
// speedup vs baseline: 4.3301x; 1.0113x over previous
#include <cuda_runtime.h>
#include <cuda_fp16.h>
#include <cstdint>

// ---------------------------------------------------------------------------
// MultiheadAttention with low-rank-augmented in/out projections.
// T=1024, B=8, E=1024, H=16, R=16, HD=64.
//
// R16: overhead trims only (precision unchanged from R15):
//  - GEMM cp.async/LDSM addresses strength-reduced (hoisted per-thread
//    offsets; per chunk one IMAD each)
//  - attention uses 3 KV stages -> one barrier per chunk instead of two
//  - weff_in/weff_out/qsplit fused into a single prologue launch
// ---------------------------------------------------------------------------

namespace {
constexpr int Tt = 1024;
constexpr int Bb = 8;
constexpr int Ee = 1024;
constexpr int Hh = 16;
constexpr int Rr = 16;
constexpr int HD = 64;
constexpr int F3 = 3 * Ee;          // 3072
constexpr int Nrows = Tt * Bb;      // 8192
constexpr int BM = 128, BN = 64;
constexpr int STAGE64 = 24576;      // A 16K, W 8K
// fused prologue block ranges (256 threads each)
constexpr int PB_WIN  = (F3 * Ee) / 256;          // 12288
constexpr int PB_WOUT = PB_WIN + (Ee * Ee) / 256; // 16384
constexpr int PB_QS   = PB_WOUT + (Nrows * Ee) / 1024; // +8192 = 24576
}

// Scratch (device globals; no runtime allocation).
__device__ __align__(16) __half g_Win_h[F3 * Ee];
__device__ __align__(16) __half g_Wout_h[Ee * Ee];
__device__ __align__(16) __half g_Ah[Nrows * Ee];
__device__ __align__(16) __half g_AOh[Nrows * Ee];
__device__ __align__(16) __half g_Q[Bb * Hh * Tt * HD];
__device__ __align__(16) __half g_K[Bb * Hh * Tt * HD];
__device__ __align__(16) __half g_V[Bb * Hh * Tt * HD];

// ---------------------------------------------------------------------------
__device__ __forceinline__ uint32_t smem_u32(const void* p) {
    uint32_t a;
    asm("{ .reg .u64 t; cvta.to.shared.u64 t, %1; cvt.u32.u64 %0, t; }"
        : "=r"(a) : "l"(p));
    return a;
}

#define LDSM4(R, A)                                                           \
    asm volatile("ldmatrix.sync.aligned.m8n8.x4.shared.b16 {%0,%1,%2,%3}, [%4];" \
                 : "=r"((R)[0]), "=r"((R)[1]), "=r"((R)[2]), "=r"((R)[3])     \
                 : "r"(A))

#define LDSM4T(R, A)                                                          \
    asm volatile("ldmatrix.sync.aligned.m8n8.x4.trans.shared.b16 {%0,%1,%2,%3}, [%4];" \
                 : "=r"((R)[0]), "=r"((R)[1]), "=r"((R)[2]), "=r"((R)[3])     \
                 : "r"(A))

#define MMAF16(C, A, B)                                                       \
    asm volatile("mma.sync.aligned.m16n8k16.row.col.f32.f16.f16.f32 "         \
                 "{%0,%1,%2,%3}, {%4,%5,%6,%7}, {%8,%9}, {%0,%1,%2,%3};"      \
                 : "+f"((C)[0]), "+f"((C)[1]), "+f"((C)[2]), "+f"((C)[3])     \
                 : "r"((A)[0]), "r"((A)[1]), "r"((A)[2]), "r"((A)[3]),        \
                   "r"((B)[0]), "r"((B)[1]))

#define CPASYNC16(D, S)                                                       \
    asm volatile("cp.async.cg.shared.global [%0], [%1], 16;"                  \
                 :: "r"(D), "l"(S))

// ---------------------------------------------------------------------------
// Fused prologue: W_eff (in+out) -> fp16, query -> fp16.
// ---------------------------------------------------------------------------
__global__ __launch_bounds__(256)
void prologue_kernel(const float* __restrict__ Win,
                     const float* __restrict__ Lin,
                     const float* __restrict__ Rin,
                     const float* __restrict__ Wout,
                     const float* __restrict__ Lout,
                     const float* __restrict__ Rout,
                     const float* __restrict__ query)
{
    const int bid = blockIdx.x;
    if (bid < PB_WOUT) {
        const float* W = (bid < PB_WIN) ? Win : Wout;
        const float* L = (bid < PB_WIN) ? Lin : Lout;
        const float* Rm = (bid < PB_WIN) ? Rin : Rout;
        __half* oh = (bid < PB_WIN) ? g_Win_h : g_Wout_h;
        int base = (bid < PB_WIN) ? bid : bid - PB_WIN;
        int idx = base * 256 + threadIdx.x;
        int f = idx >> 10;
        int e = idx & 1023;
        float s = W[idx];
#pragma unroll
        for (int r = 0; r < Rr; ++r)
            s = fmaf(L[f * Rr + r], Rm[r * Ee + e], s);
        oh[idx] = __float2half(s);
    } else {
        int idx = ((bid - PB_WOUT) * 256 + threadIdx.x) * 4;
        float4 v = *reinterpret_cast<const float4*>(query + idx);
        __half2* ph = reinterpret_cast<__half2*>(g_Ah + idx);
        float2 v01 = {v.x, v.y}, v23 = {v.z, v.w};
        ph[0] = __float22half2_rn(v01);
        ph[1] = __float22half2_rn(v23);
    }
}

// ---------------------------------------------------------------------------
// Unified single-A fp16 GEMM, BK=64 chunks, strength-reduced addressing.
// Tile 128x64x64, 8 warps (4x2), 4-stage cp.async (96KB), 2 CTAs/SM.
// MODE 0: A=g_Ah, W=g_Win_h -> scatter Q/K/V single fp16 (q *0.125)
// MODE 1: A=g_AOh, W=g_Wout_h -> out fp32 + bias
// ---------------------------------------------------------------------------
template <int MODE>
__global__ __launch_bounds__(256, 2)
void gemm_mma(const float* __restrict__ bias, float* __restrict__ out,
              int N, int K)
{
    extern __shared__ __align__(16) char sm[];
    const __half* Ag = (MODE == 0) ? g_Ah : g_AOh;
    const __half* Bg = (MODE == 0) ? g_Win_h : g_Wout_h;

    const int tid  = threadIdx.x;
    const int lane = tid & 31;
    const int wid  = tid >> 5;
    const int wm   = wid >> 1;
    const int wn   = wid & 1;
    const int m0 = blockIdx.y * BM;
    const int n0 = blockIdx.x * BN;

    const uint32_t smb = smem_u32(sm);

    // ---- hoisted cp.async geometry: 4 A lines + 2 B lines per thread
    const __half* gsrc[6];
    uint32_t sdst[6];
#pragma unroll
    for (int p = 0; p < 4; ++p) {
        int idx = tid + p * 256;
        int row = idx >> 3, c8 = idx & 7;
        sdst[p] = (uint32_t)(row * 128 + ((c8 ^ (row & 7)) << 4));
        gsrc[p] = Ag + (size_t)(m0 + row) * K + c8 * 8;
    }
#pragma unroll
    for (int p = 0; p < 2; ++p) {
        int idx = tid + p * 256;
        int row = idx >> 3, c8 = idx & 7;
        sdst[4 + p] = 16384u + (uint32_t)(row * 128 + ((c8 ^ (row & 7)) << 4));
        gsrc[4 + p] = Bg + (size_t)(n0 + row) * K + c8 * 8;
    }

    float acc[2][4][4];
#pragma unroll
    for (int a = 0; a < 2; ++a)
#pragma unroll
        for (int b = 0; b < 4; ++b)
#pragma unroll
            for (int c = 0; c < 4; ++c) acc[a][b][c] = 0.f;

    const int nchunk = K / 64;      // 16

#define ISSUE64(CIDX)                                                         \
    {                                                                         \
        uint32_t base_ = smb + (uint32_t)((CIDX) & 3) * STAGE64;              \
        _Pragma("unroll")                                                     \
        for (int p = 0; p < 6; ++p)                                           \
            CPASYNC16(base_ + sdst[p], gsrc[p] + (CIDX) * 64);                \
        asm volatile("cp.async.commit_group;" ::: "memory");                  \
    }

    ISSUE64(0);
    ISSUE64(1);
    ISSUE64(2);

    // ---- hoisted LDSM offsets (chunk-invariant)
    const int g = lane >> 3, i = lane & 7;
    uint32_t aoff[4][2], boff[4][2];
#pragma unroll
    for (int ks = 0; ks < 4; ++ks) {
        const int akc = ks * 2 + (g >> 1);
        const int arow_off = i + ((g & 1) << 3);
#pragma unroll
        for (int mt = 0; mt < 2; ++mt) {
            int row = wm * 32 + mt * 16 + arow_off;
            aoff[ks][mt] = (uint32_t)(row * 128 + ((akc ^ (row & 7)) << 4));
        }
        const int bkc = ks * 2 + (g & 1);
        const int brow_off = i + ((g >> 1) << 3);
#pragma unroll
        for (int np = 0; np < 2; ++np) {
            int row = wn * 32 + np * 16 + brow_off;
            boff[ks][np] = 16384u + (uint32_t)(row * 128 + ((bkc ^ (row & 7)) << 4));
        }
    }

    for (int c = 0; c < nchunk; ++c) {
        asm volatile("cp.async.wait_group 2;" ::: "memory");
        __syncthreads();

        if (c + 3 < nchunk) ISSUE64(c + 3);

        {
            uint32_t stb = smb + (uint32_t)(c & 3) * STAGE64;
#pragma unroll
            for (int ks = 0; ks < 4; ++ks) {
                uint32_t ah[2][4];
#pragma unroll
                for (int mt = 0; mt < 2; ++mt)
                    LDSM4(ah[mt], stb + aoff[ks][mt]);
                uint32_t bh[4][2];
#pragma unroll
                for (int np = 0; np < 2; ++np) {
                    uint32_t r4[4];
                    LDSM4(r4, stb + boff[ks][np]);
                    bh[np * 2][0] = r4[0]; bh[np * 2][1] = r4[1];
                    bh[np * 2 + 1][0] = r4[2]; bh[np * 2 + 1][1] = r4[3];
                }
#pragma unroll
                for (int mt = 0; mt < 2; ++mt)
#pragma unroll
                    for (int nb = 0; nb < 4; ++nb)
                        MMAF16(acc[mt][nb], ah[mt], bh[nb]);
            }
        }
    }
#undef ISSUE64

    __syncthreads();

    const int r = lane >> 2, tg = lane & 3;
#pragma unroll
    for (int mt = 0; mt < 2; ++mt) {
#pragma unroll
        for (int nb = 0; nb < 4; ++nb) {
            int m = m0 + wm * 32 + mt * 16 + r;
            int n = n0 + wn * 32 + nb * 8 + tg * 2;
            float2 bb = *reinterpret_cast<const float2*>(bias + n);
#pragma unroll
            for (int half = 0; half < 2; ++half) {
                int mm = m + half * 8;
                float v0 = acc[mt][nb][half * 2 + 0] + bb.x;
                float v1 = acc[mt][nb][half * 2 + 1] + bb.y;
                if (MODE == 1) {
                    float2 vv = {v0, v1};
                    *reinterpret_cast<float2*>(out + (size_t)mm * N + n) = vv;
                } else {
                    int t = mm >> 3;
                    int b = mm & 7;
                    int which = n >> 10;
                    int h = (n >> 6) & 15;
                    int d = n & 63;
                    float sc = (which == 0) ? 0.125f : 1.0f;
                    __half* dst = (which == 0) ? g_Q : (which == 1) ? g_K : g_V;
                    size_t off = ((size_t)(b * Hh + h) * Tt + t) * HD + d;
                    float2 vv = {v0 * sc, v1 * sc};
                    *reinterpret_cast<__half2*>(dst + off) = __float22half2_rn(vv);
                }
            }
        }
    }
}

// ---------------------------------------------------------------------------
// Flash attention: Q,K,V,P single fp16. 3 KV stages -> 1 barrier per chunk.
// smem: Q 16KB @0; 3 KV stages of 16KB @16384 (64KB total). 2 CTAs/SM.
// ---------------------------------------------------------------------------
__global__ __launch_bounds__(256, 2)
void attn_mma(const float* __restrict__ rpb)
{
    extern __shared__ __align__(16) char sm[];
    const int tid = threadIdx.x;
    const int lane = tid & 31;
    const int w = tid >> 5;
    const int b = blockIdx.x;
    const int h = blockIdx.y >> 3;
    const int t0 = (blockIdx.y & 7) * 128;
    const int bh = b * Hh + h;

    const uint32_t uQ = smem_u32(sm);
    const uint32_t uS0 = uQ + 16384;

    {
#pragma unroll
        for (int p = 0; p < 4; ++p) {
            int i = tid + p * 256;
            int row = i >> 3, cc = i & 7;
            const __half* src = g_Q + ((size_t)bh * Tt + t0 + row) * HD + cc * 8;
            uint32_t dst = uQ + row * 128 + (((cc ^ (row & 7))) << 4);
            CPASYNC16(dst, src);
        }
    }
    const __half* kvsrc[2] = { g_K, g_V };
#define LOAD_CHUNK(CIDX, ST)                                                   \
    {                                                                          \
        const uint32_t base_ = uS0 + (uint32_t)(ST) * 16384;                   \
        int s0_ = (CIDX) * 64;                                                 \
        _Pragma("unroll")                                                      \
        for (int p = 0; p < 4; ++p) {                                          \
            int i = tid + p * 256;                                             \
            int tile = i >> 9;                                                 \
            int rem = i & 511;                                                 \
            int row = rem >> 3, cc = rem & 7;                                  \
            const __half* src = kvsrc[tile]                                    \
                + ((size_t)bh * Tt + s0_ + row) * HD + cc * 8;                 \
            uint32_t dst = base_ + tile * 8192 + row * 128                     \
                         + (((cc ^ (row & 7))) << 4);                          \
            CPASYNC16(dst, src);                                               \
        }                                                                      \
    }

    LOAD_CHUNK(0, 0);
    asm volatile("cp.async.commit_group;" ::: "memory");
    LOAD_CHUNK(1, 1);
    asm volatile("cp.async.commit_group;" ::: "memory");

    float o[8][4];
#pragma unroll
    for (int j = 0; j < 8; ++j)
#pragma unroll
        for (int v = 0; v < 4; ++v) o[j][v] = 0.f;
    float m0r = -1e30f, m1r = -1e30f, l0r = 0.f, l1r = 0.f;

    const int rq = lane >> 2;
    const int cq = (lane & 3) * 2;
    const size_t brow0_base = ((size_t)h * Tt + (t0 + w * 16 + rq)) * Tt;
    const size_t brow1_base = brow0_base + 8 * (size_t)Tt;

    const int qrow = w * 16 + (lane & 15);
    const uint32_t qrb = uQ + qrow * 128;
    const uint32_t qsel = (uint32_t)(lane >> 4);

    int st = 0;                      // stage of chunk c (mod 3)
    for (int c = 0; c < 16; ++c) {
        if (c == 15) asm volatile("cp.async.wait_group 0;" ::: "memory");
        else         asm volatile("cp.async.wait_group 1;" ::: "memory");
        __syncthreads();

        const uint32_t stb = uS0 + (uint32_t)st * 16384;
        const int g = lane >> 3, i = lane & 7;

        float s[8][4];
#pragma unroll
        for (int j = 0; j < 8; ++j)
#pragma unroll
            for (int v = 0; v < 4; ++v) s[j][v] = 0.f;

#pragma unroll
        for (int kk = 0; kk < 4; ++kk) {
            uint32_t qh[4];
            {
                uint32_t ccol = 2u * kk + qsel;
                uint32_t off = ((ccol ^ (qrow & 7)) << 4);
                LDSM4(qh, qrb + off);
            }
            uint32_t kb[8][2];
            const int brow_off = i + ((g >> 1) << 3);
            const int bkc = kk * 2 + (g & 1);
#pragma unroll
            for (int ng = 0; ng < 4; ++ng) {
                int row = ng * 16 + brow_off;
                uint32_t off = (uint32_t)(row * 128 + ((bkc ^ (row & 7)) << 4));
                uint32_t r4[4];
                LDSM4(r4, stb + off);
                kb[ng * 2][0] = r4[0]; kb[ng * 2][1] = r4[1];
                kb[ng * 2 + 1][0] = r4[2]; kb[ng * 2 + 1][1] = r4[3];
            }
#pragma unroll
            for (int nt = 0; nt < 8; ++nt)
                MMAF16(s[nt], qh, kb[nt]);
        }

        {
            const float* bp0 = rpb + brow0_base + c * 64 + cq;
            const float* bp1 = rpb + brow1_base + c * 64 + cq;
#pragma unroll
            for (int j = 0; j < 8; ++j) {
                float2 b0 = *reinterpret_cast<const float2*>(bp0 + j * 8);
                float2 b1 = *reinterpret_cast<const float2*>(bp1 + j * 8);
                s[j][0] += b0.x; s[j][1] += b0.y;
                s[j][2] += b1.x; s[j][3] += b1.y;
            }
        }

        float cm0 = -1e30f, cm1 = -1e30f;
#pragma unroll
        for (int j = 0; j < 8; ++j) {
            cm0 = fmaxf(cm0, fmaxf(s[j][0], s[j][1]));
            cm1 = fmaxf(cm1, fmaxf(s[j][2], s[j][3]));
        }
        cm0 = fmaxf(cm0, __shfl_xor_sync(0xffffffffu, cm0, 1));
        cm0 = fmaxf(cm0, __shfl_xor_sync(0xffffffffu, cm0, 2));
        cm1 = fmaxf(cm1, __shfl_xor_sync(0xffffffffu, cm1, 1));
        cm1 = fmaxf(cm1, __shfl_xor_sync(0xffffffffu, cm1, 2));
        float m0n = fmaxf(m0r, cm0), m1n = fmaxf(m1r, cm1);
        float cor0 = __expf(m0r - m0n), cor1 = __expf(m1r - m1n);
        m0r = m0n; m1r = m1n;
        float rs0 = 0.f, rs1 = 0.f;
#pragma unroll
        for (int j = 0; j < 8; ++j) {
            s[j][0] = __expf(s[j][0] - m0n);
            s[j][1] = __expf(s[j][1] - m0n);
            s[j][2] = __expf(s[j][2] - m1n);
            s[j][3] = __expf(s[j][3] - m1n);
            rs0 += s[j][0] + s[j][1];
            rs1 += s[j][2] + s[j][3];
        }
        rs0 += __shfl_xor_sync(0xffffffffu, rs0, 1);
        rs0 += __shfl_xor_sync(0xffffffffu, rs0, 2);
        rs1 += __shfl_xor_sync(0xffffffffu, rs1, 1);
        rs1 += __shfl_xor_sync(0xffffffffu, rs1, 2);
        l0r = l0r * cor0 + rs0;
        l1r = l1r * cor1 + rs1;
#pragma unroll
        for (int j = 0; j < 8; ++j) {
            o[j][0] *= cor0; o[j][1] *= cor0;
            o[j][2] *= cor1; o[j][3] *= cor1;
        }

        uint32_t ph[8][2];
#pragma unroll
        for (int j = 0; j < 8; ++j) {
            float2 v0 = {s[j][0], s[j][1]};
            __half2 hh0 = __float22half2_rn(v0);
            ph[j][0] = *reinterpret_cast<uint32_t*>(&hh0);
            float2 v1 = {s[j][2], s[j][3]};
            __half2 hh1 = __float22half2_rn(v1);
            ph[j][1] = *reinterpret_cast<uint32_t*>(&hh1);
        }

#pragma unroll
        for (int kk = 0; kk < 4; ++kk) {
            uint32_t a_h[4] = { ph[2*kk][0], ph[2*kk][1], ph[2*kk+1][0], ph[2*kk+1][1] };
            uint32_t vb[8][2];
            const int srow = kk * 16 + i + ((g >> 1) << 3);
#pragma unroll
            for (int dg = 0; dg < 4; ++dg) {
                int ck = dg * 2 + (g & 1);
                uint32_t off = (uint32_t)(srow * 128 + ((ck ^ (srow & 7)) << 4));
                uint32_t r4[4];
                LDSM4T(r4, stb + 8192 + off);
                vb[dg * 2][0] = r4[0]; vb[dg * 2][1] = r4[2];
                vb[dg * 2 + 1][0] = r4[1]; vb[dg * 2 + 1][1] = r4[3];
            }
#pragma unroll
            for (int dt = 0; dt < 8; ++dt)
                MMAF16(o[dt], a_h, vb[dt]);
        }

        // issue chunk c+2 into stage (c+2)%3 — safe with the single top
        // barrier: that stage was last read at chunk c-1, and every thread
        // passed this chunk's barrier since then.
        if (c + 2 < 16) {
            int st2 = st + 2;
            if (st2 >= 3) st2 -= 3;
            LOAD_CHUNK(c + 2, st2);
            asm volatile("cp.async.commit_group;" ::: "memory");
        }
        if (++st == 3) st = 0;
    }

    float inv0 = 1.f / l0r, inv1 = 1.f / l1r;
    int t_row0 = t0 + w * 16 + rq;
    int t_row1 = t_row0 + 8;
#pragma unroll
    for (int j = 0; j < 8; ++j) {
        int d = j * 8 + cq;
        size_t i0 = ((size_t)t_row0 * Bb + b) * Ee + h * HD + d;
        size_t i1 = ((size_t)t_row1 * Bb + b) * Ee + h * HD + d;
        float2 v0 = {o[j][0] * inv0, o[j][1] * inv0};
        float2 v1 = {o[j][2] * inv1, o[j][3] * inv1};
        *reinterpret_cast<__half2*>(g_AOh + i0) = __float22half2_rn(v0);
        *reinterpret_cast<__half2*>(g_AOh + i1) = __float22half2_rn(v1);
    }
#undef LOAD_CHUNK
}

// ---------------------------------------------------------------------------
extern "C" void kernel_launch(void* const* d_in, const int* in_sizes, int n_in,
                              void* d_out, int out_size)
{
    const float* query = (const float*)d_in[0];
    const float* ipw   = (const float*)d_in[1];
    const float* ipb   = (const float*)d_in[2];
    const float* il    = (const float*)d_in[3];
    const float* ir    = (const float*)d_in[4];
    const float* opw   = (const float*)d_in[5];
    const float* opb   = (const float*)d_in[6];
    const float* ol    = (const float*)d_in[7];
    const float* orr   = (const float*)d_in[8];
    const float* rpb   = (const float*)d_in[9];
    float* out = (float*)d_out;

    static bool attr_set = false;
    if (!attr_set) {
        cudaFuncSetAttribute((const void*)gemm_mma<0>,
            cudaFuncAttributeMaxDynamicSharedMemorySize, 98304);
        cudaFuncSetAttribute((const void*)gemm_mma<1>,
            cudaFuncAttributeMaxDynamicSharedMemorySize, 98304);
        cudaFuncSetAttribute((const void*)attn_mma,
            cudaFuncAttributeMaxDynamicSharedMemorySize, 65536);
        attr_set = true;
    }

    prologue_kernel<<<PB_QS, 256>>>(ipw, il, ir, opw, ol, orr, query);

    gemm_mma<0><<<dim3(F3 / BN, Nrows / BM), 256, 98304>>>(ipb, nullptr, F3, Ee);

    attn_mma<<<dim3(Bb, Hh * 8), 256, 65536>>>(rpb);

    gemm_mma<1><<<dim3(Ee / BN, Nrows / BM), 256, 98304>>>(opb, out, Ee, Ee);
}

// round 17
// speedup vs baseline: 4.6403x; 1.0716x over previous
#include <cuda_runtime.h>
#include <cuda_fp16.h>
#include <cstdint>

// ---------------------------------------------------------------------------
// MultiheadAttention with low-rank-augmented in/out projections.
// T=1024, B=8, E=1024, H=16, R=16, HD=64.
//
// R17: GEMM tile widened to 128x128x64 (3 stages, 96KB, still 2 CTAs/SM) --
//      doubles mma:ldsm and halves A L2 traffic. Attention softmax moved to
//      exp2 (log2e folded into q-scale and bias FFMA). Precision unchanged.
// ---------------------------------------------------------------------------

namespace {
constexpr int Tt = 1024;
constexpr int Bb = 8;
constexpr int Ee = 1024;
constexpr int Hh = 16;
constexpr int Rr = 16;
constexpr int HD = 64;
constexpr int F3 = 3 * Ee;          // 3072
constexpr int Nrows = Tt * Bb;      // 8192
constexpr int BM = 128, BN = 128;
constexpr int STAGE = 32768;        // A 16K + B 16K
constexpr float LOG2E = 1.4426950408889634f;
// fused prologue block ranges (256 threads each)
constexpr int PB_WIN  = (F3 * Ee) / 256;          // 12288
constexpr int PB_WOUT = PB_WIN + (Ee * Ee) / 256; // 16384
constexpr int PB_QS   = PB_WOUT + (Nrows * Ee) / 1024; // 24576
}

// Scratch (device globals; no runtime allocation).
__device__ __align__(16) __half g_Win_h[F3 * Ee];
__device__ __align__(16) __half g_Wout_h[Ee * Ee];
__device__ __align__(16) __half g_Ah[Nrows * Ee];
__device__ __align__(16) __half g_AOh[Nrows * Ee];
__device__ __align__(16) __half g_Q[Bb * Hh * Tt * HD];
__device__ __align__(16) __half g_K[Bb * Hh * Tt * HD];
__device__ __align__(16) __half g_V[Bb * Hh * Tt * HD];

// ---------------------------------------------------------------------------
__device__ __forceinline__ uint32_t smem_u32(const void* p) {
    uint32_t a;
    asm("{ .reg .u64 t; cvta.to.shared.u64 t, %1; cvt.u32.u64 %0, t; }"
        : "=r"(a) : "l"(p));
    return a;
}

#define LDSM4(R, A)                                                           \
    asm volatile("ldmatrix.sync.aligned.m8n8.x4.shared.b16 {%0,%1,%2,%3}, [%4];" \
                 : "=r"((R)[0]), "=r"((R)[1]), "=r"((R)[2]), "=r"((R)[3])     \
                 : "r"(A))

#define LDSM4T(R, A)                                                          \
    asm volatile("ldmatrix.sync.aligned.m8n8.x4.trans.shared.b16 {%0,%1,%2,%3}, [%4];" \
                 : "=r"((R)[0]), "=r"((R)[1]), "=r"((R)[2]), "=r"((R)[3])     \
                 : "r"(A))

#define MMAF16(C, A, B)                                                       \
    asm volatile("mma.sync.aligned.m16n8k16.row.col.f32.f16.f16.f32 "         \
                 "{%0,%1,%2,%3}, {%4,%5,%6,%7}, {%8,%9}, {%0,%1,%2,%3};"      \
                 : "+f"((C)[0]), "+f"((C)[1]), "+f"((C)[2]), "+f"((C)[3])     \
                 : "r"((A)[0]), "r"((A)[1]), "r"((A)[2]), "r"((A)[3]),        \
                   "r"((B)[0]), "r"((B)[1]))

#define CPASYNC16(D, S)                                                       \
    asm volatile("cp.async.cg.shared.global [%0], [%1], 16;"                  \
                 :: "r"(D), "l"(S))

// ---------------------------------------------------------------------------
// Fused prologue: W_eff (in+out) -> fp16, query -> fp16.
// ---------------------------------------------------------------------------
__global__ __launch_bounds__(256)
void prologue_kernel(const float* __restrict__ Win,
                     const float* __restrict__ Lin,
                     const float* __restrict__ Rin,
                     const float* __restrict__ Wout,
                     const float* __restrict__ Lout,
                     const float* __restrict__ Rout,
                     const float* __restrict__ query)
{
    const int bid = blockIdx.x;
    if (bid < PB_WOUT) {
        const float* W = (bid < PB_WIN) ? Win : Wout;
        const float* L = (bid < PB_WIN) ? Lin : Lout;
        const float* Rm = (bid < PB_WIN) ? Rin : Rout;
        __half* oh = (bid < PB_WIN) ? g_Win_h : g_Wout_h;
        int base = (bid < PB_WIN) ? bid : bid - PB_WIN;
        int idx = base * 256 + threadIdx.x;
        int f = idx >> 10;
        int e = idx & 1023;
        float s = W[idx];
#pragma unroll
        for (int r = 0; r < Rr; ++r)
            s = fmaf(L[f * Rr + r], Rm[r * Ee + e], s);
        oh[idx] = __float2half(s);
    } else {
        int idx = ((bid - PB_WOUT) * 256 + threadIdx.x) * 4;
        float4 v = *reinterpret_cast<const float4*>(query + idx);
        __half2* ph = reinterpret_cast<__half2*>(g_Ah + idx);
        float2 v01 = {v.x, v.y}, v23 = {v.z, v.w};
        ph[0] = __float22half2_rn(v01);
        ph[1] = __float22half2_rn(v23);
    }
}

// ---------------------------------------------------------------------------
// Single-A fp16 GEMM, 128x128x64 tile, 8 warps (4x2, warp tile 32x64),
// 3-stage cp.async (96KB), 2 CTAs/SM.
// MODE 0: A=g_Ah, W=g_Win_h -> scatter Q/K/V fp16 (q *0.125*log2e)
// MODE 1: A=g_AOh, W=g_Wout_h -> out fp32 + bias
// ---------------------------------------------------------------------------
template <int MODE>
__global__ __launch_bounds__(256, 2)
void gemm_mma(const float* __restrict__ bias, float* __restrict__ out,
              int N, int K)
{
    extern __shared__ __align__(16) char sm[];
    const __half* Ag = (MODE == 0) ? g_Ah : g_AOh;
    const __half* Bg = (MODE == 0) ? g_Win_h : g_Wout_h;

    const int tid  = threadIdx.x;
    const int lane = tid & 31;
    const int wid  = tid >> 5;
    const int wm   = wid >> 1;        // 0..3 (32 rows)
    const int wn   = wid & 1;         // 0..1 (64 cols)
    const int m0 = blockIdx.y * BM;
    const int n0 = blockIdx.x * BN;

    const uint32_t smb = smem_u32(sm);

    // hoisted cp.async geometry: 4 A + 4 B lines per thread, u32 gmem offsets
    uint32_t goffA[4], goffB[4], sdstA[4], sdstB[4];
#pragma unroll
    for (int p = 0; p < 4; ++p) {
        int idx = tid + p * 256;
        int row = idx >> 3, c8 = idx & 7;
        uint32_t sw = (uint32_t)(row * 128 + ((c8 ^ (row & 7)) << 4));
        sdstA[p] = sw;
        sdstB[p] = 16384u + sw;
        goffA[p] = (uint32_t)(((m0 + row) * K + c8 * 8) * 2);
        goffB[p] = (uint32_t)(((n0 + row) * K + c8 * 8) * 2);
    }

    float acc[2][8][4];
#pragma unroll
    for (int a = 0; a < 2; ++a)
#pragma unroll
        for (int b = 0; b < 8; ++b)
#pragma unroll
            for (int c = 0; c < 4; ++c) acc[a][b][c] = 0.f;

    const int nchunk = K / 64;      // 16

#define ISSUE64(CIDX)                                                         \
    {                                                                         \
        uint32_t base_ = smb + (uint32_t)((CIDX) % 3) * STAGE;                \
        _Pragma("unroll")                                                     \
        for (int p = 0; p < 4; ++p) {                                         \
            CPASYNC16(base_ + sdstA[p],                                       \
                      (const char*)Ag + goffA[p] + (CIDX) * 128);             \
            CPASYNC16(base_ + sdstB[p],                                       \
                      (const char*)Bg + goffB[p] + (CIDX) * 128);             \
        }                                                                     \
        asm volatile("cp.async.commit_group;" ::: "memory");                  \
    }

    ISSUE64(0);
    ISSUE64(1);

    // hoisted LDSM offsets (chunk-invariant)
    const int g = lane >> 3, i = lane & 7;
    uint32_t aoff[4][2], boff[4][4];
#pragma unroll
    for (int ks = 0; ks < 4; ++ks) {
        const int akc = ks * 2 + (g >> 1);
        const int arow_off = i + ((g & 1) << 3);
#pragma unroll
        for (int mt = 0; mt < 2; ++mt) {
            int row = wm * 32 + mt * 16 + arow_off;
            aoff[ks][mt] = (uint32_t)(row * 128 + ((akc ^ (row & 7)) << 4));
        }
        const int bkc = ks * 2 + (g & 1);
        const int brow_off = i + ((g >> 1) << 3);
#pragma unroll
        for (int np = 0; np < 4; ++np) {
            int row = wn * 64 + np * 16 + brow_off;
            boff[ks][np] = 16384u + (uint32_t)(row * 128 + ((bkc ^ (row & 7)) << 4));
        }
    }

    int st = 0;
    for (int c = 0; c < nchunk; ++c) {
        asm volatile("cp.async.wait_group 1;" ::: "memory");
        __syncthreads();

        if (c + 2 < nchunk) ISSUE64(c + 2);

        {
            uint32_t stb = smb + (uint32_t)st * STAGE;
#pragma unroll
            for (int ks = 0; ks < 4; ++ks) {
                uint32_t ah[2][4];
#pragma unroll
                for (int mt = 0; mt < 2; ++mt)
                    LDSM4(ah[mt], stb + aoff[ks][mt]);
                uint32_t bh[8][2];
#pragma unroll
                for (int np = 0; np < 4; ++np) {
                    uint32_t r4[4];
                    LDSM4(r4, stb + boff[ks][np]);
                    bh[np * 2][0] = r4[0]; bh[np * 2][1] = r4[1];
                    bh[np * 2 + 1][0] = r4[2]; bh[np * 2 + 1][1] = r4[3];
                }
#pragma unroll
                for (int mt = 0; mt < 2; ++mt)
#pragma unroll
                    for (int nb = 0; nb < 8; ++nb)
                        MMAF16(acc[mt][nb], ah[mt], bh[nb]);
            }
        }
        if (++st == 3) st = 0;
    }
#undef ISSUE64

    __syncthreads();

    const int r = lane >> 2, tg = lane & 3;
#pragma unroll
    for (int mt = 0; mt < 2; ++mt) {
#pragma unroll
        for (int nb = 0; nb < 8; ++nb) {
            int m = m0 + wm * 32 + mt * 16 + r;
            int n = n0 + wn * 64 + nb * 8 + tg * 2;
            float2 bb = *reinterpret_cast<const float2*>(bias + n);
#pragma unroll
            for (int half = 0; half < 2; ++half) {
                int mm = m + half * 8;
                float v0 = acc[mt][nb][half * 2 + 0] + bb.x;
                float v1 = acc[mt][nb][half * 2 + 1] + bb.y;
                if (MODE == 1) {
                    float2 vv = {v0, v1};
                    *reinterpret_cast<float2*>(out + (size_t)mm * N + n) = vv;
                } else {
                    int t = mm >> 3;
                    int b = mm & 7;
                    int which = n >> 10;
                    int h = (n >> 6) & 15;
                    int d = n & 63;
                    // q gets 0.125 * log2e so attention can use exp2
                    float sc = (which == 0) ? (0.125f * LOG2E) : 1.0f;
                    __half* dst = (which == 0) ? g_Q : (which == 1) ? g_K : g_V;
                    size_t off = ((size_t)(b * Hh + h) * Tt + t) * HD + d;
                    float2 vv = {v0 * sc, v1 * sc};
                    *reinterpret_cast<__half2*>(dst + off) = __float22half2_rn(vv);
                }
            }
        }
    }
}

// ---------------------------------------------------------------------------
// Flash attention: Q,K,V,P single fp16; softmax in exp2 (scores already in
// log2 units). 3 KV stages, 1 barrier/chunk. 2 CTAs/SM.
// ---------------------------------------------------------------------------
__global__ __launch_bounds__(256, 2)
void attn_mma(const float* __restrict__ rpb)
{
    extern __shared__ __align__(16) char sm[];
    const int tid = threadIdx.x;
    const int lane = tid & 31;
    const int w = tid >> 5;
    const int b = blockIdx.x;
    const int h = blockIdx.y >> 3;
    const int t0 = (blockIdx.y & 7) * 128;
    const int bh = b * Hh + h;

    const uint32_t uQ = smem_u32(sm);
    const uint32_t uS0 = uQ + 16384;

    {
#pragma unroll
        for (int p = 0; p < 4; ++p) {
            int i = tid + p * 256;
            int row = i >> 3, cc = i & 7;
            const __half* src = g_Q + ((size_t)bh * Tt + t0 + row) * HD + cc * 8;
            uint32_t dst = uQ + row * 128 + (((cc ^ (row & 7))) << 4);
            CPASYNC16(dst, src);
        }
    }
    const __half* kvsrc[2] = { g_K, g_V };
#define LOAD_CHUNK(CIDX, ST)                                                   \
    {                                                                          \
        const uint32_t base_ = uS0 + (uint32_t)(ST) * 16384;                   \
        int s0_ = (CIDX) * 64;                                                 \
        _Pragma("unroll")                                                      \
        for (int p = 0; p < 4; ++p) {                                          \
            int i = tid + p * 256;                                             \
            int tile = i >> 9;                                                 \
            int rem = i & 511;                                                 \
            int row = rem >> 3, cc = rem & 7;                                  \
            const __half* src = kvsrc[tile]                                    \
                + ((size_t)bh * Tt + s0_ + row) * HD + cc * 8;                 \
            uint32_t dst = base_ + tile * 8192 + row * 128                     \
                         + (((cc ^ (row & 7))) << 4);                          \
            CPASYNC16(dst, src);                                               \
        }                                                                      \
    }

    LOAD_CHUNK(0, 0);
    asm volatile("cp.async.commit_group;" ::: "memory");
    LOAD_CHUNK(1, 1);
    asm volatile("cp.async.commit_group;" ::: "memory");

    float o[8][4];
#pragma unroll
    for (int j = 0; j < 8; ++j)
#pragma unroll
        for (int v = 0; v < 4; ++v) o[j][v] = 0.f;
    float m0r = -1e30f, m1r = -1e30f, l0r = 0.f, l1r = 0.f;

    const int rq = lane >> 2;
    const int cq = (lane & 3) * 2;
    const size_t brow0_base = ((size_t)h * Tt + (t0 + w * 16 + rq)) * Tt;
    const size_t brow1_base = brow0_base + 8 * (size_t)Tt;

    const int qrow = w * 16 + (lane & 15);
    const uint32_t qrb = uQ + qrow * 128;
    const uint32_t qsel = (uint32_t)(lane >> 4);

    int st = 0;
    for (int c = 0; c < 16; ++c) {
        if (c == 15) asm volatile("cp.async.wait_group 0;" ::: "memory");
        else         asm volatile("cp.async.wait_group 1;" ::: "memory");
        __syncthreads();

        const uint32_t stb = uS0 + (uint32_t)st * 16384;
        const int g = lane >> 3, i = lane & 7;

        float s[8][4];
#pragma unroll
        for (int j = 0; j < 8; ++j)
#pragma unroll
            for (int v = 0; v < 4; ++v) s[j][v] = 0.f;

#pragma unroll
        for (int kk = 0; kk < 4; ++kk) {
            uint32_t qh[4];
            {
                uint32_t ccol = 2u * kk + qsel;
                uint32_t off = ((ccol ^ (qrow & 7)) << 4);
                LDSM4(qh, qrb + off);
            }
            uint32_t kb[8][2];
            const int brow_off = i + ((g >> 1) << 3);
            const int bkc = kk * 2 + (g & 1);
#pragma unroll
            for (int ng = 0; ng < 4; ++ng) {
                int row = ng * 16 + brow_off;
                uint32_t off = (uint32_t)(row * 128 + ((bkc ^ (row & 7)) << 4));
                uint32_t r4[4];
                LDSM4(r4, stb + off);
                kb[ng * 2][0] = r4[0]; kb[ng * 2][1] = r4[1];
                kb[ng * 2 + 1][0] = r4[2]; kb[ng * 2 + 1][1] = r4[3];
            }
#pragma unroll
            for (int nt = 0; nt < 8; ++nt)
                MMAF16(s[nt], qh, kb[nt]);
        }

        {
            const float* bp0 = rpb + brow0_base + c * 64 + cq;
            const float* bp1 = rpb + brow1_base + c * 64 + cq;
#pragma unroll
            for (int j = 0; j < 8; ++j) {
                float2 b0 = *reinterpret_cast<const float2*>(bp0 + j * 8);
                float2 b1 = *reinterpret_cast<const float2*>(bp1 + j * 8);
                s[j][0] = fmaf(b0.x, LOG2E, s[j][0]);
                s[j][1] = fmaf(b0.y, LOG2E, s[j][1]);
                s[j][2] = fmaf(b1.x, LOG2E, s[j][2]);
                s[j][3] = fmaf(b1.y, LOG2E, s[j][3]);
            }
        }

        float cm0 = -1e30f, cm1 = -1e30f;
#pragma unroll
        for (int j = 0; j < 8; ++j) {
            cm0 = fmaxf(cm0, fmaxf(s[j][0], s[j][1]));
            cm1 = fmaxf(cm1, fmaxf(s[j][2], s[j][3]));
        }
        cm0 = fmaxf(cm0, __shfl_xor_sync(0xffffffffu, cm0, 1));
        cm0 = fmaxf(cm0, __shfl_xor_sync(0xffffffffu, cm0, 2));
        cm1 = fmaxf(cm1, __shfl_xor_sync(0xffffffffu, cm1, 1));
        cm1 = fmaxf(cm1, __shfl_xor_sync(0xffffffffu, cm1, 2));
        float m0n = fmaxf(m0r, cm0), m1n = fmaxf(m1r, cm1);
        float cor0 = exp2f(m0r - m0n), cor1 = exp2f(m1r - m1n);
        m0r = m0n; m1r = m1n;
        float rs0 = 0.f, rs1 = 0.f;
#pragma unroll
        for (int j = 0; j < 8; ++j) {
            s[j][0] = exp2f(s[j][0] - m0n);
            s[j][1] = exp2f(s[j][1] - m0n);
            s[j][2] = exp2f(s[j][2] - m1n);
            s[j][3] = exp2f(s[j][3] - m1n);
            rs0 += s[j][0] + s[j][1];
            rs1 += s[j][2] + s[j][3];
        }
        rs0 += __shfl_xor_sync(0xffffffffu, rs0, 1);
        rs0 += __shfl_xor_sync(0xffffffffu, rs0, 2);
        rs1 += __shfl_xor_sync(0xffffffffu, rs1, 1);
        rs1 += __shfl_xor_sync(0xffffffffu, rs1, 2);
        l0r = l0r * cor0 + rs0;
        l1r = l1r * cor1 + rs1;
#pragma unroll
        for (int j = 0; j < 8; ++j) {
            o[j][0] *= cor0; o[j][1] *= cor0;
            o[j][2] *= cor1; o[j][3] *= cor1;
        }

        uint32_t ph[8][2];
#pragma unroll
        for (int j = 0; j < 8; ++j) {
            float2 v0 = {s[j][0], s[j][1]};
            __half2 hh0 = __float22half2_rn(v0);
            ph[j][0] = *reinterpret_cast<uint32_t*>(&hh0);
            float2 v1 = {s[j][2], s[j][3]};
            __half2 hh1 = __float22half2_rn(v1);
            ph[j][1] = *reinterpret_cast<uint32_t*>(&hh1);
        }

#pragma unroll
        for (int kk = 0; kk < 4; ++kk) {
            uint32_t a_h[4] = { ph[2*kk][0], ph[2*kk][1], ph[2*kk+1][0], ph[2*kk+1][1] };
            uint32_t vb[8][2];
            const int srow = kk * 16 + i + ((g >> 1) << 3);
#pragma unroll
            for (int dg = 0; dg < 4; ++dg) {
                int ck = dg * 2 + (g & 1);
                uint32_t off = (uint32_t)(srow * 128 + ((ck ^ (srow & 7)) << 4));
                uint32_t r4[4];
                LDSM4T(r4, stb + 8192 + off);
                vb[dg * 2][0] = r4[0]; vb[dg * 2][1] = r4[2];
                vb[dg * 2 + 1][0] = r4[1]; vb[dg * 2 + 1][1] = r4[3];
            }
#pragma unroll
            for (int dt = 0; dt < 8; ++dt)
                MMAF16(o[dt], a_h, vb[dt]);
        }

        if (c + 2 < 16) {
            int st2 = st + 2;
            if (st2 >= 3) st2 -= 3;
            LOAD_CHUNK(c + 2, st2);
            asm volatile("cp.async.commit_group;" ::: "memory");
        }
        if (++st == 3) st = 0;
    }

    float inv0 = 1.f / l0r, inv1 = 1.f / l1r;
    int t_row0 = t0 + w * 16 + rq;
    int t_row1 = t_row0 + 8;
#pragma unroll
    for (int j = 0; j < 8; ++j) {
        int d = j * 8 + cq;
        size_t i0 = ((size_t)t_row0 * Bb + b) * Ee + h * HD + d;
        size_t i1 = ((size_t)t_row1 * Bb + b) * Ee + h * HD + d;
        float2 v0 = {o[j][0] * inv0, o[j][1] * inv0};
        float2 v1 = {o[j][2] * inv1, o[j][3] * inv1};
        *reinterpret_cast<__half2*>(g_AOh + i0) = __float22half2_rn(v0);
        *reinterpret_cast<__half2*>(g_AOh + i1) = __float22half2_rn(v1);
    }
#undef LOAD_CHUNK
}

// ---------------------------------------------------------------------------
extern "C" void kernel_launch(void* const* d_in, const int* in_sizes, int n_in,
                              void* d_out, int out_size)
{
    const float* query = (const float*)d_in[0];
    const float* ipw   = (const float*)d_in[1];
    const float* ipb   = (const float*)d_in[2];
    const float* il    = (const float*)d_in[3];
    const float* ir    = (const float*)d_in[4];
    const float* opw   = (const float*)d_in[5];
    const float* opb   = (const float*)d_in[6];
    const float* ol    = (const float*)d_in[7];
    const float* orr   = (const float*)d_in[8];
    const float* rpb   = (const float*)d_in[9];
    float* out = (float*)d_out;

    static bool attr_set = false;
    if (!attr_set) {
        cudaFuncSetAttribute((const void*)gemm_mma<0>,
            cudaFuncAttributeMaxDynamicSharedMemorySize, 98304);
        cudaFuncSetAttribute((const void*)gemm_mma<1>,
            cudaFuncAttributeMaxDynamicSharedMemorySize, 98304);
        cudaFuncSetAttribute((const void*)attn_mma,
            cudaFuncAttributeMaxDynamicSharedMemorySize, 65536);
        attr_set = true;
    }

    prologue_kernel<<<PB_QS, 256>>>(ipw, il, ir, opw, ol, orr, query);

    gemm_mma<0><<<dim3(F3 / BN, Nrows / BM), 256, 98304>>>(ipb, nullptr, F3, Ee);

    attn_mma<<<dim3(Bb, Hh * 8), 256, 65536>>>(rpb);

    gemm_mma<1><<<dim3(Ee / BN, Nrows / BM), 256, 98304>>>(opb, out, Ee, Ee);
}